// round 1
// baseline (speedup 1.0000x reference)
#include <cuda_runtime.h>
#include <cuda_bf16.h>
#include <math.h>

// Problem constants
#define BATCH 8
#define DIM   1024     // channels == tokens
#define HW2   1024     // 32*32 spatial == feature dim
#define HEADS 16
#define HD    64       // head dim
#define NBH   (BATCH*HEADS)   // 128

// ---------------- scratch (static __device__, no allocs) ----------------
__device__ float g_q [BATCH * DIM * HW2];                     // conv-Q out [B][C][HW]
__device__ float g_k [BATCH * DIM * HW2];
__device__ float g_v [BATCH * DIM * HW2];
__device__ float g_s [(size_t)NBH * DIM * DIM];               // attn scores / probs, 512MB
__device__ float g_ao[BATCH * DIM * HW2];                     // attention output [B][t][h*64+d]

// =====================================================================
// Conv 3x3, SAME padding, stride 1. y[b][co][sp] = sum_ci,k W*x + bias
// Block: 128 output channels x 128 spatial (4 rows of 32), 256 threads,
// 8x8 microtile. K-loop over ci in chunks of 8 with 9-tap shifted FMA.
// =====================================================================
#define TC 8
__global__ __launch_bounds__(256, 2)
void conv3x3_kernel(const float* __restrict__ x, const float* __restrict__ W,
                    const float* __restrict__ bias, float* __restrict__ y)
{
    __shared__ float Ws[128 * TC * 9];    // [co][ci][k] : co*72 + ci*9 + k
    __shared__ float Xs[TC * 6 * 34];     // [ci][row(-1..+4)][col(-1..+32)]

    const int b   = blockIdx.z;
    const int co0 = blockIdx.x * 128;
    const int sp0 = blockIdx.y * 128;     // 4 output rows
    const int r0  = blockIdx.y * 4;
    const int tid = threadIdx.x;
    const int tx  = tid & 15;
    const int ty  = tid >> 4;

    const int lrow     = tx >> 2;         // local output row 0..3
    const int xcolbase = (tx & 3) * 8;    // local col base 0..24

    const float* xb = x + (size_t)b * DIM * HW2;

    float acc[8][8];
    #pragma unroll
    for (int i = 0; i < 8; i++)
        #pragma unroll
        for (int j = 0; j < 8; j++) acc[i][j] = 0.f;

    for (int ci0 = 0; ci0 < DIM; ci0 += TC) {
        __syncthreads();
        // load W chunk: 128co x 8ci x 9 = 9216 floats
        for (int i = tid; i < 128 * TC * 9; i += 256) {
            int co = i / (TC * 9);
            int rest = i - co * (TC * 9);
            Ws[i] = W[(size_t)(co0 + co) * (DIM * 9) + (size_t)ci0 * 9 + rest];
        }
        // load X chunk: 8ci x 6rows x 34cols, zero padded
        for (int i = tid; i < TC * 6 * 34; i += 256) {
            int ci  = i / 204;
            int rem = i - ci * 204;
            int lr  = rem / 34;
            int c   = rem - lr * 34;
            int gr  = r0 + lr - 1;
            int gc  = c - 1;
            float vv = 0.f;
            if ((unsigned)gr < 32u && (unsigned)gc < 32u)
                vv = xb[(size_t)(ci0 + ci) * HW2 + gr * 32 + gc];
            Xs[i] = vv;
        }
        __syncthreads();

        #pragma unroll 1
        for (int ci = 0; ci < TC; ci++) {
            #pragma unroll
            for (int kh = 0; kh < 3; kh++) {
                float xt[10];
                const int xbase = ci * 204 + (lrow + kh) * 34 + xcolbase;
                #pragma unroll
                for (int c = 0; c < 10; c++) xt[c] = Xs[xbase + c];
                #pragma unroll
                for (int kw = 0; kw < 3; kw++) {
                    float wv[8];
                    #pragma unroll
                    for (int i = 0; i < 8; i++)
                        wv[i] = Ws[(ty + 16 * i) * 72 + ci * 9 + kh * 3 + kw];
                    #pragma unroll
                    for (int i = 0; i < 8; i++)
                        #pragma unroll
                        for (int j = 0; j < 8; j++)
                            acc[i][j] += wv[i] * xt[j + kw];
                }
            }
        }
    }

    float* yb = y + (size_t)b * DIM * HW2;
    #pragma unroll
    for (int i = 0; i < 8; i++) {
        int co = co0 + ty + 16 * i;
        float bi = bias[co];
        #pragma unroll
        for (int j = 0; j < 8; j++)
            yb[(size_t)co * HW2 + sp0 + tx * 8 + j] = acc[i][j] + bi;
    }
}

// =====================================================================
// S = Q K^T * 0.125 per (b,h). 128x128 tile, K=64 in chunks of 32.
// =====================================================================
__global__ __launch_bounds__(256, 2)
void qk_kernel(const float* __restrict__ gq, const float* __restrict__ gk,
               float* __restrict__ gs)
{
    __shared__ float Qs[128][33];
    __shared__ float Ks[128][33];

    const int bh = blockIdx.z;
    const int b  = bh >> 4;
    const int h  = bh & 15;
    const int t0 = blockIdx.x * 128;
    const int s0 = blockIdx.y * 128;
    const int tid = threadIdx.x;
    const int tx = tid & 15, ty = tid >> 4;

    const float* qb = gq + ((size_t)b * DIM + t0) * HW2 + h * HD;
    const float* kb = gk + ((size_t)b * DIM + s0) * HW2 + h * HD;

    float acc[8][8];
    #pragma unroll
    for (int i = 0; i < 8; i++)
        #pragma unroll
        for (int j = 0; j < 8; j++) acc[i][j] = 0.f;

    for (int k0 = 0; k0 < HD; k0 += 32) {
        __syncthreads();
        for (int i = tid; i < 128 * 32; i += 256) {
            int r = i >> 5, c = i & 31;
            Qs[r][c] = qb[(size_t)r * HW2 + k0 + c];
            Ks[r][c] = kb[(size_t)r * HW2 + k0 + c];
        }
        __syncthreads();
        #pragma unroll
        for (int d = 0; d < 32; d++) {
            float a[8], bb[8];
            #pragma unroll
            for (int i = 0; i < 8; i++) a[i] = Qs[ty + 16 * i][d];
            #pragma unroll
            for (int j = 0; j < 8; j++) bb[j] = Ks[tx + 16 * j][d];
            #pragma unroll
            for (int i = 0; i < 8; i++)
                #pragma unroll
                for (int j = 0; j < 8; j++) acc[i][j] += a[i] * bb[j];
        }
    }

    float* out = gs + ((size_t)bh * DIM + t0) * DIM + s0;
    #pragma unroll
    for (int i = 0; i < 8; i++)
        #pragma unroll
        for (int j = 0; j < 8; j++)
            out[(size_t)(ty + 16 * i) * DIM + tx + 16 * j] = acc[i][j] * 0.125f;
}

// =====================================================================
// Masked softmax over s for each (b,h,t) row, in place on g_s.
// =====================================================================
__global__ __launch_bounds__(256)
void softmax_kernel(float* __restrict__ gs, const int* __restrict__ mask)
{
    __shared__ float red[16];
    const int t  = blockIdx.x;
    const int bh = blockIdx.y;
    const int b  = bh >> 4;
    float* row = gs + ((size_t)bh * DIM + t) * DIM;
    const int* mrow = mask + ((size_t)b * DIM + t) * DIM;
    const int tid = threadIdx.x;

    float v[4];
    float mx = -3.4e38f;
    #pragma unroll
    for (int j = 0; j < 4; j++) {
        int s = tid + 256 * j;
        float x = row[s];
        if (mrow[s] == 0) x = -1e9f;
        v[j] = x;
        mx = fmaxf(mx, x);
    }
    #pragma unroll
    for (int o = 16; o > 0; o >>= 1)
        mx = fmaxf(mx, __shfl_xor_sync(0xffffffffu, mx, o));
    if ((tid & 31) == 0) red[tid >> 5] = mx;
    __syncthreads();
    mx = red[0];
    #pragma unroll
    for (int w = 1; w < 8; w++) mx = fmaxf(mx, red[w]);

    float sum = 0.f;
    #pragma unroll
    for (int j = 0; j < 4; j++) { v[j] = expf(v[j] - mx); sum += v[j]; }
    #pragma unroll
    for (int o = 16; o > 0; o >>= 1)
        sum += __shfl_xor_sync(0xffffffffu, sum, o);
    if ((tid & 31) == 0) red[8 + (tid >> 5)] = sum;
    __syncthreads();
    sum = 0.f;
    #pragma unroll
    for (int w = 0; w < 8; w++) sum += red[8 + w];

    float inv = 1.0f / sum;
    #pragma unroll
    for (int j = 0; j < 4; j++) row[tid + 256 * j] = v[j] * inv;
}

// =====================================================================
// O = P V per (b,h). 128t x 64d tile, 128 threads, K=1024 in chunks of 32.
// Output written head-concatenated: gao[b][t][h*64+d]
// =====================================================================
__global__ __launch_bounds__(128, 4)
void pv_kernel(const float* __restrict__ gs, const float* __restrict__ gv,
               float* __restrict__ gao)
{
    __shared__ float Ps[128][33];
    __shared__ float Vs[32][65];

    const int bh = blockIdx.y;
    const int b  = bh >> 4;
    const int h  = bh & 15;
    const int t0 = blockIdx.x * 128;
    const int tid = threadIdx.x;
    const int tx = tid & 7, ty = tid >> 3;

    const float* prow = gs + ((size_t)bh * DIM + t0) * DIM;
    const float* vb   = gv + (size_t)b * DIM * HW2 + h * HD;

    float acc[8][8];
    #pragma unroll
    for (int i = 0; i < 8; i++)
        #pragma unroll
        for (int j = 0; j < 8; j++) acc[i][j] = 0.f;

    for (int k0 = 0; k0 < DIM; k0 += 32) {
        __syncthreads();
        for (int i = tid; i < 128 * 32; i += 128) {
            int r = i >> 5, c = i & 31;
            Ps[r][c] = prow[(size_t)r * DIM + k0 + c];
        }
        for (int i = tid; i < 32 * 64; i += 128) {
            int r = i >> 6, c = i & 63;
            Vs[r][c] = vb[(size_t)(k0 + r) * HW2 + c];
        }
        __syncthreads();
        #pragma unroll
        for (int kk = 0; kk < 32; kk++) {
            float a[8], bv[8];
            #pragma unroll
            for (int i = 0; i < 8; i++) a[i] = Ps[ty + 16 * i][kk];
            #pragma unroll
            for (int j = 0; j < 8; j++) bv[j] = Vs[kk][tx + 8 * j];
            #pragma unroll
            for (int i = 0; i < 8; i++)
                #pragma unroll
                for (int j = 0; j < 8; j++) acc[i][j] += a[i] * bv[j];
        }
    }

    #pragma unroll
    for (int i = 0; i < 8; i++)
        #pragma unroll
        for (int j = 0; j < 8; j++)
            gao[((size_t)b * DIM + t0 + ty + 16 * i) * HW2 + h * HD + tx + 8 * j] = acc[i][j];
}

// =====================================================================
// out = AO @ Wo^T + bo.  M = B*DIM = 8192, N = K = 1024.
// =====================================================================
__global__ __launch_bounds__(256, 2)
void proj_kernel(const float* __restrict__ gao, const float* __restrict__ Wo,
                 const float* __restrict__ bo, float* __restrict__ out)
{
    __shared__ float As[128][33];
    __shared__ float Bs[128][33];

    const int m0 = blockIdx.x * 128;
    const int n0 = blockIdx.y * 128;
    const int tid = threadIdx.x;
    const int tx = tid & 15, ty = tid >> 4;

    float acc[8][8];
    #pragma unroll
    for (int i = 0; i < 8; i++)
        #pragma unroll
        for (int j = 0; j < 8; j++) acc[i][j] = 0.f;

    for (int k0 = 0; k0 < DIM; k0 += 32) {
        __syncthreads();
        for (int i = tid; i < 128 * 32; i += 256) {
            int r = i >> 5, c = i & 31;
            As[r][c] = gao[(size_t)(m0 + r) * DIM + k0 + c];
            Bs[r][c] = Wo [(size_t)(n0 + r) * DIM + k0 + c];
        }
        __syncthreads();
        #pragma unroll
        for (int d = 0; d < 32; d++) {
            float a[8], bb[8];
            #pragma unroll
            for (int i = 0; i < 8; i++) a[i] = As[ty + 16 * i][d];
            #pragma unroll
            for (int j = 0; j < 8; j++) bb[j] = Bs[tx + 16 * j][d];
            #pragma unroll
            for (int i = 0; i < 8; i++)
                #pragma unroll
                for (int j = 0; j < 8; j++) acc[i][j] += a[i] * bb[j];
        }
    }

    #pragma unroll
    for (int i = 0; i < 8; i++)
        #pragma unroll
        for (int j = 0; j < 8; j++)
            out[(size_t)(m0 + ty + 16 * i) * DIM + n0 + tx + 16 * j] =
                acc[i][j] + bo[n0 + tx + 16 * j];
}

// =====================================================================
// kernel_launch: conv(q,k,v) -> QK^T -> masked softmax -> PV -> proj
// Inputs: 0:q 1:k 2:v 3:Wq 4:bq 5:Wk 6:bk 7:Wv 8:bv 9:Wo 10:bo 11:mask
// =====================================================================
extern "C" void kernel_launch(void* const* d_in, const int* in_sizes, int n_in,
                              void* d_out, int out_size)
{
    (void)in_sizes; (void)n_in; (void)out_size;
    const float* q   = (const float*)d_in[0];
    const float* k   = (const float*)d_in[1];
    const float* v   = (const float*)d_in[2];
    const float* Wq  = (const float*)d_in[3];
    const float* bq  = (const float*)d_in[4];
    const float* Wk  = (const float*)d_in[5];
    const float* bk  = (const float*)d_in[6];
    const float* Wv  = (const float*)d_in[7];
    const float* bv  = (const float*)d_in[8];
    const float* Wo  = (const float*)d_in[9];
    const float* bo  = (const float*)d_in[10];
    const int*  mask = (const int*) d_in[11];
    float* out = (float*)d_out;

    float *gq, *gk, *gv, *gs, *gao;
    cudaGetSymbolAddress((void**)&gq,  g_q);
    cudaGetSymbolAddress((void**)&gk,  g_k);
    cudaGetSymbolAddress((void**)&gv,  g_v);
    cudaGetSymbolAddress((void**)&gs,  g_s);
    cudaGetSymbolAddress((void**)&gao, g_ao);

    dim3 cgrid(8, 8, BATCH);
    conv3x3_kernel<<<cgrid, 256>>>(q, Wq, bq, gq);
    conv3x3_kernel<<<cgrid, 256>>>(k, Wk, bk, gk);
    conv3x3_kernel<<<cgrid, 256>>>(v, Wv, bv, gv);

    qk_kernel<<<dim3(8, 8, NBH), 256>>>(gq, gk, gs);
    softmax_kernel<<<dim3(DIM, NBH), 256>>>(gs, mask);
    pv_kernel<<<dim3(8, NBH), 128>>>(gs, gv, gao);
    proj_kernel<<<dim3(64, 8), 256>>>(gao, Wo, bo, out);
}

// round 3
// speedup vs baseline: 3.3853x; 3.3853x over previous
#include <cuda_runtime.h>
#include <cuda_bf16.h>
#include <cstdint>
#include <math.h>

// Problem constants
#define BATCH 8
#define DIM   1024     // channels == tokens
#define HW2   1024     // 32*32 spatial == feature dim
#define HEADS 16
#define HD    64       // head dim
#define NBH   (BATCH*HEADS)   // 128

// ======================= helpers =======================
__device__ __forceinline__ uint32_t smem_to_u32(const void* smem_ptr) {
    uint32_t addr;
    asm("{ .reg .u64 tmp; cvta.to.shared.u64 tmp, %1; cvt.u32.u64 %0, tmp; }"
        : "=r"(addr) : "l"(smem_ptr));
    return addr;
}

#define CP_ASYNC16(dst_u32, src_ptr) \
    asm volatile("cp.async.cg.shared.global [%0], [%1], 16;" \
                 :: "r"(dst_u32), "l"(src_ptr))
#define CP_COMMIT() asm volatile("cp.async.commit_group;")
#define CP_WAIT(N)  asm volatile("cp.async.wait_group %0;" :: "n"(N))

#define LDSM4(R0,R1,R2,R3,ADDR) \
    asm volatile("ldmatrix.sync.aligned.m8n8.x4.shared.b16 {%0,%1,%2,%3}, [%4];" \
        : "=r"(R0),"=r"(R1),"=r"(R2),"=r"(R3) : "r"(ADDR))

#define MMA16816(D,A0,A1,A2,A3,B0,B1) \
    asm volatile("mma.sync.aligned.m16n8k16.row.col.f32.bf16.bf16.f32 " \
        "{%0,%1,%2,%3}, {%4,%5,%6,%7}, {%8,%9}, {%0,%1,%2,%3};" \
        : "+f"((D)[0]),"+f"((D)[1]),"+f"((D)[2]),"+f"((D)[3]) \
        : "r"(A0),"r"(A1),"r"(A2),"r"(A3),"r"(B0),"r"(B1))

// ---------------- scratch (static __device__, no allocs) ----------------
__device__ float g_q [BATCH * DIM * HW2];
__device__ float g_k [BATCH * DIM * HW2];
__device__ float g_v [BATCH * DIM * HW2];
__device__ float g_s [(size_t)NBH * DIM * DIM];               // 512MB
__device__ float g_ao[BATCH * DIM * HW2];

// bf16 hi/lo packed operands for conv implicit GEMM
#define WPK_ELEMS (3u * 9u * 1024u * 1024u)        // [conv][tap][co][ci]
#define XPK_ELEMS (3u * 8u * 1156u * 1024u)        // [conv][b][pad_pixel(34x34)][ci]
__device__ __align__(128) __nv_bfloat16 g_whi[WPK_ELEMS];
__device__ __align__(128) __nv_bfloat16 g_wlo[WPK_ELEMS];
__device__ __align__(128) __nv_bfloat16 g_xthi[XPK_ELEMS];
__device__ __align__(128) __nv_bfloat16 g_xtlo[XPK_ELEMS];

// =====================================================================
// Prep kernels
// =====================================================================
__global__ void zero4_kernel(uint4* p) {
    size_t i = (size_t)blockIdx.x * blockDim.x + threadIdx.x;
    p[i] = make_uint4(0u, 0u, 0u, 0u);
}

// W [co][ci][3][3] fp32  ->  whi/wlo [conv][tap][co][ci] bf16
__global__ void pack_w_kernel(const float* __restrict__ Wq, const float* __restrict__ Wk,
                              const float* __restrict__ Wv,
                              __nv_bfloat16* __restrict__ whi, __nv_bfloat16* __restrict__ wlo) {
    size_t i = (size_t)blockIdx.x * blockDim.x + threadIdx.x;   // < 3*9*2^20
    const size_t N1 = 9ull << 20;
    int conv = (int)(i / N1);
    size_t rem = i - (size_t)conv * N1;
    int kk = (int)(rem >> 20);
    int r2 = (int)(rem & 0xFFFFF);
    int co = r2 >> 10;
    int ci = r2 & 1023;
    const float* W = conv == 0 ? Wq : (conv == 1 ? Wk : Wv);
    float w = W[((size_t)co * 1024 + ci) * 9 + kk];
    __nv_bfloat16 h = __float2bfloat16(w);
    whi[i] = h;
    wlo[i] = __float2bfloat16(w - __bfloat162float(h));
}

// x [b][ci][32*32] fp32 -> xt [conv][b][pad_pixel][ci] bf16 (interior; border pre-zeroed)
__global__ __launch_bounds__(256)
void pack_x_kernel(const float* __restrict__ q, const float* __restrict__ k,
                   const float* __restrict__ v,
                   __nv_bfloat16* __restrict__ xthi, __nv_bfloat16* __restrict__ xtlo) {
    __shared__ float t[32][33];
    const int conv = blockIdx.z >> 3, b = blockIdx.z & 7;
    const float* x = conv == 0 ? q : (conv == 1 ? k : v);
    const int r   = blockIdx.x;        // image row 0..31
    const int ci0 = blockIdx.y * 32;
    const int tx = threadIdx.x & 31, ty = threadIdx.x >> 5;
    #pragma unroll
    for (int ii = 0; ii < 4; ii++)
        t[ty + 8*ii][tx] = x[((size_t)b * 1024 + ci0 + ty + 8*ii) * 1024 + r * 32 + tx];
    __syncthreads();
    size_t obase = ((size_t)(conv * 8 + b) * 1156 + (size_t)(r + 1) * 34 + 1) * 1024 + ci0;
    #pragma unroll
    for (int jj = 0; jj < 4; jj++) {
        int j = ty + 8*jj;             // column c
        float w = t[tx][j];
        __nv_bfloat16 h = __float2bfloat16(w);
        xthi[obase + (size_t)j * 1024 + tx] = h;
        xtlo[obase + (size_t)j * 1024 + tx] = __float2bfloat16(w - __bfloat162float(h));
    }
}

// =====================================================================
// Conv3x3 implicit GEMM via mma.sync (bf16 hi/lo x3). 128co x 128sp tile,
// K = 9 taps x 1024 ci in 64-chunks, cp.async double-buffered SMEM.
// 8 warps, each a 64x32 subtile (4x4 of m16n8k16).
// grid (8 co, 8 sp, 24 = conv*8+b), 256 threads.
// =====================================================================
#define CONV_SMEM_BYTES (2 * 4 * 16384)   // 2 bufs x (Ahi,Alo,Bhi,Blo) of 128x64 bf16

__global__ __launch_bounds__(256, 1)
void conv_mma_kernel(const __nv_bfloat16* __restrict__ whi, const __nv_bfloat16* __restrict__ wlo,
                     const __nv_bfloat16* __restrict__ xthi, const __nv_bfloat16* __restrict__ xtlo,
                     const float* __restrict__ bq, const float* __restrict__ bk,
                     const float* __restrict__ bv,
                     float* __restrict__ yq, float* __restrict__ yk, float* __restrict__ yv) {
    extern __shared__ char dsm[];
    const int tid  = threadIdx.x;
    const int wid  = tid >> 5, lane = tid & 31;
    const int co0  = blockIdx.x * 128;
    const int sp0  = blockIdx.y * 128;
    const int r0   = blockIdx.y * 4;
    const int conv = blockIdx.z >> 3;
    const int b    = blockIdx.z & 7;

    const uint32_t sbase = smem_to_u32(dsm);

    // ---- loader mapping: 16B segments ----
    const int rowb = tid >> 3;   // 0..31
    const int seg  = tid & 7;    // 16B segment within 128B row
    int rb[4], cb[4];
    #pragma unroll
    for (int i = 0; i < 4; i++) {
        int row = rowb + 32 * i;
        rb[i] = r0 + (row >> 5);
        cb[i] = row & 31;
    }

    const size_t xbase = (size_t)(conv * 8 + b) * 1156 * 1024;
    float* yout = conv == 0 ? yq : (conv == 1 ? yk : yv);
    const float* bias = conv == 0 ? bq : (conv == 1 ? bk : bv);

    // issue one chunk's cp.async loads into buffer `buf`
    auto load_chunk = [&](int c, int buf) {
        const int kk  = c >> 4;          // tap 0..8
        const int ci0 = (c & 15) << 6;   // ci chunk base
        const int kh  = kk / 3, kw = kk - kh * 3;
        const size_t wbase = (((size_t)(conv * 9 + kk) * 1024 + co0) * 1024) + ci0 + seg * 8;
        const uint32_t sb = sbase + buf * 65536;
        #pragma unroll
        for (int i = 0; i < 4; i++) {
            int row = rowb + 32 * i;
            uint32_t sw = (uint32_t)(row * 128) + (uint32_t)(((seg ^ (row & 7)) << 4));
            CP_ASYNC16(sb + sw,         whi + wbase + (size_t)row * 1024);
            CP_ASYNC16(sb + 16384 + sw, wlo + wbase + (size_t)row * 1024);
            int pix = (rb[i] + kh) * 34 + cb[i] + kw;
            size_t bo = xbase + (size_t)pix * 1024 + ci0 + seg * 8;
            CP_ASYNC16(sb + 32768 + sw, xthi + bo);
            CP_ASYNC16(sb + 49152 + sw, xtlo + bo);
        }
    };

    // ---- mma mapping ----
    const int wm = (wid & 1) * 64;    // co offset within tile
    const int wn = (wid >> 1) * 32;   // sp offset within tile

    int rowA[4], xorA[4];
    #pragma unroll
    for (int mt = 0; mt < 4; mt++) {
        rowA[mt] = wm + mt * 16 + (lane & 15);
        xorA[mt] = rowA[mt] & 7;
    }
    const int colgrpA = lane >> 4;            // 0/1 -> k 0-7 / 8-15

    int rowB[2], xorB[2];
    #pragma unroll
    for (int np = 0; np < 2; np++) {
        rowB[np] = wn + np * 16 + (lane & 7) + ((lane >> 4) & 1) * 8;
        xorB[np] = rowB[np] & 7;
    }
    const int colgrpB = (lane >> 3) & 1;      // 0/1 -> k 0-7 / 8-15

    float acc[4][4][4];
    #pragma unroll
    for (int mt = 0; mt < 4; mt++)
        #pragma unroll
        for (int nt = 0; nt < 4; nt++)
            #pragma unroll
            for (int e = 0; e < 4; e++) acc[mt][nt][e] = 0.f;

    // ---- pipeline ----
    load_chunk(0, 0);
    CP_COMMIT();

    for (int c = 0; c < 144; ++c) {
        const int buf = c & 1;
        if (c < 143) {
            load_chunk(c + 1, (c + 1) & 1);
            CP_COMMIT();
            CP_WAIT(1);
        } else {
            CP_WAIT(0);
        }
        __syncthreads();

        const uint32_t sb   = sbase + buf * 65536;
        const uint32_t aHi = sb, aLo = sb + 16384, bHi = sb + 32768, bLo = sb + 49152;

        #pragma unroll
        for (int ks = 0; ks < 4; ks++) {
            uint32_t ah[4][4], al[4][4], bh[2][4], bl[2][4];
            const int segA = ks * 2 + colgrpA;
            const int segB = ks * 2 + colgrpB;
            #pragma unroll
            for (int mt = 0; mt < 4; mt++) {
                uint32_t off = (uint32_t)(rowA[mt] * 128) + (uint32_t)((segA ^ xorA[mt]) << 4);
                LDSM4(ah[mt][0], ah[mt][1], ah[mt][2], ah[mt][3], aHi + off);
                LDSM4(al[mt][0], al[mt][1], al[mt][2], al[mt][3], aLo + off);
            }
            #pragma unroll
            for (int np = 0; np < 2; np++) {
                uint32_t off = (uint32_t)(rowB[np] * 128) + (uint32_t)((segB ^ xorB[np]) << 4);
                LDSM4(bh[np][0], bh[np][1], bh[np][2], bh[np][3], bHi + off);
                LDSM4(bl[np][0], bl[np][1], bl[np][2], bl[np][3], bLo + off);
            }
            #pragma unroll
            for (int mt = 0; mt < 4; mt++) {
                #pragma unroll
                for (int nt = 0; nt < 4; nt++) {
                    const int np = nt >> 1, h = (nt & 1) * 2;
                    MMA16816(acc[mt][nt], ah[mt][0], ah[mt][1], ah[mt][2], ah[mt][3],
                             bh[np][h], bh[np][h + 1]);
                    MMA16816(acc[mt][nt], ah[mt][0], ah[mt][1], ah[mt][2], ah[mt][3],
                             bl[np][h], bl[np][h + 1]);
                    MMA16816(acc[mt][nt], al[mt][0], al[mt][1], al[mt][2], al[mt][3],
                             bh[np][h], bh[np][h + 1]);
                }
            }
        }
        __syncthreads();
    }

    // ---- epilogue: d regs -> global with bias ----
    #pragma unroll
    for (int mt = 0; mt < 4; mt++) {
        const int co_a = co0 + wm + mt * 16 + (lane >> 2);
        const int co_b = co_a + 8;
        const float bi_a = bias[co_a];
        const float bi_b = bias[co_b];
        #pragma unroll
        for (int nt = 0; nt < 4; nt++) {
            const int sp = sp0 + wn + nt * 8 + 2 * (lane & 3);
            float2 v0 = make_float2(acc[mt][nt][0] + bi_a, acc[mt][nt][1] + bi_a);
            float2 v1 = make_float2(acc[mt][nt][2] + bi_b, acc[mt][nt][3] + bi_b);
            *(float2*)(yout + ((size_t)b * 1024 + co_a) * 1024 + sp) = v0;
            *(float2*)(yout + ((size_t)b * 1024 + co_b) * 1024 + sp) = v1;
        }
    }
}

// =====================================================================
// S = Q K^T * 0.125 per (b,h). 128x128 tile, K=64 in chunks of 32.
// =====================================================================
__global__ __launch_bounds__(256, 2)
void qk_kernel(const float* __restrict__ gq, const float* __restrict__ gk,
               float* __restrict__ gs)
{
    __shared__ float Qs[128][33];
    __shared__ float Ks[128][33];

    const int bh = blockIdx.z;
    const int b  = bh >> 4;
    const int h  = bh & 15;
    const int t0 = blockIdx.x * 128;
    const int s0 = blockIdx.y * 128;
    const int tid = threadIdx.x;
    const int tx = tid & 15, ty = tid >> 4;

    const float* qb = gq + ((size_t)b * DIM + t0) * HW2 + h * HD;
    const float* kb = gk + ((size_t)b * DIM + s0) * HW2 + h * HD;

    float acc[8][8];
    #pragma unroll
    for (int i = 0; i < 8; i++)
        #pragma unroll
        for (int j = 0; j < 8; j++) acc[i][j] = 0.f;

    for (int k0 = 0; k0 < HD; k0 += 32) {
        __syncthreads();
        for (int i = tid; i < 128 * 32; i += 256) {
            int r = i >> 5, c = i & 31;
            Qs[r][c] = qb[(size_t)r * HW2 + k0 + c];
            Ks[r][c] = kb[(size_t)r * HW2 + k0 + c];
        }
        __syncthreads();
        #pragma unroll
        for (int d = 0; d < 32; d++) {
            float a[8], bb[8];
            #pragma unroll
            for (int i = 0; i < 8; i++) a[i] = Qs[ty + 16 * i][d];
            #pragma unroll
            for (int j = 0; j < 8; j++) bb[j] = Ks[tx + 16 * j][d];
            #pragma unroll
            for (int i = 0; i < 8; i++)
                #pragma unroll
                for (int j = 0; j < 8; j++) acc[i][j] += a[i] * bb[j];
        }
    }

    float* out = gs + ((size_t)bh * DIM + t0) * DIM + s0;
    #pragma unroll
    for (int i = 0; i < 8; i++)
        #pragma unroll
        for (int j = 0; j < 8; j++)
            out[(size_t)(ty + 16 * i) * DIM + tx + 16 * j] = acc[i][j] * 0.125f;
}

// =====================================================================
// Masked softmax over s for each (b,h,t) row, in place on g_s.
// =====================================================================
__global__ __launch_bounds__(256)
void softmax_kernel(float* __restrict__ gs, const int* __restrict__ mask)
{
    __shared__ float red[16];
    const int t  = blockIdx.x;
    const int bh = blockIdx.y;
    const int b  = bh >> 4;
    float* row = gs + ((size_t)bh * DIM + t) * DIM;
    const int* mrow = mask + ((size_t)b * DIM + t) * DIM;
    const int tid = threadIdx.x;

    float v[4];
    float mx = -3.4e38f;
    #pragma unroll
    for (int j = 0; j < 4; j++) {
        int s = tid + 256 * j;
        float x = row[s];
        if (mrow[s] == 0) x = -1e9f;
        v[j] = x;
        mx = fmaxf(mx, x);
    }
    #pragma unroll
    for (int o = 16; o > 0; o >>= 1)
        mx = fmaxf(mx, __shfl_xor_sync(0xffffffffu, mx, o));
    if ((tid & 31) == 0) red[tid >> 5] = mx;
    __syncthreads();
    mx = red[0];
    #pragma unroll
    for (int w = 1; w < 8; w++) mx = fmaxf(mx, red[w]);

    float sum = 0.f;
    #pragma unroll
    for (int j = 0; j < 4; j++) { v[j] = expf(v[j] - mx); sum += v[j]; }
    #pragma unroll
    for (int o = 16; o > 0; o >>= 1)
        sum += __shfl_xor_sync(0xffffffffu, sum, o);
    if ((tid & 31) == 0) red[8 + (tid >> 5)] = sum;
    __syncthreads();
    sum = 0.f;
    #pragma unroll
    for (int w = 0; w < 8; w++) sum += red[8 + w];

    float inv = 1.0f / sum;
    #pragma unroll
    for (int j = 0; j < 4; j++) row[tid + 256 * j] = v[j] * inv;
}

// =====================================================================
// O = P V per (b,h). 128t x 64d tile, 128 threads, K=1024 in chunks of 32.
// =====================================================================
__global__ __launch_bounds__(128, 4)
void pv_kernel(const float* __restrict__ gs, const float* __restrict__ gv,
               float* __restrict__ gao)
{
    __shared__ float Ps[128][33];
    __shared__ float Vs[32][65];

    const int bh = blockIdx.y;
    const int b  = bh >> 4;
    const int h  = bh & 15;
    const int t0 = blockIdx.x * 128;
    const int tid = threadIdx.x;
    const int tx = tid & 7, ty = tid >> 3;

    const float* prow = gs + ((size_t)bh * DIM + t0) * DIM;
    const float* vb   = gv + (size_t)b * DIM * HW2 + h * HD;

    float acc[8][8];
    #pragma unroll
    for (int i = 0; i < 8; i++)
        #pragma unroll
        for (int j = 0; j < 8; j++) acc[i][j] = 0.f;

    for (int k0 = 0; k0 < DIM; k0 += 32) {
        __syncthreads();
        for (int i = tid; i < 128 * 32; i += 128) {
            int r = i >> 5, c = i & 31;
            Ps[r][c] = prow[(size_t)r * DIM + k0 + c];
        }
        for (int i = tid; i < 32 * 64; i += 128) {
            int r = i >> 6, c = i & 63;
            Vs[r][c] = vb[(size_t)(k0 + r) * HW2 + c];
        }
        __syncthreads();
        #pragma unroll
        for (int kk = 0; kk < 32; kk++) {
            float a[8], bvv[8];
            #pragma unroll
            for (int i = 0; i < 8; i++) a[i] = Ps[ty + 16 * i][kk];
            #pragma unroll
            for (int j = 0; j < 8; j++) bvv[j] = Vs[kk][tx + 8 * j];
            #pragma unroll
            for (int i = 0; i < 8; i++)
                #pragma unroll
                for (int j = 0; j < 8; j++) acc[i][j] += a[i] * bvv[j];
        }
    }

    #pragma unroll
    for (int i = 0; i < 8; i++)
        #pragma unroll
        for (int j = 0; j < 8; j++)
            gao[((size_t)b * DIM + t0 + ty + 16 * i) * HW2 + h * HD + tx + 8 * j] = acc[i][j];
}

// =====================================================================
// out = AO @ Wo^T + bo.  M = B*DIM = 8192, N = K = 1024.
// =====================================================================
__global__ __launch_bounds__(256, 2)
void proj_kernel(const float* __restrict__ gao, const float* __restrict__ Wo,
                 const float* __restrict__ bo, float* __restrict__ out)
{
    __shared__ float As[128][33];
    __shared__ float Bs[128][33];

    const int m0 = blockIdx.x * 128;
    const int n0 = blockIdx.y * 128;
    const int tid = threadIdx.x;
    const int tx = tid & 15, ty = tid >> 4;

    float acc[8][8];
    #pragma unroll
    for (int i = 0; i < 8; i++)
        #pragma unroll
        for (int j = 0; j < 8; j++) acc[i][j] = 0.f;

    for (int k0 = 0; k0 < DIM; k0 += 32) {
        __syncthreads();
        for (int i = tid; i < 128 * 32; i += 256) {
            int r = i >> 5, c = i & 31;
            As[r][c] = gao[(size_t)(m0 + r) * DIM + k0 + c];
            Bs[r][c] = Wo [(size_t)(n0 + r) * DIM + k0 + c];
        }
        __syncthreads();
        #pragma unroll
        for (int d = 0; d < 32; d++) {
            float a[8], bb[8];
            #pragma unroll
            for (int i = 0; i < 8; i++) a[i] = As[ty + 16 * i][d];
            #pragma unroll
            for (int j = 0; j < 8; j++) bb[j] = Bs[tx + 16 * j][d];
            #pragma unroll
            for (int i = 0; i < 8; i++)
                #pragma unroll
                for (int j = 0; j < 8; j++) acc[i][j] += a[i] * bb[j];
        }
    }

    #pragma unroll
    for (int i = 0; i < 8; i++)
        #pragma unroll
        for (int j = 0; j < 8; j++)
            out[(size_t)(m0 + ty + 16 * i) * DIM + n0 + tx + 16 * j] =
                acc[i][j] + bo[n0 + tx + 16 * j];
}

// =====================================================================
// kernel_launch
// Inputs: 0:q 1:k 2:v 3:Wq 4:bq 5:Wk 6:bk 7:Wv 8:bv 9:Wo 10:bo 11:mask
// =====================================================================
extern "C" void kernel_launch(void* const* d_in, const int* in_sizes, int n_in,
                              void* d_out, int out_size)
{
    (void)in_sizes; (void)n_in; (void)out_size;
    const float* q   = (const float*)d_in[0];
    const float* k   = (const float*)d_in[1];
    const float* v   = (const float*)d_in[2];
    const float* Wq  = (const float*)d_in[3];
    const float* bq  = (const float*)d_in[4];
    const float* Wk  = (const float*)d_in[5];
    const float* bk  = (const float*)d_in[6];
    const float* Wv  = (const float*)d_in[7];
    const float* bv  = (const float*)d_in[8];
    const float* Wo  = (const float*)d_in[9];
    const float* bo  = (const float*)d_in[10];
    const int*  mask = (const int*) d_in[11];
    float* out = (float*)d_out;

    float *gq, *gk, *gv, *gs, *gao;
    __nv_bfloat16 *whi, *wlo, *xthi, *xtlo;
    cudaGetSymbolAddress((void**)&gq,  g_q);
    cudaGetSymbolAddress((void**)&gk,  g_k);
    cudaGetSymbolAddress((void**)&gv,  g_v);
    cudaGetSymbolAddress((void**)&gs,  g_s);
    cudaGetSymbolAddress((void**)&gao, g_ao);
    cudaGetSymbolAddress((void**)&whi, g_whi);
    cudaGetSymbolAddress((void**)&wlo, g_wlo);
    cudaGetSymbolAddress((void**)&xthi, g_xthi);
    cudaGetSymbolAddress((void**)&xtlo, g_xtlo);

    cudaFuncSetAttribute(conv_mma_kernel,
                         cudaFuncAttributeMaxDynamicSharedMemorySize, CONV_SMEM_BYTES);

    // zero padded-x borders (full clear, interior overwritten by pack_x)
    zero4_kernel<<<XPK_ELEMS * 2 / 16 / 256, 256>>>((uint4*)xthi);
    zero4_kernel<<<XPK_ELEMS * 2 / 16 / 256, 256>>>((uint4*)xtlo);
    pack_w_kernel<<<WPK_ELEMS / 256, 256>>>(Wq, Wk, Wv, whi, wlo);
    pack_x_kernel<<<dim3(32, 32, 24), 256>>>(q, k, v, xthi, xtlo);

    conv_mma_kernel<<<dim3(8, 8, 24), 256, CONV_SMEM_BYTES>>>(
        whi, wlo, xthi, xtlo, bq, bk, bv, gq, gk, gv);

    qk_kernel<<<dim3(8, 8, NBH), 256>>>(gq, gk, gs);
    softmax_kernel<<<dim3(DIM, NBH), 256>>>(gs, mask);
    pv_kernel<<<dim3(8, NBH), 128>>>(gs, gv, gao);
    proj_kernel<<<dim3(64, 8), 256>>>(gao, Wo, bo, out);
}

// round 4
// speedup vs baseline: 3.3874x; 1.0006x over previous
#include <cuda_runtime.h>
#include <cuda_bf16.h>
#include <cstdint>
#include <math.h>

// Problem constants
#define BATCH 8
#define DIM   1024     // channels == tokens
#define HW2   1024     // 32*32 spatial == feature dim
#define HEADS 16
#define HD    64       // head dim
#define NBH   (BATCH*HEADS)   // 128

// ======================= helpers =======================
__device__ __forceinline__ uint32_t smem_to_u32(const void* smem_ptr) {
    uint32_t addr;
    asm("{ .reg .u64 tmp; cvta.to.shared.u64 tmp, %1; cvt.u32.u64 %0, tmp; }"
        : "=r"(addr) : "l"(smem_ptr));
    return addr;
}

#define CP_ASYNC16(dst_u32, src_ptr) \
    asm volatile("cp.async.cg.shared.global [%0], [%1], 16;" \
                 :: "r"(dst_u32), "l"(src_ptr))
#define CP_COMMIT() asm volatile("cp.async.commit_group;")
#define CP_WAIT(N)  asm volatile("cp.async.wait_group %0;" :: "n"(N))

#define LDSM4(R0,R1,R2,R3,ADDR) \
    asm volatile("ldmatrix.sync.aligned.m8n8.x4.shared.b16 {%0,%1,%2,%3}, [%4];" \
        : "=r"(R0),"=r"(R1),"=r"(R2),"=r"(R3) : "r"(ADDR))

#define MMA16816(D,A0,A1,A2,A3,B0,B1) \
    asm volatile("mma.sync.aligned.m16n8k16.row.col.f32.bf16.bf16.f32 " \
        "{%0,%1,%2,%3}, {%4,%5,%6,%7}, {%8,%9}, {%0,%1,%2,%3};" \
        : "+f"((D)[0]),"+f"((D)[1]),"+f"((D)[2]),"+f"((D)[3]) \
        : "r"(A0),"r"(A1),"r"(A2),"r"(A3),"r"(B0),"r"(B1))

// ---------------- scratch (static __device__, no allocs) ----------------
__device__ float g_q [BATCH * DIM * HW2];
__device__ float g_k [BATCH * DIM * HW2];
__device__ float g_v [BATCH * DIM * HW2];
__device__ float g_s [(size_t)NBH * DIM * DIM];               // 512MB
__device__ float g_ao[BATCH * DIM * HW2];

// bf16 hi/lo packed operands for conv implicit GEMM
#define WPK_ELEMS (3u * 9u * 1024u * 1024u)        // [conv][tap][co][ci]
#define XPK_ELEMS (3u * 8u * 1156u * 1024u)        // [conv][b][pad_pixel(34x34)][ci]
__device__ __align__(128) __nv_bfloat16 g_whi[WPK_ELEMS];
__device__ __align__(128) __nv_bfloat16 g_wlo[WPK_ELEMS];
__device__ __align__(128) __nv_bfloat16 g_xthi[XPK_ELEMS];
__device__ __align__(128) __nv_bfloat16 g_xtlo[XPK_ELEMS];

// =====================================================================
// Prep kernels
// =====================================================================
__global__ void zero4_kernel(uint4* p) {
    size_t i = (size_t)blockIdx.x * blockDim.x + threadIdx.x;
    p[i] = make_uint4(0u, 0u, 0u, 0u);
}

// W [co][ci][3][3] fp32  ->  whi/wlo [conv][tap][co][ci] bf16
__global__ void pack_w_kernel(const float* __restrict__ Wq, const float* __restrict__ Wk,
                              const float* __restrict__ Wv,
                              __nv_bfloat16* __restrict__ whi, __nv_bfloat16* __restrict__ wlo) {
    size_t i = (size_t)blockIdx.x * blockDim.x + threadIdx.x;   // < 3*9*2^20
    const size_t N1 = 9ull << 20;
    int conv = (int)(i / N1);
    size_t rem = i - (size_t)conv * N1;
    int kk = (int)(rem >> 20);
    int r2 = (int)(rem & 0xFFFFF);
    int co = r2 >> 10;
    int ci = r2 & 1023;
    const float* W = conv == 0 ? Wq : (conv == 1 ? Wk : Wv);
    float w = W[((size_t)co * 1024 + ci) * 9 + kk];
    __nv_bfloat16 h = __float2bfloat16(w);
    whi[i] = h;
    wlo[i] = __float2bfloat16(w - __bfloat162float(h));
}

// x [b][ci][32*32] fp32 -> xt [conv][b][pad_pixel][ci] bf16 (interior; border pre-zeroed)
__global__ __launch_bounds__(256)
void pack_x_kernel(const float* __restrict__ q, const float* __restrict__ k,
                   const float* __restrict__ v,
                   __nv_bfloat16* __restrict__ xthi, __nv_bfloat16* __restrict__ xtlo) {
    __shared__ float t[32][33];
    const int conv = blockIdx.z >> 3, b = blockIdx.z & 7;
    const float* x = conv == 0 ? q : (conv == 1 ? k : v);
    const int r   = blockIdx.x;        // image row 0..31
    const int ci0 = blockIdx.y * 32;
    const int tx = threadIdx.x & 31, ty = threadIdx.x >> 5;
    #pragma unroll
    for (int ii = 0; ii < 4; ii++)
        t[ty + 8*ii][tx] = x[((size_t)b * 1024 + ci0 + ty + 8*ii) * 1024 + r * 32 + tx];
    __syncthreads();
    size_t obase = ((size_t)(conv * 8 + b) * 1156 + (size_t)(r + 1) * 34 + 1) * 1024 + ci0;
    #pragma unroll
    for (int jj = 0; jj < 4; jj++) {
        int j = ty + 8*jj;             // column c
        float w = t[tx][j];
        __nv_bfloat16 h = __float2bfloat16(w);
        xthi[obase + (size_t)j * 1024 + tx] = h;
        xtlo[obase + (size_t)j * 1024 + tx] = __float2bfloat16(w - __bfloat162float(h));
    }
}

// =====================================================================
// Conv3x3 implicit GEMM via mma.sync (bf16 hi/lo x3). 128co x 128sp tile,
// K = 9 taps x 1024 ci in 64-chunks, cp.async double-buffered SMEM.
// 8 warps, each a 64x32 subtile (4x4 of m16n8k16).
// grid (8 co, 8 sp, 24 = conv*8+b), 256 threads.
// =====================================================================
#define CONV_SMEM_BYTES (2 * 4 * 16384)   // 2 bufs x (Ahi,Alo,Bhi,Blo) of 128x64 bf16

__global__ __launch_bounds__(256, 1)
void conv_mma_kernel(const __nv_bfloat16* __restrict__ whi, const __nv_bfloat16* __restrict__ wlo,
                     const __nv_bfloat16* __restrict__ xthi, const __nv_bfloat16* __restrict__ xtlo,
                     const float* __restrict__ bq, const float* __restrict__ bk,
                     const float* __restrict__ bv,
                     float* __restrict__ yq, float* __restrict__ yk, float* __restrict__ yv) {
    extern __shared__ char dsm[];
    const int tid  = threadIdx.x;
    const int wid  = tid >> 5, lane = tid & 31;
    const int co0  = blockIdx.x * 128;
    const int sp0  = blockIdx.y * 128;
    const int r0   = blockIdx.y * 4;
    const int conv = blockIdx.z >> 3;
    const int b    = blockIdx.z & 7;

    const uint32_t sbase = smem_to_u32(dsm);

    // ---- loader mapping: 16B segments ----
    const int rowb = tid >> 3;   // 0..31
    const int seg  = tid & 7;    // 16B segment within 128B row
    int rb[4], cb[4];
    #pragma unroll
    for (int i = 0; i < 4; i++) {
        int row = rowb + 32 * i;
        rb[i] = r0 + (row >> 5);
        cb[i] = row & 31;
    }

    const size_t xbase = (size_t)(conv * 8 + b) * 1156 * 1024;
    float* yout = conv == 0 ? yq : (conv == 1 ? yk : yv);
    const float* bias = conv == 0 ? bq : (conv == 1 ? bk : bv);

    // issue one chunk's cp.async loads into buffer `buf`
    auto load_chunk = [&](int c, int buf) {
        const int kk  = c >> 4;          // tap 0..8
        const int ci0 = (c & 15) << 6;   // ci chunk base
        const int kh  = kk / 3, kw = kk - kh * 3;
        const size_t wbase = (((size_t)(conv * 9 + kk) * 1024 + co0) * 1024) + ci0 + seg * 8;
        const uint32_t sb = sbase + buf * 65536;
        #pragma unroll
        for (int i = 0; i < 4; i++) {
            int row = rowb + 32 * i;
            uint32_t sw = (uint32_t)(row * 128) + (uint32_t)(((seg ^ (row & 7)) << 4));
            CP_ASYNC16(sb + sw,         whi + wbase + (size_t)row * 1024);
            CP_ASYNC16(sb + 16384 + sw, wlo + wbase + (size_t)row * 1024);
            int pix = (rb[i] + kh) * 34 + cb[i] + kw;
            size_t bo = xbase + (size_t)pix * 1024 + ci0 + seg * 8;
            CP_ASYNC16(sb + 32768 + sw, xthi + bo);
            CP_ASYNC16(sb + 49152 + sw, xtlo + bo);
        }
    };

    // ---- mma mapping ----
    const int wm = (wid & 1) * 64;    // co offset within tile
    const int wn = (wid >> 1) * 32;   // sp offset within tile

    int rowA[4], xorA[4];
    #pragma unroll
    for (int mt = 0; mt < 4; mt++) {
        rowA[mt] = wm + mt * 16 + (lane & 15);
        xorA[mt] = rowA[mt] & 7;
    }
    const int colgrpA = lane >> 4;            // 0/1 -> k 0-7 / 8-15

    int rowB[2], xorB[2];
    #pragma unroll
    for (int np = 0; np < 2; np++) {
        rowB[np] = wn + np * 16 + (lane & 7) + ((lane >> 4) & 1) * 8;
        xorB[np] = rowB[np] & 7;
    }
    const int colgrpB = (lane >> 3) & 1;      // 0/1 -> k 0-7 / 8-15

    float acc[4][4][4];
    #pragma unroll
    for (int mt = 0; mt < 4; mt++)
        #pragma unroll
        for (int nt = 0; nt < 4; nt++)
            #pragma unroll
            for (int e = 0; e < 4; e++) acc[mt][nt][e] = 0.f;

    // ---- pipeline ----
    load_chunk(0, 0);
    CP_COMMIT();

    for (int c = 0; c < 144; ++c) {
        const int buf = c & 1;
        if (c < 143) {
            load_chunk(c + 1, (c + 1) & 1);
            CP_COMMIT();
            CP_WAIT(1);
        } else {
            CP_WAIT(0);
        }
        __syncthreads();

        const uint32_t sb   = sbase + buf * 65536;
        const uint32_t aHi = sb, aLo = sb + 16384, bHi = sb + 32768, bLo = sb + 49152;

        #pragma unroll
        for (int ks = 0; ks < 4; ks++) {
            uint32_t ah[4][4], al[4][4], bh[2][4], bl[2][4];
            const int segA = ks * 2 + colgrpA;
            const int segB = ks * 2 + colgrpB;
            #pragma unroll
            for (int mt = 0; mt < 4; mt++) {
                uint32_t off = (uint32_t)(rowA[mt] * 128) + (uint32_t)((segA ^ xorA[mt]) << 4);
                LDSM4(ah[mt][0], ah[mt][1], ah[mt][2], ah[mt][3], aHi + off);
                LDSM4(al[mt][0], al[mt][1], al[mt][2], al[mt][3], aLo + off);
            }
            #pragma unroll
            for (int np = 0; np < 2; np++) {
                uint32_t off = (uint32_t)(rowB[np] * 128) + (uint32_t)((segB ^ xorB[np]) << 4);
                LDSM4(bh[np][0], bh[np][1], bh[np][2], bh[np][3], bHi + off);
                LDSM4(bl[np][0], bl[np][1], bl[np][2], bl[np][3], bLo + off);
            }
            #pragma unroll
            for (int mt = 0; mt < 4; mt++) {
                #pragma unroll
                for (int nt = 0; nt < 4; nt++) {
                    const int np = nt >> 1, h = (nt & 1) * 2;
                    MMA16816(acc[mt][nt], ah[mt][0], ah[mt][1], ah[mt][2], ah[mt][3],
                             bh[np][h], bh[np][h + 1]);
                    MMA16816(acc[mt][nt], ah[mt][0], ah[mt][1], ah[mt][2], ah[mt][3],
                             bl[np][h], bl[np][h + 1]);
                    MMA16816(acc[mt][nt], al[mt][0], al[mt][1], al[mt][2], al[mt][3],
                             bh[np][h], bh[np][h + 1]);
                }
            }
        }
        __syncthreads();
    }

    // ---- epilogue: d regs -> global with bias ----
    #pragma unroll
    for (int mt = 0; mt < 4; mt++) {
        const int co_a = co0 + wm + mt * 16 + (lane >> 2);
        const int co_b = co_a + 8;
        const float bi_a = bias[co_a];
        const float bi_b = bias[co_b];
        #pragma unroll
        for (int nt = 0; nt < 4; nt++) {
            const int sp = sp0 + wn + nt * 8 + 2 * (lane & 3);
            float2 v0 = make_float2(acc[mt][nt][0] + bi_a, acc[mt][nt][1] + bi_a);
            float2 v1 = make_float2(acc[mt][nt][2] + bi_b, acc[mt][nt][3] + bi_b);
            *(float2*)(yout + ((size_t)b * 1024 + co_a) * 1024 + sp) = v0;
            *(float2*)(yout + ((size_t)b * 1024 + co_b) * 1024 + sp) = v1;
        }
    }
}

// =====================================================================
// S = Q K^T * 0.125 per (b,h). 128x128 tile, K=64 in chunks of 32.
// =====================================================================
__global__ __launch_bounds__(256, 2)
void qk_kernel(const float* __restrict__ gq, const float* __restrict__ gk,
               float* __restrict__ gs)
{
    __shared__ float Qs[128][33];
    __shared__ float Ks[128][33];

    const int bh = blockIdx.z;
    const int b  = bh >> 4;
    const int h  = bh & 15;
    const int t0 = blockIdx.x * 128;
    const int s0 = blockIdx.y * 128;
    const int tid = threadIdx.x;
    const int tx = tid & 15, ty = tid >> 4;

    const float* qb = gq + ((size_t)b * DIM + t0) * HW2 + h * HD;
    const float* kb = gk + ((size_t)b * DIM + s0) * HW2 + h * HD;

    float acc[8][8];
    #pragma unroll
    for (int i = 0; i < 8; i++)
        #pragma unroll
        for (int j = 0; j < 8; j++) acc[i][j] = 0.f;

    for (int k0 = 0; k0 < HD; k0 += 32) {
        __syncthreads();
        for (int i = tid; i < 128 * 32; i += 256) {
            int r = i >> 5, c = i & 31;
            Qs[r][c] = qb[(size_t)r * HW2 + k0 + c];
            Ks[r][c] = kb[(size_t)r * HW2 + k0 + c];
        }
        __syncthreads();
        #pragma unroll
        for (int d = 0; d < 32; d++) {
            float a[8], bb[8];
            #pragma unroll
            for (int i = 0; i < 8; i++) a[i] = Qs[ty + 16 * i][d];
            #pragma unroll
            for (int j = 0; j < 8; j++) bb[j] = Ks[tx + 16 * j][d];
            #pragma unroll
            for (int i = 0; i < 8; i++)
                #pragma unroll
                for (int j = 0; j < 8; j++) acc[i][j] += a[i] * bb[j];
        }
    }

    float* out = gs + ((size_t)bh * DIM + t0) * DIM + s0;
    #pragma unroll
    for (int i = 0; i < 8; i++)
        #pragma unroll
        for (int j = 0; j < 8; j++)
            out[(size_t)(ty + 16 * i) * DIM + tx + 16 * j] = acc[i][j] * 0.125f;
}

// =====================================================================
// Masked softmax over s for each (b,h,t) row, in place on g_s.
// =====================================================================
__global__ __launch_bounds__(256)
void softmax_kernel(float* __restrict__ gs, const int* __restrict__ mask)
{
    __shared__ float red[16];
    const int t  = blockIdx.x;
    const int bh = blockIdx.y;
    const int b  = bh >> 4;
    float* row = gs + ((size_t)bh * DIM + t) * DIM;
    const int* mrow = mask + ((size_t)b * DIM + t) * DIM;
    const int tid = threadIdx.x;

    float v[4];
    float mx = -3.4e38f;
    #pragma unroll
    for (int j = 0; j < 4; j++) {
        int s = tid + 256 * j;
        float x = row[s];
        if (mrow[s] == 0) x = -1e9f;
        v[j] = x;
        mx = fmaxf(mx, x);
    }
    #pragma unroll
    for (int o = 16; o > 0; o >>= 1)
        mx = fmaxf(mx, __shfl_xor_sync(0xffffffffu, mx, o));
    if ((tid & 31) == 0) red[tid >> 5] = mx;
    __syncthreads();
    mx = red[0];
    #pragma unroll
    for (int w = 1; w < 8; w++) mx = fmaxf(mx, red[w]);

    float sum = 0.f;
    #pragma unroll
    for (int j = 0; j < 4; j++) { v[j] = expf(v[j] - mx); sum += v[j]; }
    #pragma unroll
    for (int o = 16; o > 0; o >>= 1)
        sum += __shfl_xor_sync(0xffffffffu, sum, o);
    if ((tid & 31) == 0) red[8 + (tid >> 5)] = sum;
    __syncthreads();
    sum = 0.f;
    #pragma unroll
    for (int w = 0; w < 8; w++) sum += red[8 + w];

    float inv = 1.0f / sum;
    #pragma unroll
    for (int j = 0; j < 4; j++) row[tid + 256 * j] = v[j] * inv;
}

// =====================================================================
// O = P V per (b,h). 128t x 64d tile, 128 threads, K=1024 in chunks of 32.
// =====================================================================
__global__ __launch_bounds__(128, 4)
void pv_kernel(const float* __restrict__ gs, const float* __restrict__ gv,
               float* __restrict__ gao)
{
    __shared__ float Ps[128][33];
    __shared__ float Vs[32][65];

    const int bh = blockIdx.y;
    const int b  = bh >> 4;
    const int h  = bh & 15;
    const int t0 = blockIdx.x * 128;
    const int tid = threadIdx.x;
    const int tx = tid & 7, ty = tid >> 3;

    const float* prow = gs + ((size_t)bh * DIM + t0) * DIM;
    const float* vb   = gv + (size_t)b * DIM * HW2 + h * HD;

    float acc[8][8];
    #pragma unroll
    for (int i = 0; i < 8; i++)
        #pragma unroll
        for (int j = 0; j < 8; j++) acc[i][j] = 0.f;

    for (int k0 = 0; k0 < DIM; k0 += 32) {
        __syncthreads();
        for (int i = tid; i < 128 * 32; i += 128) {
            int r = i >> 5, c = i & 31;
            Ps[r][c] = prow[(size_t)r * DIM + k0 + c];
        }
        for (int i = tid; i < 32 * 64; i += 128) {
            int r = i >> 6, c = i & 63;
            Vs[r][c] = vb[(size_t)(k0 + r) * HW2 + c];
        }
        __syncthreads();
        #pragma unroll
        for (int kk = 0; kk < 32; kk++) {
            float a[8], bvv[8];
            #pragma unroll
            for (int i = 0; i < 8; i++) a[i] = Ps[ty + 16 * i][kk];
            #pragma unroll
            for (int j = 0; j < 8; j++) bvv[j] = Vs[kk][tx + 8 * j];
            #pragma unroll
            for (int i = 0; i < 8; i++)
                #pragma unroll
                for (int j = 0; j < 8; j++) acc[i][j] += a[i] * bvv[j];
        }
    }

    #pragma unroll
    for (int i = 0; i < 8; i++)
        #pragma unroll
        for (int j = 0; j < 8; j++)
            gao[((size_t)b * DIM + t0 + ty + 16 * i) * HW2 + h * HD + tx + 8 * j] = acc[i][j];
}

// =====================================================================
// out = AO @ Wo^T + bo.  M = B*DIM = 8192, N = K = 1024.
// =====================================================================
__global__ __launch_bounds__(256, 2)
void proj_kernel(const float* __restrict__ gao, const float* __restrict__ Wo,
                 const float* __restrict__ bo, float* __restrict__ out)
{
    __shared__ float As[128][33];
    __shared__ float Bs[128][33];

    const int m0 = blockIdx.x * 128;
    const int n0 = blockIdx.y * 128;
    const int tid = threadIdx.x;
    const int tx = tid & 15, ty = tid >> 4;

    float acc[8][8];
    #pragma unroll
    for (int i = 0; i < 8; i++)
        #pragma unroll
        for (int j = 0; j < 8; j++) acc[i][j] = 0.f;

    for (int k0 = 0; k0 < DIM; k0 += 32) {
        __syncthreads();
        for (int i = tid; i < 128 * 32; i += 256) {
            int r = i >> 5, c = i & 31;
            As[r][c] = gao[(size_t)(m0 + r) * DIM + k0 + c];
            Bs[r][c] = Wo [(size_t)(n0 + r) * DIM + k0 + c];
        }
        __syncthreads();
        #pragma unroll
        for (int d = 0; d < 32; d++) {
            float a[8], bb[8];
            #pragma unroll
            for (int i = 0; i < 8; i++) a[i] = As[ty + 16 * i][d];
            #pragma unroll
            for (int j = 0; j < 8; j++) bb[j] = Bs[tx + 16 * j][d];
            #pragma unroll
            for (int i = 0; i < 8; i++)
                #pragma unroll
                for (int j = 0; j < 8; j++) acc[i][j] += a[i] * bb[j];
        }
    }

    #pragma unroll
    for (int i = 0; i < 8; i++)
        #pragma unroll
        for (int j = 0; j < 8; j++)
            out[(size_t)(m0 + ty + 16 * i) * DIM + n0 + tx + 16 * j] =
                acc[i][j] + bo[n0 + tx + 16 * j];
}

// =====================================================================
// kernel_launch
// Inputs: 0:q 1:k 2:v 3:Wq 4:bq 5:Wk 6:bk 7:Wv 8:bv 9:Wo 10:bo 11:mask
// =====================================================================
extern "C" void kernel_launch(void* const* d_in, const int* in_sizes, int n_in,
                              void* d_out, int out_size)
{
    (void)in_sizes; (void)n_in; (void)out_size;
    const float* q   = (const float*)d_in[0];
    const float* k   = (const float*)d_in[1];
    const float* v   = (const float*)d_in[2];
    const float* Wq  = (const float*)d_in[3];
    const float* bq  = (const float*)d_in[4];
    const float* Wk  = (const float*)d_in[5];
    const float* bk  = (const float*)d_in[6];
    const float* Wv  = (const float*)d_in[7];
    const float* bv  = (const float*)d_in[8];
    const float* Wo  = (const float*)d_in[9];
    const float* bo  = (const float*)d_in[10];
    const int*  mask = (const int*) d_in[11];
    float* out = (float*)d_out;

    float *gq, *gk, *gv, *gs, *gao;
    __nv_bfloat16 *whi, *wlo, *xthi, *xtlo;
    cudaGetSymbolAddress((void**)&gq,  g_q);
    cudaGetSymbolAddress((void**)&gk,  g_k);
    cudaGetSymbolAddress((void**)&gv,  g_v);
    cudaGetSymbolAddress((void**)&gs,  g_s);
    cudaGetSymbolAddress((void**)&gao, g_ao);
    cudaGetSymbolAddress((void**)&whi, g_whi);
    cudaGetSymbolAddress((void**)&wlo, g_wlo);
    cudaGetSymbolAddress((void**)&xthi, g_xthi);
    cudaGetSymbolAddress((void**)&xtlo, g_xtlo);

    cudaFuncSetAttribute(conv_mma_kernel,
                         cudaFuncAttributeMaxDynamicSharedMemorySize, CONV_SMEM_BYTES);

    // zero padded-x borders (full clear, interior overwritten by pack_x)
    zero4_kernel<<<XPK_ELEMS * 2 / 16 / 256, 256>>>((uint4*)xthi);
    zero4_kernel<<<XPK_ELEMS * 2 / 16 / 256, 256>>>((uint4*)xtlo);
    pack_w_kernel<<<WPK_ELEMS / 256, 256>>>(Wq, Wk, Wv, whi, wlo);
    pack_x_kernel<<<dim3(32, 32, 24), 256>>>(q, k, v, xthi, xtlo);

    conv_mma_kernel<<<dim3(8, 8, 24), 256, CONV_SMEM_BYTES>>>(
        whi, wlo, xthi, xtlo, bq, bk, bv, gq, gk, gv);

    qk_kernel<<<dim3(8, 8, NBH), 256>>>(gq, gk, gs);
    softmax_kernel<<<dim3(DIM, NBH), 256>>>(gs, mask);
    pv_kernel<<<dim3(8, NBH), 128>>>(gs, gv, gao);
    proj_kernel<<<dim3(64, 8), 256>>>(gao, Wo, bo, out);
}

// round 5
// speedup vs baseline: 4.6254x; 1.3655x over previous
#include <cuda_runtime.h>
#include <cuda_bf16.h>
#include <cstdint>
#include <math.h>

#define BATCH 8
#define DIM   1024
#define HEADS 16

__device__ __forceinline__ uint32_t smem_to_u32(const void* p) {
    uint32_t a;
    asm("{ .reg .u64 t; cvta.to.shared.u64 t, %1; cvt.u32.u64 %0, t; }" : "=r"(a) : "l"(p));
    return a;
}
#define CP_ASYNC16(d, s) asm volatile("cp.async.cg.shared.global [%0], [%1], 16;" :: "r"(d), "l"(s))
#define CP_COMMIT() asm volatile("cp.async.commit_group;")
#define CP_WAIT(N)  asm volatile("cp.async.wait_group %0;" :: "n"(N))
#define LDSM4(R0,R1,R2,R3,A) \
    asm volatile("ldmatrix.sync.aligned.m8n8.x4.shared.b16 {%0,%1,%2,%3}, [%4];" \
        : "=r"(R0),"=r"(R1),"=r"(R2),"=r"(R3) : "r"(A))
#define LDSM4T(R0,R1,R2,R3,A) \
    asm volatile("ldmatrix.sync.aligned.m8n8.x4.trans.shared.b16 {%0,%1,%2,%3}, [%4];" \
        : "=r"(R0),"=r"(R1),"=r"(R2),"=r"(R3) : "r"(A))
#define MMA16816(D,A0,A1,A2,A3,B0,B1) \
    asm volatile("mma.sync.aligned.m16n8k16.row.col.f32.bf16.bf16.f32 " \
        "{%0,%1,%2,%3}, {%4,%5,%6,%7}, {%8,%9}, {%0,%1,%2,%3};" \
        : "+f"((D)[0]),"+f"((D)[1]),"+f"((D)[2]),"+f"((D)[3]) \
        : "r"(A0),"r"(A1),"r"(A2),"r"(A3),"r"(B0),"r"(B1))

__device__ __forceinline__ void pack_hilo(float v0, float v1, uint32_t& hi, uint32_t& lo) {
    uint32_t h;
    asm("cvt.rn.bf16x2.f32 %0, %1, %2;" : "=r"(h) : "f"(v1), "f"(v0));
    float l0 = v0 - __uint_as_float(h << 16);
    float l1 = v1 - __uint_as_float(h & 0xffff0000u);
    asm("cvt.rn.bf16x2.f32 %0, %1, %2;" : "=r"(lo) : "f"(l1), "f"(l0));
    hi = h;
}

// ---------------- scratch ----------------
#define WPK_ELEMS (3u * 9u * 1024u * 1024u)
#define XPK_ELEMS (3u * 8u * 1156u * 1024u)
#define QKV_ELEMS (8u * 1024u * 1024u)
__device__ __align__(128) __nv_bfloat16 g_whi[WPK_ELEMS], g_wlo[WPK_ELEMS];
__device__ __align__(128) __nv_bfloat16 g_xthi[XPK_ELEMS], g_xtlo[XPK_ELEMS];
__device__ __align__(128) __nv_bfloat16 g_qh[QKV_ELEMS], g_ql[QKV_ELEMS];
__device__ __align__(128) __nv_bfloat16 g_kh[QKV_ELEMS], g_kl[QKV_ELEMS];
__device__ __align__(128) __nv_bfloat16 g_vh[QKV_ELEMS], g_vl[QKV_ELEMS];
__device__ __align__(128) __nv_bfloat16 g_aoh[QKV_ELEMS], g_aol[QKV_ELEMS];
__device__ __align__(128) __nv_bfloat16 g_woh[1024u*1024u], g_wol[1024u*1024u];
__device__ __align__(128) uint32_t g_mb[8u * 1024u * 32u];

// ---------------- prep ----------------
__global__ void zero4_kernel(uint4* p) {
    size_t i = (size_t)blockIdx.x * blockDim.x + threadIdx.x;
    p[i] = make_uint4(0u, 0u, 0u, 0u);
}

__global__ void pack_w_kernel(const float* __restrict__ Wq, const float* __restrict__ Wk,
                              const float* __restrict__ Wv,
                              __nv_bfloat16* __restrict__ whi, __nv_bfloat16* __restrict__ wlo) {
    size_t i = (size_t)blockIdx.x * blockDim.x + threadIdx.x;
    const size_t N1 = 9ull << 20;
    int conv = (int)(i / N1);
    size_t rem = i - (size_t)conv * N1;
    int kk = (int)(rem >> 20);
    int r2 = (int)(rem & 0xFFFFF);
    int co = r2 >> 10, ci = r2 & 1023;
    const float* W = conv == 0 ? Wq : (conv == 1 ? Wk : Wv);
    float w = W[((size_t)co * 1024 + ci) * 9 + kk];
    __nv_bfloat16 h = __float2bfloat16(w);
    whi[i] = h;
    wlo[i] = __float2bfloat16(w - __bfloat162float(h));
}

__global__ __launch_bounds__(256)
void pack_x_kernel(const float* __restrict__ q, const float* __restrict__ k,
                   const float* __restrict__ v,
                   __nv_bfloat16* __restrict__ xthi, __nv_bfloat16* __restrict__ xtlo) {
    __shared__ float t[32][33];
    const int conv = blockIdx.z >> 3, b = blockIdx.z & 7;
    const float* x = conv == 0 ? q : (conv == 1 ? k : v);
    const int r = blockIdx.x, ci0 = blockIdx.y * 32;
    const int tx = threadIdx.x & 31, ty = threadIdx.x >> 5;
    #pragma unroll
    for (int ii = 0; ii < 4; ii++)
        t[ty + 8*ii][tx] = x[((size_t)b * 1024 + ci0 + ty + 8*ii) * 1024 + r * 32 + tx];
    __syncthreads();
    size_t ob = ((size_t)(conv * 8 + b) * 1156 + (size_t)(r + 1) * 34 + 1) * 1024 + ci0;
    #pragma unroll
    for (int jj = 0; jj < 4; jj++) {
        int j = ty + 8*jj;
        float w = t[tx][j];
        __nv_bfloat16 h = __float2bfloat16(w);
        xthi[ob + (size_t)j * 1024 + tx] = h;
        xtlo[ob + (size_t)j * 1024 + tx] = __float2bfloat16(w - __bfloat162float(h));
    }
}

__global__ void pack_wo_kernel(const float* __restrict__ Wo,
                               __nv_bfloat16* __restrict__ wh, __nv_bfloat16* __restrict__ wl) {
    int i = blockIdx.x * 256 + threadIdx.x;
    float w = Wo[i];
    __nv_bfloat16 h = __float2bfloat16(w);
    wh[i] = h;
    wl[i] = __float2bfloat16(w - __bfloat162float(h));
}

__global__ void pack_mask_kernel(const int* __restrict__ mask, uint32_t* __restrict__ mb) {
    int idx = blockIdx.x * 256 + threadIdx.x;
    uint32_t word = __ballot_sync(0xffffffffu, mask[idx] != 0);
    if ((threadIdx.x & 31) == 0) mb[idx >> 5] = word;
}

// ---------------- conv implicit GEMM ----------------
#define CONV_SMEM_BYTES (2 * 4 * 16384)

__global__ __launch_bounds__(256, 1)
void conv_mma_kernel(const __nv_bfloat16* __restrict__ whi, const __nv_bfloat16* __restrict__ wlo,
                     const __nv_bfloat16* __restrict__ xthi, const __nv_bfloat16* __restrict__ xtlo,
                     const float* __restrict__ bq, const float* __restrict__ bk,
                     const float* __restrict__ bv,
                     __nv_bfloat16* __restrict__ qh, __nv_bfloat16* __restrict__ ql,
                     __nv_bfloat16* __restrict__ kh, __nv_bfloat16* __restrict__ kl,
                     __nv_bfloat16* __restrict__ vh, __nv_bfloat16* __restrict__ vl) {
    extern __shared__ char dsm[];
    const int tid = threadIdx.x, wid = tid >> 5, lane = tid & 31;
    const int co0 = blockIdx.x * 128, sp0 = blockIdx.y * 128, r0 = blockIdx.y * 4;
    const int conv = blockIdx.z >> 3, b = blockIdx.z & 7;
    const uint32_t sbase = smem_to_u32(dsm);
    const int rowb = tid >> 3, seg = tid & 7;
    int rb[4], cb[4];
    #pragma unroll
    for (int i = 0; i < 4; i++) {
        int row = rowb + 32 * i;
        rb[i] = r0 + (row >> 5); cb[i] = row & 31;
    }
    const size_t xbase = (size_t)(conv * 8 + b) * 1156 * 1024;

    auto load_chunk = [&](int c, int buf) {
        const int kk = c >> 4, ci0 = (c & 15) << 6;
        const int kkh = kk / 3, kw = kk - kkh * 3;
        const size_t wb = (((size_t)(conv * 9 + kk) * 1024 + co0) * 1024) + ci0 + seg * 8;
        const uint32_t sb = sbase + buf * 65536;
        #pragma unroll
        for (int i = 0; i < 4; i++) {
            int row = rowb + 32 * i;
            uint32_t sw = (uint32_t)(row * 128) + (uint32_t)(((seg ^ (row & 7)) << 4));
            CP_ASYNC16(sb + sw,         whi + wb + (size_t)row * 1024);
            CP_ASYNC16(sb + 16384 + sw, wlo + wb + (size_t)row * 1024);
            int pix = (rb[i] + kkh) * 34 + cb[i] + kw;
            size_t bo = xbase + (size_t)pix * 1024 + ci0 + seg * 8;
            CP_ASYNC16(sb + 32768 + sw, xthi + bo);
            CP_ASYNC16(sb + 49152 + sw, xtlo + bo);
        }
    };

    const int wm = (wid & 1) * 64, wn = (wid >> 1) * 32;
    int rowA[4], xorA[4];
    #pragma unroll
    for (int mt = 0; mt < 4; mt++) { rowA[mt] = wm + mt * 16 + (lane & 15); xorA[mt] = rowA[mt] & 7; }
    const int cgA = lane >> 4;
    int rowB[2], xorB[2];
    #pragma unroll
    for (int np = 0; np < 2; np++) {
        rowB[np] = wn + np * 16 + (lane & 7) + ((lane >> 4) & 1) * 8;
        xorB[np] = rowB[np] & 7;
    }
    const int cgB = (lane >> 3) & 1;

    float acc[4][4][4];
    #pragma unroll
    for (int mt = 0; mt < 4; mt++)
        #pragma unroll
        for (int nt = 0; nt < 4; nt++)
            #pragma unroll
            for (int e = 0; e < 4; e++) acc[mt][nt][e] = 0.f;

    load_chunk(0, 0); CP_COMMIT();
    for (int c = 0; c < 144; ++c) {
        const int buf = c & 1;
        if (c < 143) { load_chunk(c + 1, (c + 1) & 1); CP_COMMIT(); CP_WAIT(1); }
        else         { CP_WAIT(0); }
        __syncthreads();
        const uint32_t sb = sbase + buf * 65536;
        const uint32_t aHi = sb, aLo = sb + 16384, bHi = sb + 32768, bLo = sb + 49152;
        #pragma unroll
        for (int ks = 0; ks < 4; ks++) {
            uint32_t ah[4][4], al[4][4], bh2[2][4], bl2[2][4];
            #pragma unroll
            for (int mt = 0; mt < 4; mt++) {
                uint32_t off = (uint32_t)(rowA[mt] * 128) + (uint32_t)(((ks*2+cgA) ^ xorA[mt]) << 4);
                LDSM4(ah[mt][0], ah[mt][1], ah[mt][2], ah[mt][3], aHi + off);
                LDSM4(al[mt][0], al[mt][1], al[mt][2], al[mt][3], aLo + off);
            }
            #pragma unroll
            for (int np = 0; np < 2; np++) {
                uint32_t off = (uint32_t)(rowB[np] * 128) + (uint32_t)(((ks*2+cgB) ^ xorB[np]) << 4);
                LDSM4(bh2[np][0], bh2[np][1], bh2[np][2], bh2[np][3], bHi + off);
                LDSM4(bl2[np][0], bl2[np][1], bl2[np][2], bl2[np][3], bLo + off);
            }
            #pragma unroll
            for (int mt = 0; mt < 4; mt++)
                #pragma unroll
                for (int nt = 0; nt < 4; nt++) {
                    const int np = nt >> 1, h = (nt & 1) * 2;
                    MMA16816(acc[mt][nt], ah[mt][0],ah[mt][1],ah[mt][2],ah[mt][3], bh2[np][h], bh2[np][h+1]);
                    MMA16816(acc[mt][nt], ah[mt][0],ah[mt][1],ah[mt][2],ah[mt][3], bl2[np][h], bl2[np][h+1]);
                    MMA16816(acc[mt][nt], al[mt][0],al[mt][1],al[mt][2],al[mt][3], bh2[np][h], bh2[np][h+1]);
                }
        }
        __syncthreads();
    }

    __nv_bfloat16 *oh, *ol;
    const float* bias;
    if (conv == 0)      { oh = qh; ol = ql; bias = bq; }
    else if (conv == 1) { oh = kh; ol = kl; bias = bk; }
    else                { oh = vh; ol = vl; bias = bv; }
    const float scale = (conv == 0) ? 0.125f : 1.0f;
    #pragma unroll
    for (int mt = 0; mt < 4; mt++) {
        const int co_a = co0 + wm + mt * 16 + (lane >> 2);
        const int co_b = co_a + 8;
        const float bi_a = bias[co_a], bi_b = bias[co_b];
        #pragma unroll
        for (int nt = 0; nt < 4; nt++) {
            const int sp = sp0 + wn + nt * 8 + 2 * (lane & 3);
            uint32_t h01, l01, h23, l23;
            pack_hilo((acc[mt][nt][0] + bi_a) * scale, (acc[mt][nt][1] + bi_a) * scale, h01, l01);
            pack_hilo((acc[mt][nt][2] + bi_b) * scale, (acc[mt][nt][3] + bi_b) * scale, h23, l23);
            size_t oa = ((size_t)b * 1024 + co_a) * 1024 + sp;
            size_t ob = ((size_t)b * 1024 + co_b) * 1024 + sp;
            *(uint32_t*)(oh + oa) = h01; *(uint32_t*)(ol + oa) = l01;
            *(uint32_t*)(oh + ob) = h23; *(uint32_t*)(ol + ob) = l23;
        }
    }
}

// ---------------- fused flash attention ----------------
#define FA_KVBUF 65536
#define FA_QOFF  (2 * FA_KVBUF)
#define FA_MOFF  (FA_QOFF + 32768)
#define FA_SMEM_BYTES (FA_MOFF + 128 * 33 * 4)

__global__ __launch_bounds__(256, 1)
void flash_kernel(const __nv_bfloat16* __restrict__ qh_g, const __nv_bfloat16* __restrict__ ql_g,
                  const __nv_bfloat16* __restrict__ kh_g, const __nv_bfloat16* __restrict__ kl_g,
                  const __nv_bfloat16* __restrict__ vh_g, const __nv_bfloat16* __restrict__ vl_g,
                  const uint32_t* __restrict__ mbits,
                  __nv_bfloat16* __restrict__ aoh_g, __nv_bfloat16* __restrict__ aol_g) {
    extern __shared__ char dsm[];
    const int tid = threadIdx.x, wid = tid >> 5, lane = tid & 31;
    const int t0 = blockIdx.x * 128, bh = blockIdx.y, b = bh >> 4, h = bh & 15;
    const uint32_t sb = smem_to_u32(dsm);
    uint32_t* msk = (uint32_t*)(dsm + FA_MOFF);
    const int rowb = tid >> 3, seg = tid & 7;
    const size_t rbase = (size_t)b * 1024;
    const int fcol = h * 64, wt0 = wid * 16;

    auto load_kv = [&](int c, int buf) {
        const uint32_t p = sb + buf * FA_KVBUF;
        const int s0 = c * 128;
        #pragma unroll
        for (int i = 0; i < 4; i++) {
            int row = rowb + 32 * i;
            uint32_t sw = (uint32_t)(row * 128) + (uint32_t)(((seg ^ (row & 7)) << 4));
            size_t go = (rbase + s0 + row) * 1024 + fcol + seg * 8;
            CP_ASYNC16(p + sw,         kh_g + go);
            CP_ASYNC16(p + 16384 + sw, kl_g + go);
            CP_ASYNC16(p + 32768 + sw, vh_g + go);
            CP_ASYNC16(p + 49152 + sw, vl_g + go);
        }
    };

    #pragma unroll
    for (int i = 0; i < 4; i++) {
        int row = rowb + 32 * i;
        uint32_t sw = (uint32_t)(row * 128) + (uint32_t)(((seg ^ (row & 7)) << 4));
        size_t go = (rbase + t0 + row) * 1024 + fcol + seg * 8;
        CP_ASYNC16(sb + FA_QOFF + sw,         qh_g + go);
        CP_ASYNC16(sb + FA_QOFF + 16384 + sw, ql_g + go);
    }
    #pragma unroll
    for (int j = 0; j < 16; j++) {
        int idx = tid + 256 * j;
        int r = idx >> 5, w = idx & 31;
        msk[r * 33 + w] = mbits[((size_t)b * 1024 + t0 + r) * 32 + w];
    }
    load_kv(0, 0); CP_COMMIT();

    float m0 = -INFINITY, m1 = -INFINITY, l0 = 0.f, l1 = 0.f;
    float o[8][4];
    #pragma unroll
    for (int j = 0; j < 8; j++)
        #pragma unroll
        for (int e = 0; e < 4; e++) o[j][e] = 0.f;
    uint32_t qfh[4][4], qfl[4][4];
    const int lr0 = wt0 + (lane >> 2);

    #pragma unroll 1
    for (int c = 0; c < 8; c++) {
        if (c < 7) { load_kv(c + 1, (c + 1) & 1); CP_COMMIT(); CP_WAIT(1); }
        else       { CP_WAIT(0); }
        __syncthreads();
        if (c == 0) {
            const int rA = wt0 + (lane & 15), cg = lane >> 4;
            #pragma unroll
            for (int ks = 0; ks < 4; ks++) {
                uint32_t off = (uint32_t)(rA * 128) + (uint32_t)((((ks*2+cg)) ^ (rA & 7)) << 4);
                LDSM4(qfh[ks][0], qfh[ks][1], qfh[ks][2], qfh[ks][3], sb + FA_QOFF + off);
                LDSM4(qfl[ks][0], qfl[ks][1], qfl[ks][2], qfl[ks][3], sb + FA_QOFF + 16384 + off);
            }
        }
        const uint32_t kv = sb + (c & 1) * FA_KVBUF;

        float s[16][4];
        #pragma unroll
        for (int i = 0; i < 16; i++)
            #pragma unroll
            for (int e = 0; e < 4; e++) s[i][e] = 0.f;
        #pragma unroll
        for (int np = 0; np < 8; np++) {
            const int rB = np * 16 + (lane & 7) + ((lane >> 4) & 1) * 8;
            const int cg = (lane >> 3) & 1;
            #pragma unroll
            for (int ks = 0; ks < 4; ks++) {
                uint32_t off = (uint32_t)(rB * 128) + (uint32_t)((((ks*2+cg)) ^ (rB & 7)) << 4);
                uint32_t k4[4], kl4[4];
                LDSM4(k4[0], k4[1], k4[2], k4[3], kv + off);
                LDSM4(kl4[0], kl4[1], kl4[2], kl4[3], kv + 16384 + off);
                MMA16816(s[2*np],   qfh[ks][0],qfh[ks][1],qfh[ks][2],qfh[ks][3], k4[0], k4[1]);
                MMA16816(s[2*np],   qfh[ks][0],qfh[ks][1],qfh[ks][2],qfh[ks][3], kl4[0], kl4[1]);
                MMA16816(s[2*np],   qfl[ks][0],qfl[ks][1],qfl[ks][2],qfl[ks][3], k4[0], k4[1]);
                MMA16816(s[2*np+1], qfh[ks][0],qfh[ks][1],qfh[ks][2],qfh[ks][3], k4[2], k4[3]);
                MMA16816(s[2*np+1], qfh[ks][0],qfh[ks][1],qfh[ks][2],qfh[ks][3], kl4[2], kl4[3]);
                MMA16816(s[2*np+1], qfl[ks][0],qfl[ks][1],qfl[ks][2],qfl[ks][3], k4[2], k4[3]);
            }
        }

        float cm0 = -3.4e38f, cm1 = -3.4e38f;
        #pragma unroll
        for (int nt = 0; nt < 16; nt++) {
            const int bp = (8 * nt + 2 * (lane & 3)) & 31;
            const uint32_t wa = msk[lr0 * 33 + c * 4 + (nt >> 2)];
            const uint32_t wb = msk[(lr0 + 8) * 33 + c * 4 + (nt >> 2)];
            if (!((wa >> bp) & 1))       s[nt][0] = -1e9f;
            if (!((wa >> (bp + 1)) & 1)) s[nt][1] = -1e9f;
            if (!((wb >> bp) & 1))       s[nt][2] = -1e9f;
            if (!((wb >> (bp + 1)) & 1)) s[nt][3] = -1e9f;
            cm0 = fmaxf(cm0, fmaxf(s[nt][0], s[nt][1]));
            cm1 = fmaxf(cm1, fmaxf(s[nt][2], s[nt][3]));
        }
        cm0 = fmaxf(cm0, __shfl_xor_sync(0xffffffffu, cm0, 1));
        cm0 = fmaxf(cm0, __shfl_xor_sync(0xffffffffu, cm0, 2));
        cm1 = fmaxf(cm1, __shfl_xor_sync(0xffffffffu, cm1, 1));
        cm1 = fmaxf(cm1, __shfl_xor_sync(0xffffffffu, cm1, 2));
        float mn0 = fmaxf(m0, cm0), mn1 = fmaxf(m1, cm1);
        float sc0 = __expf(m0 - mn0), sc1 = __expf(m1 - mn1);
        m0 = mn0; m1 = mn1;
        float rs0 = 0.f, rs1 = 0.f;
        #pragma unroll
        for (int nt = 0; nt < 16; nt++) {
            s[nt][0] = __expf(s[nt][0] - mn0); s[nt][1] = __expf(s[nt][1] - mn0);
            s[nt][2] = __expf(s[nt][2] - mn1); s[nt][3] = __expf(s[nt][3] - mn1);
            rs0 += s[nt][0] + s[nt][1];
            rs1 += s[nt][2] + s[nt][3];
        }
        l0 = l0 * sc0 + rs0; l1 = l1 * sc1 + rs1;
        #pragma unroll
        for (int j = 0; j < 8; j++) {
            o[j][0] *= sc0; o[j][1] *= sc0; o[j][2] *= sc1; o[j][3] *= sc1;
        }

        #pragma unroll
        for (int ks = 0; ks < 8; ks++) {
            uint32_t ph[4], pl[4];
            pack_hilo(s[2*ks][0],   s[2*ks][1],   ph[0], pl[0]);
            pack_hilo(s[2*ks][2],   s[2*ks][3],   ph[1], pl[1]);
            pack_hilo(s[2*ks+1][0], s[2*ks+1][1], ph[2], pl[2]);
            pack_hilo(s[2*ks+1][2], s[2*ks+1][3], ph[3], pl[3]);
            const int vrow = ks * 16 + (lane & 7) + 8 * ((lane >> 3) & 1);
            #pragma unroll
            for (int ds = 0; ds < 4; ds++) {
                uint32_t off = (uint32_t)(vrow * 128) +
                               (uint32_t)((((ds*2 + (lane >> 4))) ^ (vrow & 7)) << 4);
                uint32_t v4[4], vl4[4];
                LDSM4T(v4[0], v4[1], v4[2], v4[3], kv + 32768 + off);
                LDSM4T(vl4[0], vl4[1], vl4[2], vl4[3], kv + 49152 + off);
                MMA16816(o[2*ds],   ph[0],ph[1],ph[2],ph[3], v4[0], v4[1]);
                MMA16816(o[2*ds],   ph[0],ph[1],ph[2],ph[3], vl4[0], vl4[1]);
                MMA16816(o[2*ds],   pl[0],pl[1],pl[2],pl[3], v4[0], v4[1]);
                MMA16816(o[2*ds+1], ph[0],ph[1],ph[2],ph[3], v4[2], v4[3]);
                MMA16816(o[2*ds+1], ph[0],ph[1],ph[2],ph[3], vl4[2], vl4[3]);
                MMA16816(o[2*ds+1], pl[0],pl[1],pl[2],pl[3], v4[2], v4[3]);
            }
        }
        __syncthreads();
    }

    l0 += __shfl_xor_sync(0xffffffffu, l0, 1);
    l0 += __shfl_xor_sync(0xffffffffu, l0, 2);
    l1 += __shfl_xor_sync(0xffffffffu, l1, 1);
    l1 += __shfl_xor_sync(0xffffffffu, l1, 2);
    const float i0 = 1.f / l0, i1 = 1.f / l1;
    size_t ra = (rbase + t0 + lr0) * 1024 + fcol + 2 * (lane & 3);
    size_t rb2 = ra + 8 * 1024;
    #pragma unroll
    for (int j = 0; j < 8; j++) {
        uint32_t h0, lo0, h1, lo1;
        pack_hilo(o[j][0] * i0, o[j][1] * i0, h0, lo0);
        pack_hilo(o[j][2] * i1, o[j][3] * i1, h1, lo1);
        *(uint32_t*)(aoh_g + ra + 8*j)  = h0;
        *(uint32_t*)(aol_g + ra + 8*j)  = lo0;
        *(uint32_t*)(aoh_g + rb2 + 8*j) = h1;
        *(uint32_t*)(aol_g + rb2 + 8*j) = lo1;
    }
}

// ---------------- projection GEMM ----------------
#define PROJ_SMEM_BYTES (2 * 4 * 16384)

__global__ __launch_bounds__(256, 1)
void proj_mma_kernel(const __nv_bfloat16* __restrict__ ah_g, const __nv_bfloat16* __restrict__ al_g,
                     const __nv_bfloat16* __restrict__ wh_g, const __nv_bfloat16* __restrict__ wl_g,
                     const float* __restrict__ bo, float* __restrict__ out) {
    extern __shared__ char dsm[];
    const int tid = threadIdx.x, wid = tid >> 5, lane = tid & 31;
    const int m0 = blockIdx.x * 128, n0 = blockIdx.y * 128;
    const uint32_t sbase = smem_to_u32(dsm);
    const int rowb = tid >> 3, seg = tid & 7;

    auto load_chunk = [&](int c, int buf) {
        const int ci0 = c << 6;
        const uint32_t sb = sbase + buf * 65536;
        #pragma unroll
        for (int i = 0; i < 4; i++) {
            int row = rowb + 32 * i;
            uint32_t sw = (uint32_t)(row * 128) + (uint32_t)(((seg ^ (row & 7)) << 4));
            size_t ao = (size_t)(m0 + row) * 1024 + ci0 + seg * 8;
            size_t wo = (size_t)(n0 + row) * 1024 + ci0 + seg * 8;
            CP_ASYNC16(sb + sw,         ah_g + ao);
            CP_ASYNC16(sb + 16384 + sw, al_g + ao);
            CP_ASYNC16(sb + 32768 + sw, wh_g + wo);
            CP_ASYNC16(sb + 49152 + sw, wl_g + wo);
        }
    };

    const int wm = (wid & 1) * 64, wn = (wid >> 1) * 32;
    int rowA[4], xorA[4];
    #pragma unroll
    for (int mt = 0; mt < 4; mt++) { rowA[mt] = wm + mt * 16 + (lane & 15); xorA[mt] = rowA[mt] & 7; }
    const int cgA = lane >> 4;
    int rowB[2], xorB[2];
    #pragma unroll
    for (int np = 0; np < 2; np++) {
        rowB[np] = wn + np * 16 + (lane & 7) + ((lane >> 4) & 1) * 8;
        xorB[np] = rowB[np] & 7;
    }
    const int cgB = (lane >> 3) & 1;

    float acc[4][4][4];
    #pragma unroll
    for (int mt = 0; mt < 4; mt++)
        #pragma unroll
        for (int nt = 0; nt < 4; nt++)
            #pragma unroll
            for (int e = 0; e < 4; e++) acc[mt][nt][e] = 0.f;

    load_chunk(0, 0); CP_COMMIT();
    for (int c = 0; c < 16; ++c) {
        const int buf = c & 1;
        if (c < 15) { load_chunk(c + 1, (c + 1) & 1); CP_COMMIT(); CP_WAIT(1); }
        else        { CP_WAIT(0); }
        __syncthreads();
        const uint32_t sb = sbase + buf * 65536;
        const uint32_t aHi = sb, aLo = sb + 16384, bHi = sb + 32768, bLo = sb + 49152;
        #pragma unroll
        for (int ks = 0; ks < 4; ks++) {
            uint32_t ah[4][4], al[4][4], bh2[2][4], bl2[2][4];
            #pragma unroll
            for (int mt = 0; mt < 4; mt++) {
                uint32_t off = (uint32_t)(rowA[mt] * 128) + (uint32_t)(((ks*2+cgA) ^ xorA[mt]) << 4);
                LDSM4(ah[mt][0], ah[mt][1], ah[mt][2], ah[mt][3], aHi + off);
                LDSM4(al[mt][0], al[mt][1], al[mt][2], al[mt][3], aLo + off);
            }
            #pragma unroll
            for (int np = 0; np < 2; np++) {
                uint32_t off = (uint32_t)(rowB[np] * 128) + (uint32_t)(((ks*2+cgB) ^ xorB[np]) << 4);
                LDSM4(bh2[np][0], bh2[np][1], bh2[np][2], bh2[np][3], bHi + off);
                LDSM4(bl2[np][0], bl2[np][1], bl2[np][2], bl2[np][3], bLo + off);
            }
            #pragma unroll
            for (int mt = 0; mt < 4; mt++)
                #pragma unroll
                for (int nt = 0; nt < 4; nt++) {
                    const int np = nt >> 1, h = (nt & 1) * 2;
                    MMA16816(acc[mt][nt], ah[mt][0],ah[mt][1],ah[mt][2],ah[mt][3], bh2[np][h], bh2[np][h+1]);
                    MMA16816(acc[mt][nt], ah[mt][0],ah[mt][1],ah[mt][2],ah[mt][3], bl2[np][h], bl2[np][h+1]);
                    MMA16816(acc[mt][nt], al[mt][0],al[mt][1],al[mt][2],al[mt][3], bh2[np][h], bh2[np][h+1]);
                }
        }
        __syncthreads();
    }

    #pragma unroll
    for (int mt = 0; mt < 4; mt++) {
        const int ma = m0 + wm + mt * 16 + (lane >> 2);
        const int mb2 = ma + 8;
        #pragma unroll
        for (int nt = 0; nt < 4; nt++) {
            const int n = n0 + wn + nt * 8 + 2 * (lane & 3);
            const float b0 = bo[n], b1 = bo[n + 1];
            *(float2*)(out + (size_t)ma * 1024 + n)  = make_float2(acc[mt][nt][0] + b0, acc[mt][nt][1] + b1);
            *(float2*)(out + (size_t)mb2 * 1024 + n) = make_float2(acc[mt][nt][2] + b0, acc[mt][nt][3] + b1);
        }
    }
}

// ---------------- kernel_launch ----------------
extern "C" void kernel_launch(void* const* d_in, const int* in_sizes, int n_in,
                              void* d_out, int out_size)
{
    (void)in_sizes; (void)n_in; (void)out_size;
    const float* q   = (const float*)d_in[0];
    const float* k   = (const float*)d_in[1];
    const float* v   = (const float*)d_in[2];
    const float* Wq  = (const float*)d_in[3];
    const float* bq  = (const float*)d_in[4];
    const float* Wk  = (const float*)d_in[5];
    const float* bk  = (const float*)d_in[6];
    const float* Wv  = (const float*)d_in[7];
    const float* bv  = (const float*)d_in[8];
    const float* Wo  = (const float*)d_in[9];
    const float* bo  = (const float*)d_in[10];
    const int*  mask = (const int*) d_in[11];
    float* out = (float*)d_out;

    __nv_bfloat16 *whi, *wlo, *xthi, *xtlo, *qh, *ql, *kh, *kl, *vh, *vl, *aoh, *aol, *woh, *wol;
    uint32_t* mb;
    cudaGetSymbolAddress((void**)&whi, g_whi);   cudaGetSymbolAddress((void**)&wlo, g_wlo);
    cudaGetSymbolAddress((void**)&xthi, g_xthi); cudaGetSymbolAddress((void**)&xtlo, g_xtlo);
    cudaGetSymbolAddress((void**)&qh, g_qh);     cudaGetSymbolAddress((void**)&ql, g_ql);
    cudaGetSymbolAddress((void**)&kh, g_kh);     cudaGetSymbolAddress((void**)&kl, g_kl);
    cudaGetSymbolAddress((void**)&vh, g_vh);     cudaGetSymbolAddress((void**)&vl, g_vl);
    cudaGetSymbolAddress((void**)&aoh, g_aoh);   cudaGetSymbolAddress((void**)&aol, g_aol);
    cudaGetSymbolAddress((void**)&woh, g_woh);   cudaGetSymbolAddress((void**)&wol, g_wol);
    cudaGetSymbolAddress((void**)&mb, g_mb);

    cudaFuncSetAttribute(conv_mma_kernel, cudaFuncAttributeMaxDynamicSharedMemorySize, CONV_SMEM_BYTES);
    cudaFuncSetAttribute(flash_kernel,    cudaFuncAttributeMaxDynamicSharedMemorySize, FA_SMEM_BYTES);
    cudaFuncSetAttribute(proj_mma_kernel, cudaFuncAttributeMaxDynamicSharedMemorySize, PROJ_SMEM_BYTES);

    zero4_kernel<<<XPK_ELEMS * 2 / 16 / 256, 256>>>((uint4*)xthi);
    zero4_kernel<<<XPK_ELEMS * 2 / 16 / 256, 256>>>((uint4*)xtlo);
    pack_w_kernel<<<WPK_ELEMS / 256, 256>>>(Wq, Wk, Wv, whi, wlo);
    pack_x_kernel<<<dim3(32, 32, 24), 256>>>(q, k, v, xthi, xtlo);
    pack_wo_kernel<<<4096, 256>>>(Wo, woh, wol);
    pack_mask_kernel<<<32768, 256>>>(mask, mb);

    conv_mma_kernel<<<dim3(8, 8, 24), 256, CONV_SMEM_BYTES>>>(
        whi, wlo, xthi, xtlo, bq, bk, bv, qh, ql, kh, kl, vh, vl);

    flash_kernel<<<dim3(8, 128), 256, FA_SMEM_BYTES>>>(
        qh, ql, kh, kl, vh, vl, mb, aoh, aol);

    proj_mma_kernel<<<dim3(64, 8), 256, PROJ_SMEM_BYTES>>>(aoh, aol, woh, wol, bo, out);
}

// round 6
// speedup vs baseline: 8.5290x; 1.8440x over previous
#include <cuda_runtime.h>
#include <cuda_bf16.h>
#include <cstdint>
#include <math.h>

__device__ __forceinline__ uint32_t smem_to_u32(const void* p) {
    uint32_t a;
    asm("{ .reg .u64 t; cvta.to.shared.u64 t, %1; cvt.u32.u64 %0, t; }" : "=r"(a) : "l"(p));
    return a;
}
#define CP_ASYNC16(d, s) asm volatile("cp.async.cg.shared.global [%0], [%1], 16;" :: "r"(d), "l"(s))
#define CP_COMMIT() asm volatile("cp.async.commit_group;")
#define CP_WAIT(N)  asm volatile("cp.async.wait_group %0;" :: "n"(N))
#define LDSM4(R0,R1,R2,R3,A) \
    asm volatile("ldmatrix.sync.aligned.m8n8.x4.shared.b16 {%0,%1,%2,%3}, [%4];" \
        : "=r"(R0),"=r"(R1),"=r"(R2),"=r"(R3) : "r"(A))
#define LDSM4T(R0,R1,R2,R3,A) \
    asm volatile("ldmatrix.sync.aligned.m8n8.x4.trans.shared.b16 {%0,%1,%2,%3}, [%4];" \
        : "=r"(R0),"=r"(R1),"=r"(R2),"=r"(R3) : "r"(A))
#define MMA16816(D,A0,A1,A2,A3,B0,B1) \
    asm volatile("mma.sync.aligned.m16n8k16.row.col.f32.bf16.bf16.f32 " \
        "{%0,%1,%2,%3}, {%4,%5,%6,%7}, {%8,%9}, {%0,%1,%2,%3};" \
        : "+f"((D)[0]),"+f"((D)[1]),"+f"((D)[2]),"+f"((D)[3]) \
        : "r"(A0),"r"(A1),"r"(A2),"r"(A3),"r"(B0),"r"(B1))

__device__ __forceinline__ void pack_hilo(float v0, float v1, uint32_t& hi, uint32_t& lo) {
    uint32_t h;
    asm("cvt.rn.bf16x2.f32 %0, %1, %2;" : "=r"(h) : "f"(v1), "f"(v0));
    float l0 = v0 - __uint_as_float(h << 16);
    float l1 = v1 - __uint_as_float(h & 0xffff0000u);
    asm("cvt.rn.bf16x2.f32 %0, %1, %2;" : "=r"(lo) : "f"(l1), "f"(l0));
    hi = h;
}

// ---------------- scratch ----------------
#define QKV_ELEMS (8u * 1024u * 1024u)
#define UW_ELEMS  (48ull * 1024u * 1024u)
#define VW_ELEMS  (48ull * 2048u * 1024u)
__device__ __align__(128) __nv_bfloat16 g_uwh[UW_ELEMS], g_uwl[UW_ELEMS];   // U[g][co][ci]
__device__ __align__(128) __nv_bfloat16 g_vwh[VW_ELEMS], g_vwl[VW_ELEMS];   // V[g][tile][ci]
__device__ __align__(128) float g_mw[48ull * 1024u * 2048u];                // M[g][co][tile]
__device__ __align__(128) __nv_bfloat16 g_qh[QKV_ELEMS], g_ql[QKV_ELEMS];
__device__ __align__(128) __nv_bfloat16 g_kh[QKV_ELEMS], g_kl[QKV_ELEMS];
__device__ __align__(128) __nv_bfloat16 g_vh[QKV_ELEMS], g_vl[QKV_ELEMS];
__device__ __align__(128) __nv_bfloat16 g_aoh[QKV_ELEMS], g_aol[QKV_ELEMS];
__device__ __align__(128) __nv_bfloat16 g_woh[1024u*1024u], g_wol[1024u*1024u];
__device__ __align__(128) uint32_t g_mb[8u * 1024u * 32u];

// ---------------- prep ----------------
__global__ void pack_wo_kernel(const float* __restrict__ Wo,
                               __nv_bfloat16* __restrict__ wh, __nv_bfloat16* __restrict__ wl) {
    int i = blockIdx.x * 256 + threadIdx.x;
    float w = Wo[i];
    __nv_bfloat16 h = __float2bfloat16(w);
    wh[i] = h;
    wl[i] = __float2bfloat16(w - __bfloat162float(h));
}

__global__ void pack_mask_kernel(const int* __restrict__ mask, uint32_t* __restrict__ mb) {
    int idx = blockIdx.x * 256 + threadIdx.x;
    uint32_t word = __ballot_sync(0xffffffffu, mask[idx] != 0);
    if ((threadIdx.x & 31) == 0) mb[idx >> 5] = word;
}

// ---------------- Winograd weight transform: U = G g G^T ----------------
__global__ __launch_bounds__(256)
void wino_w_kernel(const float* __restrict__ Wq, const float* __restrict__ Wk,
                   const float* __restrict__ Wv,
                   __nv_bfloat16* __restrict__ uh, __nv_bfloat16* __restrict__ ul) {
    int i = blockIdx.x * 256 + threadIdx.x;        // < 3*2^20
    int conv = i >> 20;
    int co = (i >> 10) & 1023, ci = i & 1023;
    const float* W = conv == 0 ? Wq : (conv == 1 ? Wk : Wv);
    const float* g = W + ((size_t)co * 1024 + ci) * 9;
    float gm[3][3];
    #pragma unroll
    for (int r = 0; r < 3; r++)
        #pragma unroll
        for (int c = 0; c < 3; c++) gm[r][c] = g[r * 3 + c];
    float t[4][3];
    #pragma unroll
    for (int c = 0; c < 3; c++) {
        t[0][c] = gm[0][c];
        t[1][c] = 0.5f * (gm[0][c] + gm[1][c] + gm[2][c]);
        t[2][c] = 0.5f * (gm[0][c] - gm[1][c] + gm[2][c]);
        t[3][c] = gm[2][c];
    }
    #pragma unroll
    for (int u = 0; u < 4; u++) {
        float U0 = t[u][0];
        float U1 = 0.5f * (t[u][0] + t[u][1] + t[u][2]);
        float U2 = 0.5f * (t[u][0] - t[u][1] + t[u][2]);
        float U3 = t[u][2];
        float Uv[4] = {U0, U1, U2, U3};
        #pragma unroll
        for (int v = 0; v < 4; v++) {
            int k = u * 4 + v;
            size_t o = (((size_t)(conv * 16 + k)) << 20) + ((size_t)co << 10) + ci;
            __nv_bfloat16 h = __float2bfloat16(Uv[v]);
            uh[o] = h;
            ul[o] = __float2bfloat16(Uv[v] - __bfloat162float(h));
        }
    }
}

// ---------------- Winograd input transform: V = B^T d B ----------------
// grid (16 ty, 16 ci-chunk, 24 = conv*8+b), 256 threads.
__global__ __launch_bounds__(256)
void wino_x_kernel(const float* __restrict__ q, const float* __restrict__ k,
                   const float* __restrict__ v,
                   __nv_bfloat16* __restrict__ vwh, __nv_bfloat16* __restrict__ vwl) {
    __shared__ float xs[4][64][35];   // [u][ci][col index 0 == image col -1]
    const int conv = blockIdx.z >> 3, b = blockIdx.z & 7;
    const float* x = conv == 0 ? q : (conv == 1 ? k : v);
    const int ty = blockIdx.x;
    const int ci0 = blockIdx.y * 64;
    const int tid = threadIdx.x;

    for (int l = tid; l < 4 * 64 * 34; l += 256) {
        int u = l / 2176;
        int rem = l - u * 2176;
        int ci = rem / 34, cc = rem - ci * 34;
        int gr = 2 * ty - 1 + u, gc = cc - 1;
        float val = 0.f;
        if ((unsigned)gr < 32u && (unsigned)gc < 32u)
            val = x[((size_t)(b * 1024 + ci0 + ci)) * 1024 + gr * 32 + gc];
        xs[u][ci][cc] = val;
    }
    __syncthreads();

    #pragma unroll
    for (int jj = 0; jj < 4; jj++) {
        int item = tid + 256 * jj;
        int tx = item >> 6, ci = item & 63;
        float d[4][4];
        #pragma unroll
        for (int u = 0; u < 4; u++)
            #pragma unroll
            for (int vv = 0; vv < 4; vv++) d[u][vv] = xs[u][ci][2 * tx + vv];
        float r0[4], r1[4], r2[4], r3[4];
        #pragma unroll
        for (int vv = 0; vv < 4; vv++) {
            r0[vv] = d[0][vv] - d[2][vv];
            r1[vv] = d[1][vv] + d[2][vv];
            r2[vv] = d[2][vv] - d[1][vv];
            r3[vv] = d[1][vv] - d[3][vv];
        }
        float V[4][4];
        #pragma unroll
        for (int u = 0; u < 4; u++) {
            float* rr = u == 0 ? r0 : (u == 1 ? r1 : (u == 2 ? r2 : r3));
            V[u][0] = rr[0] - rr[2];
            V[u][1] = rr[1] + rr[2];
            V[u][2] = rr[2] - rr[1];
            V[u][3] = rr[1] - rr[3];
        }
        size_t tile = (size_t)b * 256 + ty * 16 + tx;
        #pragma unroll
        for (int u = 0; u < 4; u++)
            #pragma unroll
            for (int vv = 0; vv < 4; vv++) {
                int kk = u * 4 + vv;
                size_t o = ((size_t)(conv * 16 + kk) * 2048 + tile) * 1024 + ci0 + ci;
                __nv_bfloat16 h = __float2bfloat16(V[u][vv]);
                vwh[o] = h;
                vwl[o] = __float2bfloat16(V[u][vv] - __bfloat162float(h));
            }
    }
}

// ---------------- Winograd batched GEMM: M[g] = U[g] * V[g]^T ----------------
#define GEMM_SMEM_BYTES (2 * 4 * 16384)

__global__ __launch_bounds__(256, 1)
void wino_gemm_kernel(const __nv_bfloat16* __restrict__ uh, const __nv_bfloat16* __restrict__ ul,
                      const __nv_bfloat16* __restrict__ vwh, const __nv_bfloat16* __restrict__ vwl,
                      float* __restrict__ mw) {
    extern __shared__ char dsm[];
    const int tid = threadIdx.x, wid = tid >> 5, lane = tid & 31;
    const int m0 = blockIdx.x * 128, n0 = blockIdx.y * 128, gidx = blockIdx.z;
    const __nv_bfloat16* ah_g = uh  + ((size_t)gidx << 20);
    const __nv_bfloat16* al_g = ul  + ((size_t)gidx << 20);
    const __nv_bfloat16* bh_g = vwh + ((size_t)gidx << 21);
    const __nv_bfloat16* bl_g = vwl + ((size_t)gidx << 21);
    const uint32_t sbase = smem_to_u32(dsm);
    const int rowb = tid >> 3, seg = tid & 7;

    auto load_chunk = [&](int c, int buf) {
        const int ci0 = c << 6;
        const uint32_t sb = sbase + buf * 65536;
        #pragma unroll
        for (int i = 0; i < 4; i++) {
            int row = rowb + 32 * i;
            uint32_t sw = (uint32_t)(row * 128) + (uint32_t)(((seg ^ (row & 7)) << 4));
            size_t ao = (size_t)(m0 + row) * 1024 + ci0 + seg * 8;
            size_t bo = (size_t)(n0 + row) * 1024 + ci0 + seg * 8;
            CP_ASYNC16(sb + sw,         ah_g + ao);
            CP_ASYNC16(sb + 16384 + sw, al_g + ao);
            CP_ASYNC16(sb + 32768 + sw, bh_g + bo);
            CP_ASYNC16(sb + 49152 + sw, bl_g + bo);
        }
    };

    const int wm = (wid & 1) * 64, wn = (wid >> 1) * 32;
    int rowA[4], xorA[4];
    #pragma unroll
    for (int mt = 0; mt < 4; mt++) { rowA[mt] = wm + mt * 16 + (lane & 15); xorA[mt] = rowA[mt] & 7; }
    const int cgA = lane >> 4;
    int rowB[2], xorB[2];
    #pragma unroll
    for (int np = 0; np < 2; np++) {
        rowB[np] = wn + np * 16 + (lane & 7) + ((lane >> 4) & 1) * 8;
        xorB[np] = rowB[np] & 7;
    }
    const int cgB = (lane >> 3) & 1;

    float acc[4][4][4];
    #pragma unroll
    for (int mt = 0; mt < 4; mt++)
        #pragma unroll
        for (int nt = 0; nt < 4; nt++)
            #pragma unroll
            for (int e = 0; e < 4; e++) acc[mt][nt][e] = 0.f;

    load_chunk(0, 0); CP_COMMIT();
    for (int c = 0; c < 16; ++c) {
        const int buf = c & 1;
        if (c < 15) { load_chunk(c + 1, (c + 1) & 1); CP_COMMIT(); CP_WAIT(1); }
        else        { CP_WAIT(0); }
        __syncthreads();
        const uint32_t sb = sbase + buf * 65536;
        const uint32_t aHi = sb, aLo = sb + 16384, bHi = sb + 32768, bLo = sb + 49152;
        #pragma unroll
        for (int ks = 0; ks < 4; ks++) {
            uint32_t ah[4][4], al[4][4], bh2[2][4], bl2[2][4];
            #pragma unroll
            for (int mt = 0; mt < 4; mt++) {
                uint32_t off = (uint32_t)(rowA[mt] * 128) + (uint32_t)(((ks*2+cgA) ^ xorA[mt]) << 4);
                LDSM4(ah[mt][0], ah[mt][1], ah[mt][2], ah[mt][3], aHi + off);
                LDSM4(al[mt][0], al[mt][1], al[mt][2], al[mt][3], aLo + off);
            }
            #pragma unroll
            for (int np = 0; np < 2; np++) {
                uint32_t off = (uint32_t)(rowB[np] * 128) + (uint32_t)(((ks*2+cgB) ^ xorB[np]) << 4);
                LDSM4(bh2[np][0], bh2[np][1], bh2[np][2], bh2[np][3], bHi + off);
                LDSM4(bl2[np][0], bl2[np][1], bl2[np][2], bl2[np][3], bLo + off);
            }
            #pragma unroll
            for (int mt = 0; mt < 4; mt++)
                #pragma unroll
                for (int nt = 0; nt < 4; nt++) {
                    const int np = nt >> 1, h = (nt & 1) * 2;
                    MMA16816(acc[mt][nt], ah[mt][0],ah[mt][1],ah[mt][2],ah[mt][3], bh2[np][h], bh2[np][h+1]);
                    MMA16816(acc[mt][nt], ah[mt][0],ah[mt][1],ah[mt][2],ah[mt][3], bl2[np][h], bl2[np][h+1]);
                    MMA16816(acc[mt][nt], al[mt][0],al[mt][1],al[mt][2],al[mt][3], bh2[np][h], bh2[np][h+1]);
                }
        }
        __syncthreads();
    }

    float* outp = mw + ((size_t)gidx << 21) * 1024 / 1024;   // g*1024*2048
    outp = mw + (size_t)gidx * 1024 * 2048;
    #pragma unroll
    for (int mt = 0; mt < 4; mt++) {
        const int ma = m0 + wm + mt * 16 + (lane >> 2);
        const int mb2 = ma + 8;
        #pragma unroll
        for (int nt = 0; nt < 4; nt++) {
            const int n = n0 + wn + nt * 8 + 2 * (lane & 3);
            *(float2*)(outp + (size_t)ma  * 2048 + n) = make_float2(acc[mt][nt][0], acc[mt][nt][1]);
            *(float2*)(outp + (size_t)mb2 * 2048 + n) = make_float2(acc[mt][nt][2], acc[mt][nt][3]);
        }
    }
}

// ---------------- Winograd output transform: Y = A^T M A ----------------
__global__ __launch_bounds__(256)
void wino_out_kernel(const float* __restrict__ mw,
                     const float* __restrict__ bq, const float* __restrict__ bk,
                     const float* __restrict__ bv,
                     __nv_bfloat16* __restrict__ qh, __nv_bfloat16* __restrict__ ql,
                     __nv_bfloat16* __restrict__ kh, __nv_bfloat16* __restrict__ kl,
                     __nv_bfloat16* __restrict__ vh, __nv_bfloat16* __restrict__ vl) {
    const int idx = blockIdx.x * 256 + threadIdx.x;   // < 3*1024*2048
    const int conv = idx >> 21;
    const int rem = idx & 0x1FFFFF;
    const int co = rem >> 11;
    const int tile = rem & 2047;

    float M[16];
    #pragma unroll
    for (int k = 0; k < 16; k++)
        M[k] = mw[((size_t)(conv * 16 + k) * 1024 + co) * 2048 + tile];

    float t0[4], t1[4];
    #pragma unroll
    for (int j = 0; j < 4; j++) {
        t0[j] = M[j] + M[4 + j] + M[8 + j];
        t1[j] = M[4 + j] - M[8 + j] - M[12 + j];
    }
    float y00 = t0[0] + t0[1] + t0[2], y01 = t0[1] - t0[2] - t0[3];
    float y10 = t1[0] + t1[1] + t1[2], y11 = t1[1] - t1[2] - t1[3];

    __nv_bfloat16 *oh, *ol;
    const float* bias;
    if (conv == 0)      { oh = qh; ol = ql; bias = bq; }
    else if (conv == 1) { oh = kh; ol = kl; bias = bk; }
    else                { oh = vh; ol = vl; bias = bv; }
    const float scale = (conv == 0) ? 0.125f : 1.0f;
    const float bi = bias[co];

    const int b = tile >> 8, t = tile & 255;
    const int tyy = t >> 4, txx = t & 15;
    size_t base = ((size_t)(b * 1024 + co)) * 1024 + (2 * tyy) * 32 + 2 * txx;
    uint32_t h0, l0, h1, l1;
    pack_hilo((y00 + bi) * scale, (y01 + bi) * scale, h0, l0);
    pack_hilo((y10 + bi) * scale, (y11 + bi) * scale, h1, l1);
    *(uint32_t*)(oh + base)      = h0;
    *(uint32_t*)(ol + base)      = l0;
    *(uint32_t*)(oh + base + 32) = h1;
    *(uint32_t*)(ol + base + 32) = l1;
}

// ---------------- fused flash attention ----------------
#define FA_KVBUF 65536
#define FA_QOFF  (2 * FA_KVBUF)
#define FA_MOFF  (FA_QOFF + 32768)
#define FA_SMEM_BYTES (FA_MOFF + 128 * 33 * 4)

__global__ __launch_bounds__(256, 1)
void flash_kernel(const __nv_bfloat16* __restrict__ qh_g, const __nv_bfloat16* __restrict__ ql_g,
                  const __nv_bfloat16* __restrict__ kh_g, const __nv_bfloat16* __restrict__ kl_g,
                  const __nv_bfloat16* __restrict__ vh_g, const __nv_bfloat16* __restrict__ vl_g,
                  const uint32_t* __restrict__ mbits,
                  __nv_bfloat16* __restrict__ aoh_g, __nv_bfloat16* __restrict__ aol_g) {
    extern __shared__ char dsm[];
    const int tid = threadIdx.x, wid = tid >> 5, lane = tid & 31;
    const int t0 = blockIdx.x * 128, bh = blockIdx.y, b = bh >> 4, h = bh & 15;
    const uint32_t sb = smem_to_u32(dsm);
    uint32_t* msk = (uint32_t*)(dsm + FA_MOFF);
    const int rowb = tid >> 3, seg = tid & 7;
    const size_t rbase = (size_t)b * 1024;
    const int fcol = h * 64, wt0 = wid * 16;

    auto load_kv = [&](int c, int buf) {
        const uint32_t p = sb + buf * FA_KVBUF;
        const int s0 = c * 128;
        #pragma unroll
        for (int i = 0; i < 4; i++) {
            int row = rowb + 32 * i;
            uint32_t sw = (uint32_t)(row * 128) + (uint32_t)(((seg ^ (row & 7)) << 4));
            size_t go = (rbase + s0 + row) * 1024 + fcol + seg * 8;
            CP_ASYNC16(p + sw,         kh_g + go);
            CP_ASYNC16(p + 16384 + sw, kl_g + go);
            CP_ASYNC16(p + 32768 + sw, vh_g + go);
            CP_ASYNC16(p + 49152 + sw, vl_g + go);
        }
    };

    #pragma unroll
    for (int i = 0; i < 4; i++) {
        int row = rowb + 32 * i;
        uint32_t sw = (uint32_t)(row * 128) + (uint32_t)(((seg ^ (row & 7)) << 4));
        size_t go = (rbase + t0 + row) * 1024 + fcol + seg * 8;
        CP_ASYNC16(sb + FA_QOFF + sw,         qh_g + go);
        CP_ASYNC16(sb + FA_QOFF + 16384 + sw, ql_g + go);
    }
    #pragma unroll
    for (int j = 0; j < 16; j++) {
        int idx = tid + 256 * j;
        int r = idx >> 5, w = idx & 31;
        msk[r * 33 + w] = mbits[((size_t)b * 1024 + t0 + r) * 32 + w];
    }
    load_kv(0, 0); CP_COMMIT();

    float m0 = -INFINITY, m1 = -INFINITY, l0 = 0.f, l1 = 0.f;
    float o[8][4];
    #pragma unroll
    for (int j = 0; j < 8; j++)
        #pragma unroll
        for (int e = 0; e < 4; e++) o[j][e] = 0.f;
    uint32_t qfh[4][4], qfl[4][4];
    const int lr0 = wt0 + (lane >> 2);

    #pragma unroll 1
    for (int c = 0; c < 8; c++) {
        if (c < 7) { load_kv(c + 1, (c + 1) & 1); CP_COMMIT(); CP_WAIT(1); }
        else       { CP_WAIT(0); }
        __syncthreads();
        if (c == 0) {
            const int rA = wt0 + (lane & 15), cg = lane >> 4;
            #pragma unroll
            for (int ks = 0; ks < 4; ks++) {
                uint32_t off = (uint32_t)(rA * 128) + (uint32_t)((((ks*2+cg)) ^ (rA & 7)) << 4);
                LDSM4(qfh[ks][0], qfh[ks][1], qfh[ks][2], qfh[ks][3], sb + FA_QOFF + off);
                LDSM4(qfl[ks][0], qfl[ks][1], qfl[ks][2], qfl[ks][3], sb + FA_QOFF + 16384 + off);
            }
        }
        const uint32_t kv = sb + (c & 1) * FA_KVBUF;

        float s[16][4];
        #pragma unroll
        for (int i = 0; i < 16; i++)
            #pragma unroll
            for (int e = 0; e < 4; e++) s[i][e] = 0.f;
        #pragma unroll
        for (int np = 0; np < 8; np++) {
            const int rB = np * 16 + (lane & 7) + ((lane >> 4) & 1) * 8;
            const int cg = (lane >> 3) & 1;
            #pragma unroll
            for (int ks = 0; ks < 4; ks++) {
                uint32_t off = (uint32_t)(rB * 128) + (uint32_t)((((ks*2+cg)) ^ (rB & 7)) << 4);
                uint32_t k4[4], kl4[4];
                LDSM4(k4[0], k4[1], k4[2], k4[3], kv + off);
                LDSM4(kl4[0], kl4[1], kl4[2], kl4[3], kv + 16384 + off);
                MMA16816(s[2*np],   qfh[ks][0],qfh[ks][1],qfh[ks][2],qfh[ks][3], k4[0], k4[1]);
                MMA16816(s[2*np],   qfh[ks][0],qfh[ks][1],qfh[ks][2],qfh[ks][3], kl4[0], kl4[1]);
                MMA16816(s[2*np],   qfl[ks][0],qfl[ks][1],qfl[ks][2],qfl[ks][3], k4[0], k4[1]);
                MMA16816(s[2*np+1], qfh[ks][0],qfh[ks][1],qfh[ks][2],qfh[ks][3], k4[2], k4[3]);
                MMA16816(s[2*np+1], qfh[ks][0],qfh[ks][1],qfh[ks][2],qfh[ks][3], kl4[2], kl4[3]);
                MMA16816(s[2*np+1], qfl[ks][0],qfl[ks][1],qfl[ks][2],qfl[ks][3], k4[2], k4[3]);
            }
        }

        float cm0 = -3.4e38f, cm1 = -3.4e38f;
        #pragma unroll
        for (int nt = 0; nt < 16; nt++) {
            const int bp = (8 * nt + 2 * (lane & 3)) & 31;
            const uint32_t wa = msk[lr0 * 33 + c * 4 + (nt >> 2)];
            const uint32_t wb = msk[(lr0 + 8) * 33 + c * 4 + (nt >> 2)];
            if (!((wa >> bp) & 1))       s[nt][0] = -1e9f;
            if (!((wa >> (bp + 1)) & 1)) s[nt][1] = -1e9f;
            if (!((wb >> bp) & 1))       s[nt][2] = -1e9f;
            if (!((wb >> (bp + 1)) & 1)) s[nt][3] = -1e9f;
            cm0 = fmaxf(cm0, fmaxf(s[nt][0], s[nt][1]));
            cm1 = fmaxf(cm1, fmaxf(s[nt][2], s[nt][3]));
        }
        cm0 = fmaxf(cm0, __shfl_xor_sync(0xffffffffu, cm0, 1));
        cm0 = fmaxf(cm0, __shfl_xor_sync(0xffffffffu, cm0, 2));
        cm1 = fmaxf(cm1, __shfl_xor_sync(0xffffffffu, cm1, 1));
        cm1 = fmaxf(cm1, __shfl_xor_sync(0xffffffffu, cm1, 2));
        float mn0 = fmaxf(m0, cm0), mn1 = fmaxf(m1, cm1);
        float sc0 = __expf(m0 - mn0), sc1 = __expf(m1 - mn1);
        m0 = mn0; m1 = mn1;
        float rs0 = 0.f, rs1 = 0.f;
        #pragma unroll
        for (int nt = 0; nt < 16; nt++) {
            s[nt][0] = __expf(s[nt][0] - mn0); s[nt][1] = __expf(s[nt][1] - mn0);
            s[nt][2] = __expf(s[nt][2] - mn1); s[nt][3] = __expf(s[nt][3] - mn1);
            rs0 += s[nt][0] + s[nt][1];
            rs1 += s[nt][2] + s[nt][3];
        }
        l0 = l0 * sc0 + rs0; l1 = l1 * sc1 + rs1;
        #pragma unroll
        for (int j = 0; j < 8; j++) {
            o[j][0] *= sc0; o[j][1] *= sc0; o[j][2] *= sc1; o[j][3] *= sc1;
        }

        #pragma unroll
        for (int ks = 0; ks < 8; ks++) {
            uint32_t ph[4], pl[4];
            pack_hilo(s[2*ks][0],   s[2*ks][1],   ph[0], pl[0]);
            pack_hilo(s[2*ks][2],   s[2*ks][3],   ph[1], pl[1]);
            pack_hilo(s[2*ks+1][0], s[2*ks+1][1], ph[2], pl[2]);
            pack_hilo(s[2*ks+1][2], s[2*ks+1][3], ph[3], pl[3]);
            const int vrow = ks * 16 + (lane & 7) + 8 * ((lane >> 3) & 1);
            #pragma unroll
            for (int ds = 0; ds < 4; ds++) {
                uint32_t off = (uint32_t)(vrow * 128) +
                               (uint32_t)((((ds*2 + (lane >> 4))) ^ (vrow & 7)) << 4);
                uint32_t v4[4], vl4[4];
                LDSM4T(v4[0], v4[1], v4[2], v4[3], kv + 32768 + off);
                LDSM4T(vl4[0], vl4[1], vl4[2], vl4[3], kv + 49152 + off);
                MMA16816(o[2*ds],   ph[0],ph[1],ph[2],ph[3], v4[0], v4[1]);
                MMA16816(o[2*ds],   ph[0],ph[1],ph[2],ph[3], vl4[0], vl4[1]);
                MMA16816(o[2*ds],   pl[0],pl[1],pl[2],pl[3], v4[0], v4[1]);
                MMA16816(o[2*ds+1], ph[0],ph[1],ph[2],ph[3], v4[2], v4[3]);
                MMA16816(o[2*ds+1], ph[0],ph[1],ph[2],ph[3], vl4[2], vl4[3]);
                MMA16816(o[2*ds+1], pl[0],pl[1],pl[2],pl[3], v4[2], v4[3]);
            }
        }
        __syncthreads();
    }

    l0 += __shfl_xor_sync(0xffffffffu, l0, 1);
    l0 += __shfl_xor_sync(0xffffffffu, l0, 2);
    l1 += __shfl_xor_sync(0xffffffffu, l1, 1);
    l1 += __shfl_xor_sync(0xffffffffu, l1, 2);
    const float i0 = 1.f / l0, i1 = 1.f / l1;
    size_t ra = (rbase + t0 + lr0) * 1024 + fcol + 2 * (lane & 3);
    size_t rb2 = ra + 8 * 1024;
    #pragma unroll
    for (int j = 0; j < 8; j++) {
        uint32_t h0, lo0, h1, lo1;
        pack_hilo(o[j][0] * i0, o[j][1] * i0, h0, lo0);
        pack_hilo(o[j][2] * i1, o[j][3] * i1, h1, lo1);
        *(uint32_t*)(aoh_g + ra + 8*j)  = h0;
        *(uint32_t*)(aol_g + ra + 8*j)  = lo0;
        *(uint32_t*)(aoh_g + rb2 + 8*j) = h1;
        *(uint32_t*)(aol_g + rb2 + 8*j) = lo1;
    }
}

// ---------------- projection GEMM ----------------
__global__ __launch_bounds__(256, 1)
void proj_mma_kernel(const __nv_bfloat16* __restrict__ ah_g, const __nv_bfloat16* __restrict__ al_g,
                     const __nv_bfloat16* __restrict__ wh_g, const __nv_bfloat16* __restrict__ wl_g,
                     const float* __restrict__ bo, float* __restrict__ out) {
    extern __shared__ char dsm[];
    const int tid = threadIdx.x, wid = tid >> 5, lane = tid & 31;
    const int m0 = blockIdx.x * 128, n0 = blockIdx.y * 128;
    const uint32_t sbase = smem_to_u32(dsm);
    const int rowb = tid >> 3, seg = tid & 7;

    auto load_chunk = [&](int c, int buf) {
        const int ci0 = c << 6;
        const uint32_t sb = sbase + buf * 65536;
        #pragma unroll
        for (int i = 0; i < 4; i++) {
            int row = rowb + 32 * i;
            uint32_t sw = (uint32_t)(row * 128) + (uint32_t)(((seg ^ (row & 7)) << 4));
            size_t ao = (size_t)(m0 + row) * 1024 + ci0 + seg * 8;
            size_t wo = (size_t)(n0 + row) * 1024 + ci0 + seg * 8;
            CP_ASYNC16(sb + sw,         ah_g + ao);
            CP_ASYNC16(sb + 16384 + sw, al_g + ao);
            CP_ASYNC16(sb + 32768 + sw, wh_g + wo);
            CP_ASYNC16(sb + 49152 + sw, wl_g + wo);
        }
    };

    const int wm = (wid & 1) * 64, wn = (wid >> 1) * 32;
    int rowA[4], xorA[4];
    #pragma unroll
    for (int mt = 0; mt < 4; mt++) { rowA[mt] = wm + mt * 16 + (lane & 15); xorA[mt] = rowA[mt] & 7; }
    const int cgA = lane >> 4;
    int rowB[2], xorB[2];
    #pragma unroll
    for (int np = 0; np < 2; np++) {
        rowB[np] = wn + np * 16 + (lane & 7) + ((lane >> 4) & 1) * 8;
        xorB[np] = rowB[np] & 7;
    }
    const int cgB = (lane >> 3) & 1;

    float acc[4][4][4];
    #pragma unroll
    for (int mt = 0; mt < 4; mt++)
        #pragma unroll
        for (int nt = 0; nt < 4; nt++)
            #pragma unroll
            for (int e = 0; e < 4; e++) acc[mt][nt][e] = 0.f;

    load_chunk(0, 0); CP_COMMIT();
    for (int c = 0; c < 16; ++c) {
        const int buf = c & 1;
        if (c < 15) { load_chunk(c + 1, (c + 1) & 1); CP_COMMIT(); CP_WAIT(1); }
        else        { CP_WAIT(0); }
        __syncthreads();
        const uint32_t sb = sbase + buf * 65536;
        const uint32_t aHi = sb, aLo = sb + 16384, bHi = sb + 32768, bLo = sb + 49152;
        #pragma unroll
        for (int ks = 0; ks < 4; ks++) {
            uint32_t ah[4][4], al[4][4], bh2[2][4], bl2[2][4];
            #pragma unroll
            for (int mt = 0; mt < 4; mt++) {
                uint32_t off = (uint32_t)(rowA[mt] * 128) + (uint32_t)(((ks*2+cgA) ^ xorA[mt]) << 4);
                LDSM4(ah[mt][0], ah[mt][1], ah[mt][2], ah[mt][3], aHi + off);
                LDSM4(al[mt][0], al[mt][1], al[mt][2], al[mt][3], aLo + off);
            }
            #pragma unroll
            for (int np = 0; np < 2; np++) {
                uint32_t off = (uint32_t)(rowB[np] * 128) + (uint32_t)(((ks*2+cgB) ^ xorB[np]) << 4);
                LDSM4(bh2[np][0], bh2[np][1], bh2[np][2], bh2[np][3], bHi + off);
                LDSM4(bl2[np][0], bl2[np][1], bl2[np][2], bl2[np][3], bLo + off);
            }
            #pragma unroll
            for (int mt = 0; mt < 4; mt++)
                #pragma unroll
                for (int nt = 0; nt < 4; nt++) {
                    const int np = nt >> 1, h = (nt & 1) * 2;
                    MMA16816(acc[mt][nt], ah[mt][0],ah[mt][1],ah[mt][2],ah[mt][3], bh2[np][h], bh2[np][h+1]);
                    MMA16816(acc[mt][nt], ah[mt][0],ah[mt][1],ah[mt][2],ah[mt][3], bl2[np][h], bl2[np][h+1]);
                    MMA16816(acc[mt][nt], al[mt][0],al[mt][1],al[mt][2],al[mt][3], bh2[np][h], bh2[np][h+1]);
                }
        }
        __syncthreads();
    }

    #pragma unroll
    for (int mt = 0; mt < 4; mt++) {
        const int ma = m0 + wm + mt * 16 + (lane >> 2);
        const int mb2 = ma + 8;
        #pragma unroll
        for (int nt = 0; nt < 4; nt++) {
            const int n = n0 + wn + nt * 8 + 2 * (lane & 3);
            const float b0 = bo[n], b1 = bo[n + 1];
            *(float2*)(out + (size_t)ma * 1024 + n)  = make_float2(acc[mt][nt][0] + b0, acc[mt][nt][1] + b1);
            *(float2*)(out + (size_t)mb2 * 1024 + n) = make_float2(acc[mt][nt][2] + b0, acc[mt][nt][3] + b1);
        }
    }
}

// ---------------- kernel_launch ----------------
extern "C" void kernel_launch(void* const* d_in, const int* in_sizes, int n_in,
                              void* d_out, int out_size)
{
    (void)in_sizes; (void)n_in; (void)out_size;
    const float* q   = (const float*)d_in[0];
    const float* k   = (const float*)d_in[1];
    const float* v   = (const float*)d_in[2];
    const float* Wq  = (const float*)d_in[3];
    const float* bq  = (const float*)d_in[4];
    const float* Wk  = (const float*)d_in[5];
    const float* bk  = (const float*)d_in[6];
    const float* Wv  = (const float*)d_in[7];
    const float* bv  = (const float*)d_in[8];
    const float* Wo  = (const float*)d_in[9];
    const float* bo  = (const float*)d_in[10];
    const int*  mask = (const int*) d_in[11];
    float* out = (float*)d_out;

    __nv_bfloat16 *uwh, *uwl, *vwh, *vwl, *qh, *ql, *kh, *kl, *vh, *vl, *aoh, *aol, *woh, *wol;
    float* mw;
    uint32_t* mb;
    cudaGetSymbolAddress((void**)&uwh, g_uwh);   cudaGetSymbolAddress((void**)&uwl, g_uwl);
    cudaGetSymbolAddress((void**)&vwh, g_vwh);   cudaGetSymbolAddress((void**)&vwl, g_vwl);
    cudaGetSymbolAddress((void**)&mw, g_mw);
    cudaGetSymbolAddress((void**)&qh, g_qh);     cudaGetSymbolAddress((void**)&ql, g_ql);
    cudaGetSymbolAddress((void**)&kh, g_kh);     cudaGetSymbolAddress((void**)&kl, g_kl);
    cudaGetSymbolAddress((void**)&vh, g_vh);     cudaGetSymbolAddress((void**)&vl, g_vl);
    cudaGetSymbolAddress((void**)&aoh, g_aoh);   cudaGetSymbolAddress((void**)&aol, g_aol);
    cudaGetSymbolAddress((void**)&woh, g_woh);   cudaGetSymbolAddress((void**)&wol, g_wol);
    cudaGetSymbolAddress((void**)&mb, g_mb);

    cudaFuncSetAttribute(wino_gemm_kernel, cudaFuncAttributeMaxDynamicSharedMemorySize, GEMM_SMEM_BYTES);
    cudaFuncSetAttribute(flash_kernel,     cudaFuncAttributeMaxDynamicSharedMemorySize, FA_SMEM_BYTES);
    cudaFuncSetAttribute(proj_mma_kernel,  cudaFuncAttributeMaxDynamicSharedMemorySize, GEMM_SMEM_BYTES);

    wino_w_kernel<<<12288, 256>>>(Wq, Wk, Wv, uwh, uwl);
    wino_x_kernel<<<dim3(16, 16, 24), 256>>>(q, k, v, vwh, vwl);
    pack_wo_kernel<<<4096, 256>>>(Wo, woh, wol);
    pack_mask_kernel<<<32768, 256>>>(mask, mb);

    wino_gemm_kernel<<<dim3(8, 16, 48), 256, GEMM_SMEM_BYTES>>>(uwh, uwl, vwh, vwl, mw);
    wino_out_kernel<<<24576, 256>>>(mw, bq, bk, bv, qh, ql, kh, kl, vh, vl);

    flash_kernel<<<dim3(8, 128), 256, FA_SMEM_BYTES>>>(
        qh, ql, kh, kl, vh, vl, mb, aoh, aol);

    proj_mma_kernel<<<dim3(64, 8), 256, GEMM_SMEM_BYTES>>>(aoh, aol, woh, wol, bo, out);
}

// round 8
// speedup vs baseline: 12.1066x; 1.4195x over previous
#include <cuda_runtime.h>
#include <cuda_bf16.h>
#include <cstdint>
#include <math.h>

__device__ __forceinline__ uint32_t smem_to_u32(const void* p) {
    uint32_t a;
    asm("{ .reg .u64 t; cvta.to.shared.u64 t, %1; cvt.u32.u64 %0, t; }" : "=r"(a) : "l"(p));
    return a;
}
#define CP_ASYNC16(d, s) asm volatile("cp.async.cg.shared.global [%0], [%1], 16;" :: "r"(d), "l"(s))
#define CP_COMMIT() asm volatile("cp.async.commit_group;")
#define CP_WAIT(N)  asm volatile("cp.async.wait_group %0;" :: "n"(N))
#define LDSM4(R0,R1,R2,R3,A) \
    asm volatile("ldmatrix.sync.aligned.m8n8.x4.shared.b16 {%0,%1,%2,%3}, [%4];" \
        : "=r"(R0),"=r"(R1),"=r"(R2),"=r"(R3) : "r"(A))
#define LDSM4T(R0,R1,R2,R3,A) \
    asm volatile("ldmatrix.sync.aligned.m8n8.x4.trans.shared.b16 {%0,%1,%2,%3}, [%4];" \
        : "=r"(R0),"=r"(R1),"=r"(R2),"=r"(R3) : "r"(A))
#define MMA16816(D,A0,A1,A2,A3,B0,B1) \
    asm volatile("mma.sync.aligned.m16n8k16.row.col.f32.bf16.bf16.f32 " \
        "{%0,%1,%2,%3}, {%4,%5,%6,%7}, {%8,%9}, {%0,%1,%2,%3};" \
        : "+f"((D)[0]),"+f"((D)[1]),"+f"((D)[2]),"+f"((D)[3]) \
        : "r"(A0),"r"(A1),"r"(A2),"r"(A3),"r"(B0),"r"(B1))

__device__ __forceinline__ void pack_hilo(float v0, float v1, uint32_t& hi, uint32_t& lo) {
    uint32_t h;
    asm("cvt.rn.bf16x2.f32 %0, %1, %2;" : "=r"(h) : "f"(v1), "f"(v0));
    float l0 = v0 - __uint_as_float(h << 16);
    float l1 = v1 - __uint_as_float(h & 0xffff0000u);
    asm("cvt.rn.bf16x2.f32 %0, %1, %2;" : "=r"(lo) : "f"(l1), "f"(l0));
    hi = h;
}

// ---------------- scratch ----------------
// F(4x4,3x3): 36 g-planes per conv, 512 tiles (8 img * 64), K=1024
#define QKV_ELEMS (8u * 1024u * 1024u)
#define UW_ELEMS  (108ull * 1024u * 1024u)
#define VW_ELEMS  (108ull * 512u * 1024u)
__device__ __align__(128) __nv_bfloat16 g_uwh[UW_ELEMS], g_uwl[UW_ELEMS];   // U[g][co][ci]
__device__ __align__(128) __nv_bfloat16 g_vwh[VW_ELEMS], g_vwl[VW_ELEMS];   // V[g][tile][ci]
__device__ __align__(128) float g_mw[108ull * 1024u * 512u];                // M[g][co][tile]
__device__ __align__(128) __nv_bfloat16 g_qh[QKV_ELEMS], g_ql[QKV_ELEMS];
__device__ __align__(128) __nv_bfloat16 g_kh[QKV_ELEMS], g_kl[QKV_ELEMS];
__device__ __align__(128) __nv_bfloat16 g_vh[QKV_ELEMS], g_vl[QKV_ELEMS];
__device__ __align__(128) __nv_bfloat16 g_aoh[QKV_ELEMS], g_aol[QKV_ELEMS];
__device__ __align__(128) __nv_bfloat16 g_woh[1024u*1024u], g_wol[1024u*1024u];
__device__ __align__(128) uint32_t g_mb[8u * 1024u * 32u];

// ---------------- prep ----------------
__global__ void pack_wo_kernel(const float* __restrict__ Wo,
                               __nv_bfloat16* __restrict__ wh, __nv_bfloat16* __restrict__ wl) {
    int i = blockIdx.x * 256 + threadIdx.x;
    float w = Wo[i];
    __nv_bfloat16 h = __float2bfloat16(w);
    wh[i] = h;
    wl[i] = __float2bfloat16(w - __bfloat162float(h));
}

__global__ void pack_mask_kernel(const int* __restrict__ mask, uint32_t* __restrict__ mb) {
    int idx = blockIdx.x * 256 + threadIdx.x;
    uint32_t word = __ballot_sync(0xffffffffu, mask[idx] != 0);
    if ((threadIdx.x & 31) == 0) mb[idx >> 5] = word;
}

// ---------------- Winograd F(4,3) weight transform: U = G g G^T ----------------
__device__ __forceinline__ void gtrans(float a, float b, float d, float* y) {
    const float s6 = 1.f / 6.f, s12 = 1.f / 12.f, s24 = 1.f / 24.f;
    y[0] = 0.25f * a;
    y[1] = -(a + b + d) * s6;
    y[2] = (-a + b - d) * s6;
    y[3] = a * s24 + b * s12 + d * s6;
    y[4] = a * s24 - b * s12 + d * s6;
    y[5] = d;
}

__global__ __launch_bounds__(256)
void wino_w_kernel(const float* __restrict__ Wq, const float* __restrict__ Wk,
                   const float* __restrict__ Wv,
                   __nv_bfloat16* __restrict__ uh, __nv_bfloat16* __restrict__ ul) {
    int i = blockIdx.x * 256 + threadIdx.x;        // < 3*2^20
    int conv = i >> 20;
    int co = (i >> 10) & 1023, ci = i & 1023;
    const float* W = conv == 0 ? Wq : (conv == 1 ? Wk : Wv);
    const float* g = W + ((size_t)co * 1024 + ci) * 9;
    float t[6][3];
    #pragma unroll
    for (int c = 0; c < 3; c++) {
        float col[6];
        gtrans(g[c], g[3 + c], g[6 + c], col);
        #pragma unroll
        for (int u = 0; u < 6; u++) t[u][c] = col[u];
    }
    #pragma unroll
    for (int u = 0; u < 6; u++) {
        float U[6];
        gtrans(t[u][0], t[u][1], t[u][2], U);
        #pragma unroll
        for (int v = 0; v < 6; v++) {
            int kk = u * 6 + v;
            size_t o = (((size_t)(conv * 36 + kk)) << 20) + ((size_t)co << 10) + ci;
            __nv_bfloat16 h = __float2bfloat16(U[v]);
            uh[o] = h;
            ul[o] = __float2bfloat16(U[v] - __bfloat162float(h));
        }
    }
}

// ---------------- Winograd input transform: V = B^T d B ----------------
__device__ __forceinline__ void btrans(const float* x, float* y) {
    y[0] = 4.f * x[0] - 5.f * x[2] + x[4];
    y[1] = -4.f * x[1] - 4.f * x[2] + x[3] + x[4];
    y[2] = 4.f * x[1] - 4.f * x[2] - x[3] + x[4];
    y[3] = -2.f * x[1] - x[2] + 2.f * x[3] + x[4];
    y[4] = 2.f * x[1] - x[2] - 2.f * x[3] + x[4];
    y[5] = 4.f * x[1] - 5.f * x[3] + x[5];
}

// grid (8 ty, 32 ci-chunk(32), 24 = conv*8+b), 256 threads.
__global__ __launch_bounds__(256)
void wino_x_kernel(const float* __restrict__ q, const float* __restrict__ k,
                   const float* __restrict__ v,
                   __nv_bfloat16* __restrict__ vwh, __nv_bfloat16* __restrict__ vwl) {
    __shared__ float xs[6][32][34];   // [u][ci][col; col 0 == image col -1]
    const int conv = blockIdx.z >> 3, b = blockIdx.z & 7;
    const float* x = conv == 0 ? q : (conv == 1 ? k : v);
    const int ty = blockIdx.x;
    const int ci0 = blockIdx.y * 32;
    const int tid = threadIdx.x;

    for (int l = tid; l < 6 * 32 * 34; l += 256) {
        int u = l / 1088;
        int rem = l - u * 1088;
        int ci = rem / 34, cc = rem - ci * 34;
        int gr = 4 * ty - 1 + u, gc = cc - 1;
        float val = 0.f;
        if ((unsigned)gr < 32u && (unsigned)gc < 32u)
            val = x[((size_t)(b * 1024 + ci0 + ci)) * 1024 + gr * 32 + gc];
        xs[u][ci][cc] = val;
    }
    __syncthreads();

    const int tx = tid >> 5, ci = tid & 31;
    float d[6][6];
    #pragma unroll
    for (int u = 0; u < 6; u++)
        #pragma unroll
        for (int vv = 0; vv < 6; vv++) d[u][vv] = xs[u][ci][4 * tx + vv];
    float t1[6][6];
    #pragma unroll
    for (int vv = 0; vv < 6; vv++) {
        float col[6] = {d[0][vv], d[1][vv], d[2][vv], d[3][vv], d[4][vv], d[5][vv]};
        float y[6];
        btrans(col, y);
        #pragma unroll
        for (int u = 0; u < 6; u++) t1[u][vv] = y[u];
    }
    const size_t tile = (size_t)b * 64 + ty * 8 + tx;
    #pragma unroll
    for (int u = 0; u < 6; u++) {
        float y[6];
        btrans(t1[u], y);
        #pragma unroll
        for (int vv = 0; vv < 6; vv++) {
            int kk = u * 6 + vv;
            size_t o = ((size_t)(conv * 36 + kk) * 512 + tile) * 1024 + ci0 + ci;
            __nv_bfloat16 h = __float2bfloat16(y[vv]);
            vwh[o] = h;
            vwl[o] = __float2bfloat16(y[vv] - __bfloat162float(h));
        }
    }
}

// ---------------- Winograd batched GEMM: M[g] = U[g] * V[g]^T ----------------
#define GEMM_SMEM_BYTES (2 * 4 * 16384)

__global__ __launch_bounds__(256, 1)
void wino_gemm_kernel(const __nv_bfloat16* __restrict__ uh, const __nv_bfloat16* __restrict__ ul,
                      const __nv_bfloat16* __restrict__ vwh, const __nv_bfloat16* __restrict__ vwl,
                      float* __restrict__ mw) {
    extern __shared__ char dsm[];
    const int tid = threadIdx.x, wid = tid >> 5, lane = tid & 31;
    const int m0 = blockIdx.x * 128, n0 = blockIdx.y * 128, gidx = blockIdx.z;
    const __nv_bfloat16* ah_g = uh  + ((size_t)gidx << 20);
    const __nv_bfloat16* al_g = ul  + ((size_t)gidx << 20);
    const __nv_bfloat16* bh_g = vwh + ((size_t)gidx << 19);
    const __nv_bfloat16* bl_g = vwl + ((size_t)gidx << 19);
    const uint32_t sbase = smem_to_u32(dsm);
    const int rowb = tid >> 3, seg = tid & 7;

    auto load_chunk = [&](int c, int buf) {
        const int ci0 = c << 6;
        const uint32_t sb = sbase + buf * 65536;
        #pragma unroll
        for (int i = 0; i < 4; i++) {
            int row = rowb + 32 * i;
            uint32_t sw = (uint32_t)(row * 128) + (uint32_t)(((seg ^ (row & 7)) << 4));
            size_t ao = (size_t)(m0 + row) * 1024 + ci0 + seg * 8;
            size_t bo = (size_t)(n0 + row) * 1024 + ci0 + seg * 8;
            CP_ASYNC16(sb + sw,         ah_g + ao);
            CP_ASYNC16(sb + 16384 + sw, al_g + ao);
            CP_ASYNC16(sb + 32768 + sw, bh_g + bo);
            CP_ASYNC16(sb + 49152 + sw, bl_g + bo);
        }
    };

    const int wm = (wid & 1) * 64, wn = (wid >> 1) * 32;
    int rowA[4], xorA[4];
    #pragma unroll
    for (int mt = 0; mt < 4; mt++) { rowA[mt] = wm + mt * 16 + (lane & 15); xorA[mt] = rowA[mt] & 7; }
    const int cgA = lane >> 4;
    int rowB[2], xorB[2];
    #pragma unroll
    for (int np = 0; np < 2; np++) {
        rowB[np] = wn + np * 16 + (lane & 7) + ((lane >> 4) & 1) * 8;
        xorB[np] = rowB[np] & 7;
    }
    const int cgB = (lane >> 3) & 1;

    float acc[4][4][4];
    #pragma unroll
    for (int mt = 0; mt < 4; mt++)
        #pragma unroll
        for (int nt = 0; nt < 4; nt++)
            #pragma unroll
            for (int e = 0; e < 4; e++) acc[mt][nt][e] = 0.f;

    load_chunk(0, 0); CP_COMMIT();
    for (int c = 0; c < 16; ++c) {
        const int buf = c & 1;
        if (c < 15) { load_chunk(c + 1, (c + 1) & 1); CP_COMMIT(); CP_WAIT(1); }
        else        { CP_WAIT(0); }
        __syncthreads();
        const uint32_t sb = sbase + buf * 65536;
        const uint32_t aHi = sb, aLo = sb + 16384, bHi = sb + 32768, bLo = sb + 49152;
        #pragma unroll
        for (int ks = 0; ks < 4; ks++) {
            uint32_t ah[4][4], al[4][4], bh2[2][4], bl2[2][4];
            #pragma unroll
            for (int mt = 0; mt < 4; mt++) {
                uint32_t off = (uint32_t)(rowA[mt] * 128) + (uint32_t)(((ks*2+cgA) ^ xorA[mt]) << 4);
                LDSM4(ah[mt][0], ah[mt][1], ah[mt][2], ah[mt][3], aHi + off);
                LDSM4(al[mt][0], al[mt][1], al[mt][2], al[mt][3], aLo + off);
            }
            #pragma unroll
            for (int np = 0; np < 2; np++) {
                uint32_t off = (uint32_t)(rowB[np] * 128) + (uint32_t)(((ks*2+cgB) ^ xorB[np]) << 4);
                LDSM4(bh2[np][0], bh2[np][1], bh2[np][2], bh2[np][3], bHi + off);
                LDSM4(bl2[np][0], bl2[np][1], bl2[np][2], bl2[np][3], bLo + off);
            }
            #pragma unroll
            for (int mt = 0; mt < 4; mt++)
                #pragma unroll
                for (int nt = 0; nt < 4; nt++) {
                    const int np = nt >> 1, h = (nt & 1) * 2;
                    MMA16816(acc[mt][nt], ah[mt][0],ah[mt][1],ah[mt][2],ah[mt][3], bh2[np][h], bh2[np][h+1]);
                    MMA16816(acc[mt][nt], ah[mt][0],ah[mt][1],ah[mt][2],ah[mt][3], bl2[np][h], bl2[np][h+1]);
                    MMA16816(acc[mt][nt], al[mt][0],al[mt][1],al[mt][2],al[mt][3], bh2[np][h], bh2[np][h+1]);
                }
        }
        __syncthreads();
    }

    float* outp = mw + (size_t)gidx * 1024 * 512;
    #pragma unroll
    for (int mt = 0; mt < 4; mt++) {
        const int ma = m0 + wm + mt * 16 + (lane >> 2);
        const int mb2 = ma + 8;
        #pragma unroll
        for (int nt = 0; nt < 4; nt++) {
            const int n = n0 + wn + nt * 8 + 2 * (lane & 3);
            *(float2*)(outp + (size_t)ma  * 512 + n) = make_float2(acc[mt][nt][0], acc[mt][nt][1]);
            *(float2*)(outp + (size_t)mb2 * 512 + n) = make_float2(acc[mt][nt][2], acc[mt][nt][3]);
        }
    }
}

// ---------------- Winograd output transform: Y = A^T M A ----------------
__device__ __forceinline__ void atrans(const float* x, float* y) {
    y[0] = x[0] + x[1] + x[2] + x[3] + x[4];
    y[1] = x[1] - x[2] + 2.f * x[3] - 2.f * x[4];
    y[2] = x[1] + x[2] + 4.f * x[3] + 4.f * x[4];
    y[3] = x[1] - x[2] + 8.f * x[3] - 8.f * x[4] + x[5];
}

__global__ __launch_bounds__(256)
void wino_out_kernel(const float* __restrict__ mw,
                     const float* __restrict__ bq, const float* __restrict__ bk,
                     const float* __restrict__ bv,
                     __nv_bfloat16* __restrict__ qh, __nv_bfloat16* __restrict__ ql,
                     __nv_bfloat16* __restrict__ kh, __nv_bfloat16* __restrict__ kl,
                     __nv_bfloat16* __restrict__ vh, __nv_bfloat16* __restrict__ vl) {
    const int idx = blockIdx.x * 256 + threadIdx.x;   // < 3*1024*512
    const int conv = idx >> 19;
    const int rem = idx & 0x7FFFF;
    const int co = rem >> 9;
    const int tile = rem & 511;

    float M[36];
    #pragma unroll
    for (int kk = 0; kk < 36; kk++)
        M[kk] = mw[(size_t)(conv * 36 + kk) * 524288 + (size_t)co * 512 + tile];

    float t[4][6];
    #pragma unroll
    for (int vv = 0; vv < 6; vv++) {
        float col[6] = {M[vv], M[6 + vv], M[12 + vv], M[18 + vv], M[24 + vv], M[30 + vv]};
        float y[4];
        atrans(col, y);
        #pragma unroll
        for (int r = 0; r < 4; r++) t[r][vv] = y[r];
    }

    __nv_bfloat16 *oh, *ol;
    const float* bias;
    if (conv == 0)      { oh = qh; ol = ql; bias = bq; }
    else if (conv == 1) { oh = kh; ol = kl; bias = bk; }
    else                { oh = vh; ol = vl; bias = bv; }
    const float scale = (conv == 0) ? 0.125f : 1.0f;
    const float bi = bias[co];

    const int b = tile >> 6, tt = tile & 63;
    const int tyy = tt >> 3, txx = tt & 7;
    size_t base = ((size_t)(b * 1024 + co)) * 1024 + (4 * tyy) * 32 + 4 * txx;
    #pragma unroll
    for (int r = 0; r < 4; r++) {
        float y[4];
        atrans(t[r], y);
        uint32_t h0, l0, h1, l1;
        pack_hilo((y[0] + bi) * scale, (y[1] + bi) * scale, h0, l0);
        pack_hilo((y[2] + bi) * scale, (y[3] + bi) * scale, h1, l1);
        size_t o = base + (size_t)r * 32;
        *(uint32_t*)(oh + o)     = h0;
        *(uint32_t*)(oh + o + 2) = h1;
        *(uint32_t*)(ol + o)     = l0;
        *(uint32_t*)(ol + o + 2) = l1;
    }
}

// ---------------- fused flash attention ----------------
#define FA_KVBUF 65536
#define FA_QOFF  (2 * FA_KVBUF)
#define FA_MOFF  (FA_QOFF + 32768)
#define FA_SMEM_BYTES (FA_MOFF + 128 * 33 * 4)

__global__ __launch_bounds__(256, 1)
void flash_kernel(const __nv_bfloat16* __restrict__ qh_g, const __nv_bfloat16* __restrict__ ql_g,
                  const __nv_bfloat16* __restrict__ kh_g, const __nv_bfloat16* __restrict__ kl_g,
                  const __nv_bfloat16* __restrict__ vh_g, const __nv_bfloat16* __restrict__ vl_g,
                  const uint32_t* __restrict__ mbits,
                  __nv_bfloat16* __restrict__ aoh_g, __nv_bfloat16* __restrict__ aol_g) {
    extern __shared__ char dsm[];
    const int tid = threadIdx.x, wid = tid >> 5, lane = tid & 31;
    const int t0 = blockIdx.x * 128, bh = blockIdx.y, b = bh >> 4, h = bh & 15;
    const uint32_t sb = smem_to_u32(dsm);
    uint32_t* msk = (uint32_t*)(dsm + FA_MOFF);
    const int rowb = tid >> 3, seg = tid & 7;
    const size_t rbase = (size_t)b * 1024;
    const int fcol = h * 64, wt0 = wid * 16;

    auto load_kv = [&](int c, int buf) {
        const uint32_t p = sb + buf * FA_KVBUF;
        const int s0 = c * 128;
        #pragma unroll
        for (int i = 0; i < 4; i++) {
            int row = rowb + 32 * i;
            uint32_t sw = (uint32_t)(row * 128) + (uint32_t)(((seg ^ (row & 7)) << 4));
            size_t go = (rbase + s0 + row) * 1024 + fcol + seg * 8;
            CP_ASYNC16(p + sw,         kh_g + go);
            CP_ASYNC16(p + 16384 + sw, kl_g + go);
            CP_ASYNC16(p + 32768 + sw, vh_g + go);
            CP_ASYNC16(p + 49152 + sw, vl_g + go);
        }
    };

    #pragma unroll
    for (int i = 0; i < 4; i++) {
        int row = rowb + 32 * i;
        uint32_t sw = (uint32_t)(row * 128) + (uint32_t)(((seg ^ (row & 7)) << 4));
        size_t go = (rbase + t0 + row) * 1024 + fcol + seg * 8;
        CP_ASYNC16(sb + FA_QOFF + sw,         qh_g + go);
        CP_ASYNC16(sb + FA_QOFF + 16384 + sw, ql_g + go);
    }
    #pragma unroll
    for (int j = 0; j < 16; j++) {
        int idx = tid + 256 * j;
        int r = idx >> 5, w = idx & 31;
        msk[r * 33 + w] = mbits[((size_t)b * 1024 + t0 + r) * 32 + w];
    }
    load_kv(0, 0); CP_COMMIT();

    float m0 = -INFINITY, m1 = -INFINITY, l0 = 0.f, l1 = 0.f;
    float o[8][4];
    #pragma unroll
    for (int j = 0; j < 8; j++)
        #pragma unroll
        for (int e = 0; e < 4; e++) o[j][e] = 0.f;
    uint32_t qfh[4][4], qfl[4][4];
    const int lr0 = wt0 + (lane >> 2);

    #pragma unroll 1
    for (int c = 0; c < 8; c++) {
        if (c < 7) { load_kv(c + 1, (c + 1) & 1); CP_COMMIT(); CP_WAIT(1); }
        else       { CP_WAIT(0); }
        __syncthreads();
        if (c == 0) {
            const int rA = wt0 + (lane & 15), cg = lane >> 4;
            #pragma unroll
            for (int ks = 0; ks < 4; ks++) {
                uint32_t off = (uint32_t)(rA * 128) + (uint32_t)((((ks*2+cg)) ^ (rA & 7)) << 4);
                LDSM4(qfh[ks][0], qfh[ks][1], qfh[ks][2], qfh[ks][3], sb + FA_QOFF + off);
                LDSM4(qfl[ks][0], qfl[ks][1], qfl[ks][2], qfl[ks][3], sb + FA_QOFF + 16384 + off);
            }
        }
        const uint32_t kv = sb + (c & 1) * FA_KVBUF;

        float s[16][4];
        #pragma unroll
        for (int i = 0; i < 16; i++)
            #pragma unroll
            for (int e = 0; e < 4; e++) s[i][e] = 0.f;
        #pragma unroll
        for (int np = 0; np < 8; np++) {
            const int rB = np * 16 + (lane & 7) + ((lane >> 4) & 1) * 8;
            const int cg = (lane >> 3) & 1;
            #pragma unroll
            for (int ks = 0; ks < 4; ks++) {
                uint32_t off = (uint32_t)(rB * 128) + (uint32_t)((((ks*2+cg)) ^ (rB & 7)) << 4);
                uint32_t k4[4], kl4[4];
                LDSM4(k4[0], k4[1], k4[2], k4[3], kv + off);
                LDSM4(kl4[0], kl4[1], kl4[2], kl4[3], kv + 16384 + off);
                MMA16816(s[2*np],   qfh[ks][0],qfh[ks][1],qfh[ks][2],qfh[ks][3], k4[0], k4[1]);
                MMA16816(s[2*np],   qfh[ks][0],qfh[ks][1],qfh[ks][2],qfh[ks][3], kl4[0], kl4[1]);
                MMA16816(s[2*np],   qfl[ks][0],qfl[ks][1],qfl[ks][2],qfl[ks][3], k4[0], k4[1]);
                MMA16816(s[2*np+1], qfh[ks][0],qfh[ks][1],qfh[ks][2],qfh[ks][3], k4[2], k4[3]);
                MMA16816(s[2*np+1], qfh[ks][0],qfh[ks][1],qfh[ks][2],qfh[ks][3], kl4[2], kl4[3]);
                MMA16816(s[2*np+1], qfl[ks][0],qfl[ks][1],qfl[ks][2],qfl[ks][3], k4[2], k4[3]);
            }
        }

        float cm0 = -3.4e38f, cm1 = -3.4e38f;
        #pragma unroll
        for (int nt = 0; nt < 16; nt++) {
            const int bp = (8 * nt + 2 * (lane & 3)) & 31;
            const uint32_t wa = msk[lr0 * 33 + c * 4 + (nt >> 2)];
            const uint32_t wb = msk[(lr0 + 8) * 33 + c * 4 + (nt >> 2)];
            if (!((wa >> bp) & 1))       s[nt][0] = -1e9f;
            if (!((wa >> (bp + 1)) & 1)) s[nt][1] = -1e9f;
            if (!((wb >> bp) & 1))       s[nt][2] = -1e9f;
            if (!((wb >> (bp + 1)) & 1)) s[nt][3] = -1e9f;
            cm0 = fmaxf(cm0, fmaxf(s[nt][0], s[nt][1]));
            cm1 = fmaxf(cm1, fmaxf(s[nt][2], s[nt][3]));
        }
        cm0 = fmaxf(cm0, __shfl_xor_sync(0xffffffffu, cm0, 1));
        cm0 = fmaxf(cm0, __shfl_xor_sync(0xffffffffu, cm0, 2));
        cm1 = fmaxf(cm1, __shfl_xor_sync(0xffffffffu, cm1, 1));
        cm1 = fmaxf(cm1, __shfl_xor_sync(0xffffffffu, cm1, 2));
        float mn0 = fmaxf(m0, cm0), mn1 = fmaxf(m1, cm1);
        float sc0 = __expf(m0 - mn0), sc1 = __expf(m1 - mn1);
        m0 = mn0; m1 = mn1;
        float rs0 = 0.f, rs1 = 0.f;
        #pragma unroll
        for (int nt = 0; nt < 16; nt++) {
            s[nt][0] = __expf(s[nt][0] - mn0); s[nt][1] = __expf(s[nt][1] - mn0);
            s[nt][2] = __expf(s[nt][2] - mn1); s[nt][3] = __expf(s[nt][3] - mn1);
            rs0 += s[nt][0] + s[nt][1];
            rs1 += s[nt][2] + s[nt][3];
        }
        l0 = l0 * sc0 + rs0; l1 = l1 * sc1 + rs1;
        #pragma unroll
        for (int j = 0; j < 8; j++) {
            o[j][0] *= sc0; o[j][1] *= sc0; o[j][2] *= sc1; o[j][3] *= sc1;
        }

        #pragma unroll
        for (int ks = 0; ks < 8; ks++) {
            uint32_t ph[4], pl[4];
            pack_hilo(s[2*ks][0],   s[2*ks][1],   ph[0], pl[0]);
            pack_hilo(s[2*ks][2],   s[2*ks][3],   ph[1], pl[1]);
            pack_hilo(s[2*ks+1][0], s[2*ks+1][1], ph[2], pl[2]);
            pack_hilo(s[2*ks+1][2], s[2*ks+1][3], ph[3], pl[3]);
            const int vrow = ks * 16 + (lane & 7) + 8 * ((lane >> 3) & 1);
            #pragma unroll
            for (int ds = 0; ds < 4; ds++) {
                uint32_t off = (uint32_t)(vrow * 128) +
                               (uint32_t)((((ds*2 + (lane >> 4))) ^ (vrow & 7)) << 4);
                uint32_t v4[4], vl4[4];
                LDSM4T(v4[0], v4[1], v4[2], v4[3], kv + 32768 + off);
                LDSM4T(vl4[0], vl4[1], vl4[2], vl4[3], kv + 49152 + off);
                MMA16816(o[2*ds],   ph[0],ph[1],ph[2],ph[3], v4[0], v4[1]);
                MMA16816(o[2*ds],   ph[0],ph[1],ph[2],ph[3], vl4[0], vl4[1]);
                MMA16816(o[2*ds],   pl[0],pl[1],pl[2],pl[3], v4[0], v4[1]);
                MMA16816(o[2*ds+1], ph[0],ph[1],ph[2],ph[3], v4[2], v4[3]);
                MMA16816(o[2*ds+1], ph[0],ph[1],ph[2],ph[3], vl4[2], vl4[3]);
                MMA16816(o[2*ds+1], pl[0],pl[1],pl[2],pl[3], v4[2], v4[3]);
            }
        }
        __syncthreads();
    }

    l0 += __shfl_xor_sync(0xffffffffu, l0, 1);
    l0 += __shfl_xor_sync(0xffffffffu, l0, 2);
    l1 += __shfl_xor_sync(0xffffffffu, l1, 1);
    l1 += __shfl_xor_sync(0xffffffffu, l1, 2);
    const float i0 = 1.f / l0, i1 = 1.f / l1;
    size_t ra = (rbase + t0 + lr0) * 1024 + fcol + 2 * (lane & 3);
    size_t rb2 = ra + 8 * 1024;
    #pragma unroll
    for (int j = 0; j < 8; j++) {
        uint32_t h0, lo0, h1, lo1;
        pack_hilo(o[j][0] * i0, o[j][1] * i0, h0, lo0);
        pack_hilo(o[j][2] * i1, o[j][3] * i1, h1, lo1);
        *(uint32_t*)(aoh_g + ra + 8*j)  = h0;
        *(uint32_t*)(aol_g + ra + 8*j)  = lo0;
        *(uint32_t*)(aoh_g + rb2 + 8*j) = h1;
        *(uint32_t*)(aol_g + rb2 + 8*j) = lo1;
    }
}

// ---------------- projection GEMM ----------------
__global__ __launch_bounds__(256, 1)
void proj_mma_kernel(const __nv_bfloat16* __restrict__ ah_g, const __nv_bfloat16* __restrict__ al_g,
                     const __nv_bfloat16* __restrict__ wh_g, const __nv_bfloat16* __restrict__ wl_g,
                     const float* __restrict__ bo, float* __restrict__ out) {
    extern __shared__ char dsm[];
    const int tid = threadIdx.x, wid = tid >> 5, lane = tid & 31;
    const int m0 = blockIdx.x * 128, n0 = blockIdx.y * 128;
    const uint32_t sbase = smem_to_u32(dsm);
    const int rowb = tid >> 3, seg = tid & 7;

    auto load_chunk = [&](int c, int buf) {
        const int ci0 = c << 6;
        const uint32_t sb = sbase + buf * 65536;
        #pragma unroll
        for (int i = 0; i < 4; i++) {
            int row = rowb + 32 * i;
            uint32_t sw = (uint32_t)(row * 128) + (uint32_t)(((seg ^ (row & 7)) << 4));
            size_t ao = (size_t)(m0 + row) * 1024 + ci0 + seg * 8;
            size_t wo = (size_t)(n0 + row) * 1024 + ci0 + seg * 8;
            CP_ASYNC16(sb + sw,         ah_g + ao);
            CP_ASYNC16(sb + 16384 + sw, al_g + ao);
            CP_ASYNC16(sb + 32768 + sw, wh_g + wo);
            CP_ASYNC16(sb + 49152 + sw, wl_g + wo);
        }
    };

    const int wm = (wid & 1) * 64, wn = (wid >> 1) * 32;
    int rowA[4], xorA[4];
    #pragma unroll
    for (int mt = 0; mt < 4; mt++) { rowA[mt] = wm + mt * 16 + (lane & 15); xorA[mt] = rowA[mt] & 7; }
    const int cgA = lane >> 4;
    int rowB[2], xorB[2];
    #pragma unroll
    for (int np = 0; np < 2; np++) {
        rowB[np] = wn + np * 16 + (lane & 7) + ((lane >> 4) & 1) * 8;
        xorB[np] = rowB[np] & 7;
    }
    const int cgB = (lane >> 3) & 1;

    float acc[4][4][4];
    #pragma unroll
    for (int mt = 0; mt < 4; mt++)
        #pragma unroll
        for (int nt = 0; nt < 4; nt++)
            #pragma unroll
            for (int e = 0; e < 4; e++) acc[mt][nt][e] = 0.f;

    load_chunk(0, 0); CP_COMMIT();
    for (int c = 0; c < 16; ++c) {
        const int buf = c & 1;
        if (c < 15) { load_chunk(c + 1, (c + 1) & 1); CP_COMMIT(); CP_WAIT(1); }
        else        { CP_WAIT(0); }
        __syncthreads();
        const uint32_t sb = sbase + buf * 65536;
        const uint32_t aHi = sb, aLo = sb + 16384, bHi = sb + 32768, bLo = sb + 49152;
        #pragma unroll
        for (int ks = 0; ks < 4; ks++) {
            uint32_t ah[4][4], al[4][4], bh2[2][4], bl2[2][4];
            #pragma unroll
            for (int mt = 0; mt < 4; mt++) {
                uint32_t off = (uint32_t)(rowA[mt] * 128) + (uint32_t)(((ks*2+cgA) ^ xorA[mt]) << 4);
                LDSM4(ah[mt][0], ah[mt][1], ah[mt][2], ah[mt][3], aHi + off);
                LDSM4(al[mt][0], al[mt][1], al[mt][2], al[mt][3], aLo + off);
            }
            #pragma unroll
            for (int np = 0; np < 2; np++) {
                uint32_t off = (uint32_t)(rowB[np] * 128) + (uint32_t)(((ks*2+cgB) ^ xorB[np]) << 4);
                LDSM4(bh2[np][0], bh2[np][1], bh2[np][2], bh2[np][3], bHi + off);
                LDSM4(bl2[np][0], bl2[np][1], bl2[np][2], bl2[np][3], bLo + off);
            }
            #pragma unroll
            for (int mt = 0; mt < 4; mt++)
                #pragma unroll
                for (int nt = 0; nt < 4; nt++) {
                    const int np = nt >> 1, h = (nt & 1) * 2;
                    MMA16816(acc[mt][nt], ah[mt][0],ah[mt][1],ah[mt][2],ah[mt][3], bh2[np][h], bh2[np][h+1]);
                    MMA16816(acc[mt][nt], ah[mt][0],ah[mt][1],ah[mt][2],ah[mt][3], bl2[np][h], bl2[np][h+1]);
                    MMA16816(acc[mt][nt], al[mt][0],al[mt][1],al[mt][2],al[mt][3], bh2[np][h], bh2[np][h+1]);
                }
        }
        __syncthreads();
    }

    #pragma unroll
    for (int mt = 0; mt < 4; mt++) {
        const int ma = m0 + wm + mt * 16 + (lane >> 2);
        const int mb2 = ma + 8;
        #pragma unroll
        for (int nt = 0; nt < 4; nt++) {
            const int n = n0 + wn + nt * 8 + 2 * (lane & 3);
            const float b0 = bo[n], b1 = bo[n + 1];
            *(float2*)(out + (size_t)ma * 1024 + n)  = make_float2(acc[mt][nt][0] + b0, acc[mt][nt][1] + b1);
            *(float2*)(out + (size_t)mb2 * 1024 + n) = make_float2(acc[mt][nt][2] + b0, acc[mt][nt][3] + b1);
        }
    }
}

// ---------------- kernel_launch ----------------
extern "C" void kernel_launch(void* const* d_in, const int* in_sizes, int n_in,
                              void* d_out, int out_size)
{
    (void)in_sizes; (void)n_in; (void)out_size;
    const float* q   = (const float*)d_in[0];
    const float* k   = (const float*)d_in[1];
    const float* v   = (const float*)d_in[2];
    const float* Wq  = (const float*)d_in[3];
    const float* bq  = (const float*)d_in[4];
    const float* Wk  = (const float*)d_in[5];
    const float* bk  = (const float*)d_in[6];
    const float* Wv  = (const float*)d_in[7];
    const float* bv  = (const float*)d_in[8];
    const float* Wo  = (const float*)d_in[9];
    const float* bo  = (const float*)d_in[10];
    const int*  mask = (const int*) d_in[11];
    float* out = (float*)d_out;

    __nv_bfloat16 *uwh, *uwl, *vwh, *vwl, *qh, *ql, *kh, *kl, *vh, *vl, *aoh, *aol, *woh, *wol;
    float* mw;
    uint32_t* mb;
    cudaGetSymbolAddress((void**)&uwh, g_uwh);   cudaGetSymbolAddress((void**)&uwl, g_uwl);
    cudaGetSymbolAddress((void**)&vwh, g_vwh);   cudaGetSymbolAddress((void**)&vwl, g_vwl);
    cudaGetSymbolAddress((void**)&mw, g_mw);
    cudaGetSymbolAddress((void**)&qh, g_qh);     cudaGetSymbolAddress((void**)&ql, g_ql);
    cudaGetSymbolAddress((void**)&kh, g_kh);     cudaGetSymbolAddress((void**)&kl, g_kl);
    cudaGetSymbolAddress((void**)&vh, g_vh);     cudaGetSymbolAddress((void**)&vl, g_vl);
    cudaGetSymbolAddress((void**)&aoh, g_aoh);   cudaGetSymbolAddress((void**)&aol, g_aol);
    cudaGetSymbolAddress((void**)&woh, g_woh);   cudaGetSymbolAddress((void**)&wol, g_wol);
    cudaGetSymbolAddress((void**)&mb, g_mb);

    cudaFuncSetAttribute(wino_gemm_kernel, cudaFuncAttributeMaxDynamicSharedMemorySize, GEMM_SMEM_BYTES);
    cudaFuncSetAttribute(flash_kernel,     cudaFuncAttributeMaxDynamicSharedMemorySize, FA_SMEM_BYTES);
    cudaFuncSetAttribute(proj_mma_kernel,  cudaFuncAttributeMaxDynamicSharedMemorySize, GEMM_SMEM_BYTES);

    wino_w_kernel<<<12288, 256>>>(Wq, Wk, Wv, uwh, uwl);
    wino_x_kernel<<<dim3(8, 32, 24), 256>>>(q, k, v, vwh, vwl);
    pack_wo_kernel<<<4096, 256>>>(Wo, woh, wol);
    pack_mask_kernel<<<32768, 256>>>(mask, mb);

    wino_gemm_kernel<<<dim3(8, 4, 108), 256, GEMM_SMEM_BYTES>>>(uwh, uwl, vwh, vwl, mw);
    wino_out_kernel<<<6144, 256>>>(mw, bq, bk, bv, qh, ql, kh, kl, vh, vl);

    flash_kernel<<<dim3(8, 128), 256, FA_SMEM_BYTES>>>(
        qh, ql, kh, kl, vh, vl, mb, aoh, aol);

    proj_mma_kernel<<<dim3(64, 8), 256, GEMM_SMEM_BYTES>>>(aoh, aol, woh, wol, bo, out);
}

// round 9
// speedup vs baseline: 12.1396x; 1.0027x over previous
#include <cuda_runtime.h>
#include <cuda_bf16.h>
#include <cstdint>
#include <math.h>

__device__ __forceinline__ uint32_t smem_to_u32(const void* p) {
    uint32_t a;
    asm("{ .reg .u64 t; cvta.to.shared.u64 t, %1; cvt.u32.u64 %0, t; }" : "=r"(a) : "l"(p));
    return a;
}
#define CP_ASYNC16(d, s) asm volatile("cp.async.cg.shared.global [%0], [%1], 16;" :: "r"(d), "l"(s))
#define CP_COMMIT() asm volatile("cp.async.commit_group;")
#define CP_WAIT(N)  asm volatile("cp.async.wait_group %0;" :: "n"(N))
#define LDSM4(R0,R1,R2,R3,A) \
    asm volatile("ldmatrix.sync.aligned.m8n8.x4.shared.b16 {%0,%1,%2,%3}, [%4];" \
        : "=r"(R0),"=r"(R1),"=r"(R2),"=r"(R3) : "r"(A))
#define LDSM4T(R0,R1,R2,R3,A) \
    asm volatile("ldmatrix.sync.aligned.m8n8.x4.trans.shared.b16 {%0,%1,%2,%3}, [%4];" \
        : "=r"(R0),"=r"(R1),"=r"(R2),"=r"(R3) : "r"(A))
#define MMA16816(D,A0,A1,A2,A3,B0,B1) \
    asm volatile("mma.sync.aligned.m16n8k16.row.col.f32.bf16.bf16.f32 " \
        "{%0,%1,%2,%3}, {%4,%5,%6,%7}, {%8,%9}, {%0,%1,%2,%3};" \
        : "+f"((D)[0]),"+f"((D)[1]),"+f"((D)[2]),"+f"((D)[3]) \
        : "r"(A0),"r"(A1),"r"(A2),"r"(A3),"r"(B0),"r"(B1))

__device__ __forceinline__ void pack_hilo(float v0, float v1, uint32_t& hi, uint32_t& lo) {
    uint32_t h;
    asm("cvt.rn.bf16x2.f32 %0, %1, %2;" : "=r"(h) : "f"(v1), "f"(v0));
    float l0 = v0 - __uint_as_float(h << 16);
    float l1 = v1 - __uint_as_float(h & 0xffff0000u);
    asm("cvt.rn.bf16x2.f32 %0, %1, %2;" : "=r"(lo) : "f"(l1), "f"(l0));
    hi = h;
}

// ---------------- scratch ----------------
// F(4x4,3x3): 36 g-planes per conv, 512 tiles (8 img * 64), K=1024
#define QKV_ELEMS (8u * 1024u * 1024u)
#define UW_ELEMS  (108ull * 1024u * 1024u)
#define VW_ELEMS  (108ull * 512u * 1024u)
__device__ __align__(128) __nv_bfloat16 g_uwh[UW_ELEMS], g_uwl[UW_ELEMS];   // U[g][co][ci]
__device__ __align__(128) __nv_bfloat16 g_vwh[VW_ELEMS], g_vwl[VW_ELEMS];   // V[g][tile][ci]
__device__ __align__(128) float g_mw[108ull * 1024u * 512u];                // M[g][co][tile]
__device__ __align__(128) __nv_bfloat16 g_qh[QKV_ELEMS], g_ql[QKV_ELEMS];
__device__ __align__(128) __nv_bfloat16 g_kh[QKV_ELEMS], g_kl[QKV_ELEMS];
__device__ __align__(128) __nv_bfloat16 g_vh[QKV_ELEMS], g_vl[QKV_ELEMS];
__device__ __align__(128) __nv_bfloat16 g_aoh[QKV_ELEMS], g_aol[QKV_ELEMS];
__device__ __align__(128) __nv_bfloat16 g_woh[1024u*1024u], g_wol[1024u*1024u];
__device__ __align__(128) uint32_t g_mb[8u * 1024u * 32u];

// ---------------- prep ----------------
__global__ void pack_wo_kernel(const float* __restrict__ Wo,
                               __nv_bfloat16* __restrict__ wh, __nv_bfloat16* __restrict__ wl) {
    int i = blockIdx.x * 256 + threadIdx.x;
    float w = Wo[i];
    __nv_bfloat16 h = __float2bfloat16(w);
    wh[i] = h;
    wl[i] = __float2bfloat16(w - __bfloat162float(h));
}

__global__ void pack_mask_kernel(const int* __restrict__ mask, uint32_t* __restrict__ mb) {
    int idx = blockIdx.x * 256 + threadIdx.x;
    uint32_t word = __ballot_sync(0xffffffffu, mask[idx] != 0);
    if ((threadIdx.x & 31) == 0) mb[idx >> 5] = word;
}

// ---------------- Winograd F(4,3) weight transform: U = G g G^T ----------------
__device__ __forceinline__ void gtrans(float a, float b, float d, float* y) {
    const float s6 = 1.f / 6.f, s12 = 1.f / 12.f, s24 = 1.f / 24.f;
    y[0] = 0.25f * a;
    y[1] = -(a + b + d) * s6;
    y[2] = (-a + b - d) * s6;
    y[3] = a * s24 + b * s12 + d * s6;
    y[4] = a * s24 - b * s12 + d * s6;
    y[5] = d;
}

__global__ __launch_bounds__(256)
void wino_w_kernel(const float* __restrict__ Wq, const float* __restrict__ Wk,
                   const float* __restrict__ Wv,
                   __nv_bfloat16* __restrict__ uh, __nv_bfloat16* __restrict__ ul) {
    int i = blockIdx.x * 256 + threadIdx.x;        // < 3*2^20
    int conv = i >> 20;
    int co = (i >> 10) & 1023, ci = i & 1023;
    const float* W = conv == 0 ? Wq : (conv == 1 ? Wk : Wv);
    const float* g = W + ((size_t)co * 1024 + ci) * 9;
    float t[6][3];
    #pragma unroll
    for (int c = 0; c < 3; c++) {
        float col[6];
        gtrans(g[c], g[3 + c], g[6 + c], col);
        #pragma unroll
        for (int u = 0; u < 6; u++) t[u][c] = col[u];
    }
    #pragma unroll
    for (int u = 0; u < 6; u++) {
        float U[6];
        gtrans(t[u][0], t[u][1], t[u][2], U);
        #pragma unroll
        for (int v = 0; v < 6; v++) {
            int kk = u * 6 + v;
            size_t o = (((size_t)(conv * 36 + kk)) << 20) + ((size_t)co << 10) + ci;
            __nv_bfloat16 h = __float2bfloat16(U[v]);
            uh[o] = h;
            ul[o] = __float2bfloat16(U[v] - __bfloat162float(h));
        }
    }
}

// ---------------- Winograd input transform: V = B^T d B ----------------
__device__ __forceinline__ void btrans(const float* x, float* y) {
    y[0] = 4.f * x[0] - 5.f * x[2] + x[4];
    y[1] = -4.f * x[1] - 4.f * x[2] + x[3] + x[4];
    y[2] = 4.f * x[1] - 4.f * x[2] - x[3] + x[4];
    y[3] = -2.f * x[1] - x[2] + 2.f * x[3] + x[4];
    y[4] = 2.f * x[1] - x[2] - 2.f * x[3] + x[4];
    y[5] = 4.f * x[1] - 5.f * x[3] + x[5];
}

// grid (8 ty, 32 ci-chunk(32), 24 = conv*8+b), 256 threads.
__global__ __launch_bounds__(256)
void wino_x_kernel(const float* __restrict__ q, const float* __restrict__ k,
                   const float* __restrict__ v,
                   __nv_bfloat16* __restrict__ vwh, __nv_bfloat16* __restrict__ vwl) {
    __shared__ float xs[6][32][34];   // [u][ci][col; col 0 == image col -1]
    const int conv = blockIdx.z >> 3, b = blockIdx.z & 7;
    const float* x = conv == 0 ? q : (conv == 1 ? k : v);
    const int ty = blockIdx.x;
    const int ci0 = blockIdx.y * 32;
    const int tid = threadIdx.x;

    for (int l = tid; l < 6 * 32 * 34; l += 256) {
        int u = l / 1088;
        int rem = l - u * 1088;
        int ci = rem / 34, cc = rem - ci * 34;
        int gr = 4 * ty - 1 + u, gc = cc - 1;
        float val = 0.f;
        if ((unsigned)gr < 32u && (unsigned)gc < 32u)
            val = x[((size_t)(b * 1024 + ci0 + ci)) * 1024 + gr * 32 + gc];
        xs[u][ci][cc] = val;
    }
    __syncthreads();

    const int tx = tid >> 5, ci = tid & 31;
    float d[6][6];
    #pragma unroll
    for (int u = 0; u < 6; u++)
        #pragma unroll
        for (int vv = 0; vv < 6; vv++) d[u][vv] = xs[u][ci][4 * tx + vv];
    float t1[6][6];
    #pragma unroll
    for (int vv = 0; vv < 6; vv++) {
        float col[6] = {d[0][vv], d[1][vv], d[2][vv], d[3][vv], d[4][vv], d[5][vv]};
        float y[6];
        btrans(col, y);
        #pragma unroll
        for (int u = 0; u < 6; u++) t1[u][vv] = y[u];
    }
    const size_t tile = (size_t)b * 64 + ty * 8 + tx;
    #pragma unroll
    for (int u = 0; u < 6; u++) {
        float y[6];
        btrans(t1[u], y);
        #pragma unroll
        for (int vv = 0; vv < 6; vv++) {
            int kk = u * 6 + vv;
            size_t o = ((size_t)(conv * 36 + kk) * 512 + tile) * 1024 + ci0 + ci;
            __nv_bfloat16 h = __float2bfloat16(y[vv]);
            vwh[o] = h;
            vwl[o] = __float2bfloat16(y[vv] - __bfloat162float(h));
        }
    }
}

// ---------------- Winograd batched GEMM: M[g] = U[g] * V[g]^T ----------------
#define GEMM_SMEM_BYTES (2 * 4 * 16384)

__global__ __launch_bounds__(256, 1)
void wino_gemm_kernel(const __nv_bfloat16* __restrict__ uh, const __nv_bfloat16* __restrict__ ul,
                      const __nv_bfloat16* __restrict__ vwh, const __nv_bfloat16* __restrict__ vwl,
                      float* __restrict__ mw) {
    extern __shared__ char dsm[];
    const int tid = threadIdx.x, wid = tid >> 5, lane = tid & 31;
    const int m0 = blockIdx.x * 128, n0 = blockIdx.y * 128, gidx = blockIdx.z;
    const __nv_bfloat16* ah_g = uh  + ((size_t)gidx << 20);
    const __nv_bfloat16* al_g = ul  + ((size_t)gidx << 20);
    const __nv_bfloat16* bh_g = vwh + ((size_t)gidx << 19);
    const __nv_bfloat16* bl_g = vwl + ((size_t)gidx << 19);
    const uint32_t sbase = smem_to_u32(dsm);
    const int rowb = tid >> 3, seg = tid & 7;

    auto load_chunk = [&](int c, int buf) {
        const int ci0 = c << 6;
        const uint32_t sb = sbase + buf * 65536;
        #pragma unroll
        for (int i = 0; i < 4; i++) {
            int row = rowb + 32 * i;
            uint32_t sw = (uint32_t)(row * 128) + (uint32_t)(((seg ^ (row & 7)) << 4));
            size_t ao = (size_t)(m0 + row) * 1024 + ci0 + seg * 8;
            size_t bo = (size_t)(n0 + row) * 1024 + ci0 + seg * 8;
            CP_ASYNC16(sb + sw,         ah_g + ao);
            CP_ASYNC16(sb + 16384 + sw, al_g + ao);
            CP_ASYNC16(sb + 32768 + sw, bh_g + bo);
            CP_ASYNC16(sb + 49152 + sw, bl_g + bo);
        }
    };

    const int wm = (wid & 1) * 64, wn = (wid >> 1) * 32;
    int rowA[4], xorA[4];
    #pragma unroll
    for (int mt = 0; mt < 4; mt++) { rowA[mt] = wm + mt * 16 + (lane & 15); xorA[mt] = rowA[mt] & 7; }
    const int cgA = lane >> 4;
    int rowB[2], xorB[2];
    #pragma unroll
    for (int np = 0; np < 2; np++) {
        rowB[np] = wn + np * 16 + (lane & 7) + ((lane >> 4) & 1) * 8;
        xorB[np] = rowB[np] & 7;
    }
    const int cgB = (lane >> 3) & 1;

    float acc[4][4][4];
    #pragma unroll
    for (int mt = 0; mt < 4; mt++)
        #pragma unroll
        for (int nt = 0; nt < 4; nt++)
            #pragma unroll
            for (int e = 0; e < 4; e++) acc[mt][nt][e] = 0.f;

    load_chunk(0, 0); CP_COMMIT();
    for (int c = 0; c < 16; ++c) {
        const int buf = c & 1;
        if (c < 15) { load_chunk(c + 1, (c + 1) & 1); CP_COMMIT(); CP_WAIT(1); }
        else        { CP_WAIT(0); }
        __syncthreads();
        const uint32_t sb = sbase + buf * 65536;
        const uint32_t aHi = sb, aLo = sb + 16384, bHi = sb + 32768, bLo = sb + 49152;
        #pragma unroll
        for (int ks = 0; ks < 4; ks++) {
            uint32_t ah[4][4], al[4][4], bh2[2][4], bl2[2][4];
            #pragma unroll
            for (int mt = 0; mt < 4; mt++) {
                uint32_t off = (uint32_t)(rowA[mt] * 128) + (uint32_t)(((ks*2+cgA) ^ xorA[mt]) << 4);
                LDSM4(ah[mt][0], ah[mt][1], ah[mt][2], ah[mt][3], aHi + off);
                LDSM4(al[mt][0], al[mt][1], al[mt][2], al[mt][3], aLo + off);
            }
            #pragma unroll
            for (int np = 0; np < 2; np++) {
                uint32_t off = (uint32_t)(rowB[np] * 128) + (uint32_t)(((ks*2+cgB) ^ xorB[np]) << 4);
                LDSM4(bh2[np][0], bh2[np][1], bh2[np][2], bh2[np][3], bHi + off);
                LDSM4(bl2[np][0], bl2[np][1], bl2[np][2], bl2[np][3], bLo + off);
            }
            #pragma unroll
            for (int mt = 0; mt < 4; mt++)
                #pragma unroll
                for (int nt = 0; nt < 4; nt++) {
                    const int np = nt >> 1, h = (nt & 1) * 2;
                    MMA16816(acc[mt][nt], ah[mt][0],ah[mt][1],ah[mt][2],ah[mt][3], bh2[np][h], bh2[np][h+1]);
                    MMA16816(acc[mt][nt], ah[mt][0],ah[mt][1],ah[mt][2],ah[mt][3], bl2[np][h], bl2[np][h+1]);
                    MMA16816(acc[mt][nt], al[mt][0],al[mt][1],al[mt][2],al[mt][3], bh2[np][h], bh2[np][h+1]);
                }
        }
        __syncthreads();
    }

    float* outp = mw + (size_t)gidx * 1024 * 512;
    #pragma unroll
    for (int mt = 0; mt < 4; mt++) {
        const int ma = m0 + wm + mt * 16 + (lane >> 2);
        const int mb2 = ma + 8;
        #pragma unroll
        for (int nt = 0; nt < 4; nt++) {
            const int n = n0 + wn + nt * 8 + 2 * (lane & 3);
            *(float2*)(outp + (size_t)ma  * 512 + n) = make_float2(acc[mt][nt][0], acc[mt][nt][1]);
            *(float2*)(outp + (size_t)mb2 * 512 + n) = make_float2(acc[mt][nt][2], acc[mt][nt][3]);
        }
    }
}

// ---------------- Winograd output transform: Y = A^T M A ----------------
__device__ __forceinline__ void atrans(const float* x, float* y) {
    y[0] = x[0] + x[1] + x[2] + x[3] + x[4];
    y[1] = x[1] - x[2] + 2.f * x[3] - 2.f * x[4];
    y[2] = x[1] + x[2] + 4.f * x[3] + 4.f * x[4];
    y[3] = x[1] - x[2] + 8.f * x[3] - 8.f * x[4] + x[5];
}

__global__ __launch_bounds__(256)
void wino_out_kernel(const float* __restrict__ mw,
                     const float* __restrict__ bq, const float* __restrict__ bk,
                     const float* __restrict__ bv,
                     __nv_bfloat16* __restrict__ qh, __nv_bfloat16* __restrict__ ql,
                     __nv_bfloat16* __restrict__ kh, __nv_bfloat16* __restrict__ kl,
                     __nv_bfloat16* __restrict__ vh, __nv_bfloat16* __restrict__ vl) {
    const int idx = blockIdx.x * 256 + threadIdx.x;   // < 3*1024*512
    const int conv = idx >> 19;
    const int rem = idx & 0x7FFFF;
    const int co = rem >> 9;
    const int tile = rem & 511;

    float M[36];
    #pragma unroll
    for (int kk = 0; kk < 36; kk++)
        M[kk] = mw[(size_t)(conv * 36 + kk) * 524288 + (size_t)co * 512 + tile];

    float t[4][6];
    #pragma unroll
    for (int vv = 0; vv < 6; vv++) {
        float col[6] = {M[vv], M[6 + vv], M[12 + vv], M[18 + vv], M[24 + vv], M[30 + vv]};
        float y[4];
        atrans(col, y);
        #pragma unroll
        for (int r = 0; r < 4; r++) t[r][vv] = y[r];
    }

    __nv_bfloat16 *oh, *ol;
    const float* bias;
    if (conv == 0)      { oh = qh; ol = ql; bias = bq; }
    else if (conv == 1) { oh = kh; ol = kl; bias = bk; }
    else                { oh = vh; ol = vl; bias = bv; }
    const float scale = (conv == 0) ? 0.125f : 1.0f;
    const float bi = bias[co];

    const int b = tile >> 6, tt = tile & 63;
    const int tyy = tt >> 3, txx = tt & 7;
    size_t base = ((size_t)(b * 1024 + co)) * 1024 + (4 * tyy) * 32 + 4 * txx;
    #pragma unroll
    for (int r = 0; r < 4; r++) {
        float y[4];
        atrans(t[r], y);
        uint32_t h0, l0, h1, l1;
        pack_hilo((y[0] + bi) * scale, (y[1] + bi) * scale, h0, l0);
        pack_hilo((y[2] + bi) * scale, (y[3] + bi) * scale, h1, l1);
        size_t o = base + (size_t)r * 32;
        *(uint32_t*)(oh + o)     = h0;
        *(uint32_t*)(oh + o + 2) = h1;
        *(uint32_t*)(ol + o)     = l0;
        *(uint32_t*)(ol + o + 2) = l1;
    }
}

// ---------------- fused flash attention ----------------
#define FA_KVBUF 65536
#define FA_QOFF  (2 * FA_KVBUF)
#define FA_MOFF  (FA_QOFF + 32768)
#define FA_SMEM_BYTES (FA_MOFF + 128 * 33 * 4)

__global__ __launch_bounds__(256, 1)
void flash_kernel(const __nv_bfloat16* __restrict__ qh_g, const __nv_bfloat16* __restrict__ ql_g,
                  const __nv_bfloat16* __restrict__ kh_g, const __nv_bfloat16* __restrict__ kl_g,
                  const __nv_bfloat16* __restrict__ vh_g, const __nv_bfloat16* __restrict__ vl_g,
                  const uint32_t* __restrict__ mbits,
                  __nv_bfloat16* __restrict__ aoh_g, __nv_bfloat16* __restrict__ aol_g) {
    extern __shared__ char dsm[];
    const int tid = threadIdx.x, wid = tid >> 5, lane = tid & 31;
    const int t0 = blockIdx.x * 128, bh = blockIdx.y, b = bh >> 4, h = bh & 15;
    const uint32_t sb = smem_to_u32(dsm);
    uint32_t* msk = (uint32_t*)(dsm + FA_MOFF);
    const int rowb = tid >> 3, seg = tid & 7;
    const size_t rbase = (size_t)b * 1024;
    const int fcol = h * 64, wt0 = wid * 16;

    auto load_kv = [&](int c, int buf) {
        const uint32_t p = sb + buf * FA_KVBUF;
        const int s0 = c * 128;
        #pragma unroll
        for (int i = 0; i < 4; i++) {
            int row = rowb + 32 * i;
            uint32_t sw = (uint32_t)(row * 128) + (uint32_t)(((seg ^ (row & 7)) << 4));
            size_t go = (rbase + s0 + row) * 1024 + fcol + seg * 8;
            CP_ASYNC16(p + sw,         kh_g + go);
            CP_ASYNC16(p + 16384 + sw, kl_g + go);
            CP_ASYNC16(p + 32768 + sw, vh_g + go);
            CP_ASYNC16(p + 49152 + sw, vl_g + go);
        }
    };

    #pragma unroll
    for (int i = 0; i < 4; i++) {
        int row = rowb + 32 * i;
        uint32_t sw = (uint32_t)(row * 128) + (uint32_t)(((seg ^ (row & 7)) << 4));
        size_t go = (rbase + t0 + row) * 1024 + fcol + seg * 8;
        CP_ASYNC16(sb + FA_QOFF + sw,         qh_g + go);
        CP_ASYNC16(sb + FA_QOFF + 16384 + sw, ql_g + go);
    }
    #pragma unroll
    for (int j = 0; j < 16; j++) {
        int idx = tid + 256 * j;
        int r = idx >> 5, w = idx & 31;
        msk[r * 33 + w] = mbits[((size_t)b * 1024 + t0 + r) * 32 + w];
    }
    load_kv(0, 0); CP_COMMIT();

    float m0 = -INFINITY, m1 = -INFINITY, l0 = 0.f, l1 = 0.f;
    float o[8][4];
    #pragma unroll
    for (int j = 0; j < 8; j++)
        #pragma unroll
        for (int e = 0; e < 4; e++) o[j][e] = 0.f;
    uint32_t qfh[4][4], qfl[4][4];
    const int lr0 = wt0 + (lane >> 2);

    #pragma unroll 1
    for (int c = 0; c < 8; c++) {
        if (c < 7) { load_kv(c + 1, (c + 1) & 1); CP_COMMIT(); CP_WAIT(1); }
        else       { CP_WAIT(0); }
        __syncthreads();
        if (c == 0) {
            const int rA = wt0 + (lane & 15), cg = lane >> 4;
            #pragma unroll
            for (int ks = 0; ks < 4; ks++) {
                uint32_t off = (uint32_t)(rA * 128) + (uint32_t)((((ks*2+cg)) ^ (rA & 7)) << 4);
                LDSM4(qfh[ks][0], qfh[ks][1], qfh[ks][2], qfh[ks][3], sb + FA_QOFF + off);
                LDSM4(qfl[ks][0], qfl[ks][1], qfl[ks][2], qfl[ks][3], sb + FA_QOFF + 16384 + off);
            }
        }
        const uint32_t kv = sb + (c & 1) * FA_KVBUF;

        float s[16][4];
        #pragma unroll
        for (int i = 0; i < 16; i++)
            #pragma unroll
            for (int e = 0; e < 4; e++) s[i][e] = 0.f;
        #pragma unroll
        for (int np = 0; np < 8; np++) {
            const int rB = np * 16 + (lane & 7) + ((lane >> 4) & 1) * 8;
            const int cg = (lane >> 3) & 1;
            #pragma unroll
            for (int ks = 0; ks < 4; ks++) {
                uint32_t off = (uint32_t)(rB * 128) + (uint32_t)((((ks*2+cg)) ^ (rB & 7)) << 4);
                uint32_t k4[4], kl4[4];
                LDSM4(k4[0], k4[1], k4[2], k4[3], kv + off);
                LDSM4(kl4[0], kl4[1], kl4[2], kl4[3], kv + 16384 + off);
                MMA16816(s[2*np],   qfh[ks][0],qfh[ks][1],qfh[ks][2],qfh[ks][3], k4[0], k4[1]);
                MMA16816(s[2*np],   qfh[ks][0],qfh[ks][1],qfh[ks][2],qfh[ks][3], kl4[0], kl4[1]);
                MMA16816(s[2*np],   qfl[ks][0],qfl[ks][1],qfl[ks][2],qfl[ks][3], k4[0], k4[1]);
                MMA16816(s[2*np+1], qfh[ks][0],qfh[ks][1],qfh[ks][2],qfh[ks][3], k4[2], k4[3]);
                MMA16816(s[2*np+1], qfh[ks][0],qfh[ks][1],qfh[ks][2],qfh[ks][3], kl4[2], kl4[3]);
                MMA16816(s[2*np+1], qfl[ks][0],qfl[ks][1],qfl[ks][2],qfl[ks][3], k4[2], k4[3]);
            }
        }

        float cm0 = -3.4e38f, cm1 = -3.4e38f;
        #pragma unroll
        for (int nt = 0; nt < 16; nt++) {
            const int bp = (8 * nt + 2 * (lane & 3)) & 31;
            const uint32_t wa = msk[lr0 * 33 + c * 4 + (nt >> 2)];
            const uint32_t wb = msk[(lr0 + 8) * 33 + c * 4 + (nt >> 2)];
            if (!((wa >> bp) & 1))       s[nt][0] = -1e9f;
            if (!((wa >> (bp + 1)) & 1)) s[nt][1] = -1e9f;
            if (!((wb >> bp) & 1))       s[nt][2] = -1e9f;
            if (!((wb >> (bp + 1)) & 1)) s[nt][3] = -1e9f;
            cm0 = fmaxf(cm0, fmaxf(s[nt][0], s[nt][1]));
            cm1 = fmaxf(cm1, fmaxf(s[nt][2], s[nt][3]));
        }
        cm0 = fmaxf(cm0, __shfl_xor_sync(0xffffffffu, cm0, 1));
        cm0 = fmaxf(cm0, __shfl_xor_sync(0xffffffffu, cm0, 2));
        cm1 = fmaxf(cm1, __shfl_xor_sync(0xffffffffu, cm1, 1));
        cm1 = fmaxf(cm1, __shfl_xor_sync(0xffffffffu, cm1, 2));
        float mn0 = fmaxf(m0, cm0), mn1 = fmaxf(m1, cm1);
        float sc0 = __expf(m0 - mn0), sc1 = __expf(m1 - mn1);
        m0 = mn0; m1 = mn1;
        float rs0 = 0.f, rs1 = 0.f;
        #pragma unroll
        for (int nt = 0; nt < 16; nt++) {
            s[nt][0] = __expf(s[nt][0] - mn0); s[nt][1] = __expf(s[nt][1] - mn0);
            s[nt][2] = __expf(s[nt][2] - mn1); s[nt][3] = __expf(s[nt][3] - mn1);
            rs0 += s[nt][0] + s[nt][1];
            rs1 += s[nt][2] + s[nt][3];
        }
        l0 = l0 * sc0 + rs0; l1 = l1 * sc1 + rs1;
        #pragma unroll
        for (int j = 0; j < 8; j++) {
            o[j][0] *= sc0; o[j][1] *= sc0; o[j][2] *= sc1; o[j][3] *= sc1;
        }

        #pragma unroll
        for (int ks = 0; ks < 8; ks++) {
            uint32_t ph[4], pl[4];
            pack_hilo(s[2*ks][0],   s[2*ks][1],   ph[0], pl[0]);
            pack_hilo(s[2*ks][2],   s[2*ks][3],   ph[1], pl[1]);
            pack_hilo(s[2*ks+1][0], s[2*ks+1][1], ph[2], pl[2]);
            pack_hilo(s[2*ks+1][2], s[2*ks+1][3], ph[3], pl[3]);
            const int vrow = ks * 16 + (lane & 7) + 8 * ((lane >> 3) & 1);
            #pragma unroll
            for (int ds = 0; ds < 4; ds++) {
                uint32_t off = (uint32_t)(vrow * 128) +
                               (uint32_t)((((ds*2 + (lane >> 4))) ^ (vrow & 7)) << 4);
                uint32_t v4[4], vl4[4];
                LDSM4T(v4[0], v4[1], v4[2], v4[3], kv + 32768 + off);
                LDSM4T(vl4[0], vl4[1], vl4[2], vl4[3], kv + 49152 + off);
                MMA16816(o[2*ds],   ph[0],ph[1],ph[2],ph[3], v4[0], v4[1]);
                MMA16816(o[2*ds],   ph[0],ph[1],ph[2],ph[3], vl4[0], vl4[1]);
                MMA16816(o[2*ds],   pl[0],pl[1],pl[2],pl[3], v4[0], v4[1]);
                MMA16816(o[2*ds+1], ph[0],ph[1],ph[2],ph[3], v4[2], v4[3]);
                MMA16816(o[2*ds+1], ph[0],ph[1],ph[2],ph[3], vl4[2], vl4[3]);
                MMA16816(o[2*ds+1], pl[0],pl[1],pl[2],pl[3], v4[2], v4[3]);
            }
        }
        __syncthreads();
    }

    l0 += __shfl_xor_sync(0xffffffffu, l0, 1);
    l0 += __shfl_xor_sync(0xffffffffu, l0, 2);
    l1 += __shfl_xor_sync(0xffffffffu, l1, 1);
    l1 += __shfl_xor_sync(0xffffffffu, l1, 2);
    const float i0 = 1.f / l0, i1 = 1.f / l1;
    size_t ra = (rbase + t0 + lr0) * 1024 + fcol + 2 * (lane & 3);
    size_t rb2 = ra + 8 * 1024;
    #pragma unroll
    for (int j = 0; j < 8; j++) {
        uint32_t h0, lo0, h1, lo1;
        pack_hilo(o[j][0] * i0, o[j][1] * i0, h0, lo0);
        pack_hilo(o[j][2] * i1, o[j][3] * i1, h1, lo1);
        *(uint32_t*)(aoh_g + ra + 8*j)  = h0;
        *(uint32_t*)(aol_g + ra + 8*j)  = lo0;
        *(uint32_t*)(aoh_g + rb2 + 8*j) = h1;
        *(uint32_t*)(aol_g + rb2 + 8*j) = lo1;
    }
}

// ---------------- projection GEMM ----------------
__global__ __launch_bounds__(256, 1)
void proj_mma_kernel(const __nv_bfloat16* __restrict__ ah_g, const __nv_bfloat16* __restrict__ al_g,
                     const __nv_bfloat16* __restrict__ wh_g, const __nv_bfloat16* __restrict__ wl_g,
                     const float* __restrict__ bo, float* __restrict__ out) {
    extern __shared__ char dsm[];
    const int tid = threadIdx.x, wid = tid >> 5, lane = tid & 31;
    const int m0 = blockIdx.x * 128, n0 = blockIdx.y * 128;
    const uint32_t sbase = smem_to_u32(dsm);
    const int rowb = tid >> 3, seg = tid & 7;

    auto load_chunk = [&](int c, int buf) {
        const int ci0 = c << 6;
        const uint32_t sb = sbase + buf * 65536;
        #pragma unroll
        for (int i = 0; i < 4; i++) {
            int row = rowb + 32 * i;
            uint32_t sw = (uint32_t)(row * 128) + (uint32_t)(((seg ^ (row & 7)) << 4));
            size_t ao = (size_t)(m0 + row) * 1024 + ci0 + seg * 8;
            size_t wo = (size_t)(n0 + row) * 1024 + ci0 + seg * 8;
            CP_ASYNC16(sb + sw,         ah_g + ao);
            CP_ASYNC16(sb + 16384 + sw, al_g + ao);
            CP_ASYNC16(sb + 32768 + sw, wh_g + wo);
            CP_ASYNC16(sb + 49152 + sw, wl_g + wo);
        }
    };

    const int wm = (wid & 1) * 64, wn = (wid >> 1) * 32;
    int rowA[4], xorA[4];
    #pragma unroll
    for (int mt = 0; mt < 4; mt++) { rowA[mt] = wm + mt * 16 + (lane & 15); xorA[mt] = rowA[mt] & 7; }
    const int cgA = lane >> 4;
    int rowB[2], xorB[2];
    #pragma unroll
    for (int np = 0; np < 2; np++) {
        rowB[np] = wn + np * 16 + (lane & 7) + ((lane >> 4) & 1) * 8;
        xorB[np] = rowB[np] & 7;
    }
    const int cgB = (lane >> 3) & 1;

    float acc[4][4][4];
    #pragma unroll
    for (int mt = 0; mt < 4; mt++)
        #pragma unroll
        for (int nt = 0; nt < 4; nt++)
            #pragma unroll
            for (int e = 0; e < 4; e++) acc[mt][nt][e] = 0.f;

    load_chunk(0, 0); CP_COMMIT();
    for (int c = 0; c < 16; ++c) {
        const int buf = c & 1;
        if (c < 15) { load_chunk(c + 1, (c + 1) & 1); CP_COMMIT(); CP_WAIT(1); }
        else        { CP_WAIT(0); }
        __syncthreads();
        const uint32_t sb = sbase + buf * 65536;
        const uint32_t aHi = sb, aLo = sb + 16384, bHi = sb + 32768, bLo = sb + 49152;
        #pragma unroll
        for (int ks = 0; ks < 4; ks++) {
            uint32_t ah[4][4], al[4][4], bh2[2][4], bl2[2][4];
            #pragma unroll
            for (int mt = 0; mt < 4; mt++) {
                uint32_t off = (uint32_t)(rowA[mt] * 128) + (uint32_t)(((ks*2+cgA) ^ xorA[mt]) << 4);
                LDSM4(ah[mt][0], ah[mt][1], ah[mt][2], ah[mt][3], aHi + off);
                LDSM4(al[mt][0], al[mt][1], al[mt][2], al[mt][3], aLo + off);
            }
            #pragma unroll
            for (int np = 0; np < 2; np++) {
                uint32_t off = (uint32_t)(rowB[np] * 128) + (uint32_t)(((ks*2+cgB) ^ xorB[np]) << 4);
                LDSM4(bh2[np][0], bh2[np][1], bh2[np][2], bh2[np][3], bHi + off);
                LDSM4(bl2[np][0], bl2[np][1], bl2[np][2], bl2[np][3], bLo + off);
            }
            #pragma unroll
            for (int mt = 0; mt < 4; mt++)
                #pragma unroll
                for (int nt = 0; nt < 4; nt++) {
                    const int np = nt >> 1, h = (nt & 1) * 2;
                    MMA16816(acc[mt][nt], ah[mt][0],ah[mt][1],ah[mt][2],ah[mt][3], bh2[np][h], bh2[np][h+1]);
                    MMA16816(acc[mt][nt], ah[mt][0],ah[mt][1],ah[mt][2],ah[mt][3], bl2[np][h], bl2[np][h+1]);
                    MMA16816(acc[mt][nt], al[mt][0],al[mt][1],al[mt][2],al[mt][3], bh2[np][h], bh2[np][h+1]);
                }
        }
        __syncthreads();
    }

    #pragma unroll
    for (int mt = 0; mt < 4; mt++) {
        const int ma = m0 + wm + mt * 16 + (lane >> 2);
        const int mb2 = ma + 8;
        #pragma unroll
        for (int nt = 0; nt < 4; nt++) {
            const int n = n0 + wn + nt * 8 + 2 * (lane & 3);
            const float b0 = bo[n], b1 = bo[n + 1];
            *(float2*)(out + (size_t)ma * 1024 + n)  = make_float2(acc[mt][nt][0] + b0, acc[mt][nt][1] + b1);
            *(float2*)(out + (size_t)mb2 * 1024 + n) = make_float2(acc[mt][nt][2] + b0, acc[mt][nt][3] + b1);
        }
    }
}

// ---------------- kernel_launch ----------------
extern "C" void kernel_launch(void* const* d_in, const int* in_sizes, int n_in,
                              void* d_out, int out_size)
{
    (void)in_sizes; (void)n_in; (void)out_size;
    const float* q   = (const float*)d_in[0];
    const float* k   = (const float*)d_in[1];
    const float* v   = (const float*)d_in[2];
    const float* Wq  = (const float*)d_in[3];
    const float* bq  = (const float*)d_in[4];
    const float* Wk  = (const float*)d_in[5];
    const float* bk  = (const float*)d_in[6];
    const float* Wv  = (const float*)d_in[7];
    const float* bv  = (const float*)d_in[8];
    const float* Wo  = (const float*)d_in[9];
    const float* bo  = (const float*)d_in[10];
    const int*  mask = (const int*) d_in[11];
    float* out = (float*)d_out;

    __nv_bfloat16 *uwh, *uwl, *vwh, *vwl, *qh, *ql, *kh, *kl, *vh, *vl, *aoh, *aol, *woh, *wol;
    float* mw;
    uint32_t* mb;
    cudaGetSymbolAddress((void**)&uwh, g_uwh);   cudaGetSymbolAddress((void**)&uwl, g_uwl);
    cudaGetSymbolAddress((void**)&vwh, g_vwh);   cudaGetSymbolAddress((void**)&vwl, g_vwl);
    cudaGetSymbolAddress((void**)&mw, g_mw);
    cudaGetSymbolAddress((void**)&qh, g_qh);     cudaGetSymbolAddress((void**)&ql, g_ql);
    cudaGetSymbolAddress((void**)&kh, g_kh);     cudaGetSymbolAddress((void**)&kl, g_kl);
    cudaGetSymbolAddress((void**)&vh, g_vh);     cudaGetSymbolAddress((void**)&vl, g_vl);
    cudaGetSymbolAddress((void**)&aoh, g_aoh);   cudaGetSymbolAddress((void**)&aol, g_aol);
    cudaGetSymbolAddress((void**)&woh, g_woh);   cudaGetSymbolAddress((void**)&wol, g_wol);
    cudaGetSymbolAddress((void**)&mb, g_mb);

    cudaFuncSetAttribute(wino_gemm_kernel, cudaFuncAttributeMaxDynamicSharedMemorySize, GEMM_SMEM_BYTES);
    cudaFuncSetAttribute(flash_kernel,     cudaFuncAttributeMaxDynamicSharedMemorySize, FA_SMEM_BYTES);
    cudaFuncSetAttribute(proj_mma_kernel,  cudaFuncAttributeMaxDynamicSharedMemorySize, GEMM_SMEM_BYTES);

    wino_w_kernel<<<12288, 256>>>(Wq, Wk, Wv, uwh, uwl);
    wino_x_kernel<<<dim3(8, 32, 24), 256>>>(q, k, v, vwh, vwl);
    pack_wo_kernel<<<4096, 256>>>(Wo, woh, wol);
    pack_mask_kernel<<<32768, 256>>>(mask, mb);

    wino_gemm_kernel<<<dim3(8, 4, 108), 256, GEMM_SMEM_BYTES>>>(uwh, uwl, vwh, vwl, mw);
    wino_out_kernel<<<6144, 256>>>(mw, bq, bk, bv, qh, ql, kh, kl, vh, vl);

    flash_kernel<<<dim3(8, 128), 256, FA_SMEM_BYTES>>>(
        qh, ql, kh, kl, vh, vl, mb, aoh, aol);

    proj_mma_kernel<<<dim3(64, 8), 256, GEMM_SMEM_BYTES>>>(aoh, aol, woh, wol, bo, out);
}